// round 1
// baseline (speedup 1.0000x reference)
#include <cuda_runtime.h>
#include <math.h>

#define BB 32
#define NN 4096
#define DD 256
#define MSGK 256
#define NHEAD 4
#define HD 64

// ------------------------- device scratch -------------------------
__device__ int   g_topk_idx[BB * MSGK];
__device__ float g_topk_val[BB * MSGK];
__device__ int   g_slot[BB * NN];
__device__ int   g_slot2[BB * NN];
__device__ float g_qkv[BB * MSGK * 3 * DD];
__device__ float g_attn[BB * MSGK * DD];
__device__ float g_msg[BB * MSGK * DD];
__device__ float g_h[(size_t)BB * NN * DD];
__device__ float g_tmp[(size_t)BB * NN * DD];
__device__ float g_newhid[(size_t)BB * NN * DD];
__device__ float g_newact[BB * NN];

__device__ __forceinline__ float gelu_f(float x) {
    return 0.5f * x * (1.0f + erff(x * 0.70710678118654752440f));
}

// ------------------------- top-k via bitonic sort -------------------------
// One block per batch row. Sorts 4096 (val,idx) pairs descending in smem,
// then writes slot map (rank if in top-kk else -1) and optional compact idx/val.
__global__ void sort_topk_kernel(const float* __restrict__ act,
                                 const int* __restrict__ kptr, int kconst,
                                 int* __restrict__ idx_out, float* __restrict__ val_out,
                                 int* __restrict__ slotmap) {
    __shared__ float sv[NN];
    __shared__ int   si[NN];
    int b = blockIdx.x;
    int tid = threadIdx.x;
    int kk = kptr ? *kptr : kconst;
    if (kk > NN) kk = NN;
    if (kk < 0) kk = 0;

    for (int i = tid; i < NN; i += blockDim.x) { sv[i] = act[b * NN + i]; si[i] = i; }
    __syncthreads();

    for (int ksz = 2; ksz <= NN; ksz <<= 1) {
        for (int j = ksz >> 1; j > 0; j >>= 1) {
            for (int i = tid; i < NN; i += blockDim.x) {
                int ixj = i ^ j;
                if (ixj > i) {
                    bool dirDesc = ((i & ksz) == 0);
                    float vi = sv[i], vx = sv[ixj];
                    bool sw = dirDesc ? (vi < vx) : (vi > vx);
                    if (sw) {
                        sv[i] = vx; sv[ixj] = vi;
                        int t = si[i]; si[i] = si[ixj]; si[ixj] = t;
                    }
                }
            }
            __syncthreads();
        }
    }

    for (int i = tid; i < NN; i += blockDim.x) slotmap[b * NN + i] = -1;
    __syncthreads();
    for (int j = tid; j < kk; j += blockDim.x) {
        slotmap[b * NN + si[j]] = j;
        if (idx_out) { idx_out[b * kk + j] = si[j]; val_out[b * kk + j] = sv[j]; }
    }
}

// ------------------------- generic tiled GEMM -------------------------
// C[M, Ncols] = epi( A@W^T + bias ), W is [Ncols_total, Ktot] row-major.
// A is logically [M, Ktot] assembled from:
//   k <  K1 : A1 rows (optionally gathered: row m -> hidden[(m>>8)*NN + gather[m]])
//   k >= K1 : A2 rows, either dense (row m) or slot-gathered
//             (s = slotmap[m]; s<0 -> 0; else A2[(m>>12)*MSGK + s])
// Block: 32 rows x 256 cols, 256 threads, each thread 2x16 outputs.
#define GEMM_BM 32
#define GEMM_BK 16

__global__ void gemm_kernel(const float* __restrict__ A1, const float* __restrict__ A2,
                            const int* __restrict__ gather, const int* __restrict__ slotmap,
                            const float* __restrict__ W, const float* __restrict__ bias,
                            const float* __restrict__ rowscale, float* __restrict__ C,
                            int K1, int Ktot, int kshift, int Ncols, int apply_gelu) {
    extern __shared__ float sm[];
    float* As = sm;                 // [Ktot][33] padded, layout As[k*33 + row]
    float* Ws = sm + Ktot * 33;     // [16][256]

    int tid = threadIdx.x;
    int r0 = blockIdx.x * GEMM_BM;
    int cy = blockIdx.y;
    int kmask = Ktot - 1;
    int K2 = Ktot - K1;

    // Load A tile (coalesced along k)
    for (int e = tid; e < GEMM_BM * Ktot; e += 256) {
        int row = e >> kshift;
        int k = e & kmask;
        int m = r0 + row;
        float v;
        if (k < K1) {
            long long src;
            if (gather) {
                int b = m >> 8;  // MSGK rows per batch
                src = ((long long)(b * NN + gather[m])) * K1 + k;
            } else {
                src = (long long)m * K1 + k;
            }
            v = A1[src];
        } else {
            int k2 = k - K1;
            if (slotmap) {
                int s = slotmap[m];
                if (s < 0) v = 0.0f;
                else {
                    int b = m >> 12;  // NN rows per batch
                    v = A2[((long long)(b * MSGK + s)) * K2 + k2];
                }
            } else {
                v = A2[(long long)m * K2 + k2];
            }
        }
        As[k * 33 + row] = v;
    }

    int tx = tid & 15;   // col group: cols tx*16 .. tx*16+15
    int ty = tid >> 4;   // row group: rows ty*2, ty*2+1

    float4 acc0[4], acc1[4];
#pragma unroll
    for (int i = 0; i < 4; i++) { acc0[i] = make_float4(0.f,0.f,0.f,0.f); acc1[i] = make_float4(0.f,0.f,0.f,0.f); }

    const float4* W4 = reinterpret_cast<const float4*>(W);

    for (int kb = 0; kb < Ktot; kb += GEMM_BK) {
        __syncthreads();  // guards As (first iter) and Ws reuse
#pragma unroll
        for (int it = 0; it < 4; it++) {
            int f = tid + it * 256;          // [0,1024) float4s of the 16x256 W tile
            int n = f >> 2;
            int q = f & 3;
            float4 wv = W4[(((long long)(cy * 256 + n)) * Ktot + kb) / 4 + q];
            Ws[(q * 4 + 0) * 256 + n] = wv.x;
            Ws[(q * 4 + 1) * 256 + n] = wv.y;
            Ws[(q * 4 + 2) * 256 + n] = wv.z;
            Ws[(q * 4 + 3) * 256 + n] = wv.w;
        }
        __syncthreads();
#pragma unroll
        for (int kkq = 0; kkq < GEMM_BK; kkq++) {
            int k = kb + kkq;
            float a0 = As[k * 33 + ty * 2];
            float a1 = As[k * 33 + ty * 2 + 1];
            const float4* wrow = reinterpret_cast<const float4*>(Ws + kkq * 256 + tx * 16);
#pragma unroll
            for (int i = 0; i < 4; i++) {
                float4 w = wrow[i];
                acc0[i].x += a0 * w.x; acc0[i].y += a0 * w.y; acc0[i].z += a0 * w.z; acc0[i].w += a0 * w.w;
                acc1[i].x += a1 * w.x; acc1[i].y += a1 * w.y; acc1[i].z += a1 * w.z; acc1[i].w += a1 * w.w;
            }
        }
    }

    // Epilogue
    int m0 = r0 + ty * 2;
    int m1 = m0 + 1;
    float s0 = rowscale ? rowscale[m0] : 1.0f;
    float s1 = rowscale ? rowscale[m1] : 1.0f;
#pragma unroll
    for (int i = 0; i < 4; i++) {
        int col = cy * 256 + tx * 16 + i * 4;
        float4 bb = *reinterpret_cast<const float4*>(bias + col);
        float4 c0 = acc0[i], c1 = acc1[i];
        c0.x += bb.x; c0.y += bb.y; c0.z += bb.z; c0.w += bb.w;
        c1.x += bb.x; c1.y += bb.y; c1.z += bb.z; c1.w += bb.w;
        if (apply_gelu) {
            c0.x = gelu_f(c0.x); c0.y = gelu_f(c0.y); c0.z = gelu_f(c0.z); c0.w = gelu_f(c0.w);
            c1.x = gelu_f(c1.x); c1.y = gelu_f(c1.y); c1.z = gelu_f(c1.z); c1.w = gelu_f(c1.w);
        }
        c0.x *= s0; c0.y *= s0; c0.z *= s0; c0.w *= s0;
        c1.x *= s1; c1.y *= s1; c1.z *= s1; c1.w *= s1;
        *reinterpret_cast<float4*>(C + (long long)m0 * Ncols + col) = c0;
        *reinterpret_cast<float4*>(C + (long long)m1 * Ncols + col) = c1;
    }
}

// ------------------------- attention -------------------------
// One block per (b, h). 256 threads, one q-row each. K,V tiles in smem (128 KB).
__global__ void attn_kernel(const float* __restrict__ qkv, float* __restrict__ out) {
    extern __shared__ float sm[];
    float* Ks = sm;                 // [256][64]
    float* Vs = sm + MSGK * HD;     // [256][64]
    int bh = blockIdx.x;
    int b = bh >> 2;
    int h = bh & 3;
    int tid = threadIdx.x;
    const float* base = qkv + (long long)b * MSGK * 768;

    for (int t = tid; t < MSGK * HD; t += 256) {
        int j = t >> 6;
        int d = t & 63;
        Ks[t] = base[j * 768 + 256 + h * 64 + d];
        Vs[t] = base[j * 768 + 512 + h * 64 + d];
    }
    __syncthreads();

    float q[HD], o[HD];
#pragma unroll
    for (int d = 0; d < HD; d++) { q[d] = base[tid * 768 + h * 64 + d] * 0.125f; o[d] = 0.0f; }

    float mval = -1e30f, l = 0.0f;
    for (int j = 0; j < MSGK; j++) {
        float s = 0.0f;
#pragma unroll
        for (int d = 0; d < HD; d++) s += q[d] * Ks[j * 64 + d];
        float nm = fmaxf(mval, s);
        float corr = expf(mval - nm);
        float p = expf(s - nm);
        l = l * corr + p;
#pragma unroll
        for (int d = 0; d < HD; d++) o[d] = o[d] * corr + p * Vs[j * 64 + d];
        mval = nm;
    }
    float inv = 1.0f / l;
    float* op = out + ((long long)(b * MSGK + tid)) * DD + h * 64;
#pragma unroll
    for (int d = 0; d < HD; d++) op[d] = o[d] * inv;
}

// ------------------------- layernorm -------------------------
__global__ void ln_kernel(const float* __restrict__ x, const float* __restrict__ g,
                          const float* __restrict__ bta, float* __restrict__ out) {
    int warp = (blockIdx.x * blockDim.x + threadIdx.x) >> 5;
    int lane = threadIdx.x & 31;
    const float* xr = x + (long long)warp * DD;
    float vals[8];
    float s = 0.0f;
#pragma unroll
    for (int i = 0; i < 8; i++) { vals[i] = xr[lane + i * 32]; s += vals[i]; }
#pragma unroll
    for (int off = 16; off; off >>= 1) s += __shfl_xor_sync(0xffffffffu, s, off);
    float mu = s * (1.0f / 256.0f);
    float vs = 0.0f;
#pragma unroll
    for (int i = 0; i < 8; i++) { float d = vals[i] - mu; vs += d * d; }
#pragma unroll
    for (int off = 16; off; off >>= 1) vs += __shfl_xor_sync(0xffffffffu, vs, off);
    float inv = rsqrtf(vs * (1.0f / 256.0f) + 1e-5f);
    float* orow = out + (long long)warp * DD;
#pragma unroll
    for (int i = 0; i < 8; i++) {
        int c = lane + i * 32;
        orow[c] = (vals[i] - mu) * inv * g[c] + bta[c];
    }
}

// ------------------------- activation update (dot + sigmoid + blend) -------------------------
__global__ void act_update_kernel(const float* __restrict__ h2, const float* __restrict__ w2,
                                  const float* __restrict__ b2, const float* __restrict__ act,
                                  float* __restrict__ newact) {
    int warp = (blockIdx.x * blockDim.x + threadIdx.x) >> 5;
    int lane = threadIdx.x & 31;
    const float* hr = h2 + (long long)warp * DD;
    float s = 0.0f;
#pragma unroll
    for (int i = 0; i < 8; i++) { int c = lane + i * 32; s += hr[c] * w2[c]; }
#pragma unroll
    for (int off = 16; off; off >>= 1) s += __shfl_xor_sync(0xffffffffu, s, off);
    if (lane == 0) {
        float d = 1.0f / (1.0f + expf(-(s + b2[0])));
        float na = 0.7f * act[warp] + 0.3f * d;
        na = fminf(fmaxf(na, 0.0f), 1.0f);
        newact[warp] = na;
    }
}

// ------------------------- finalize (mask + write outputs) -------------------------
__global__ void finalize_kernel(const float* __restrict__ newact, const float* __restrict__ newhid,
                                const int* __restrict__ slot2, float* __restrict__ out) {
    long long total_act = (long long)BB * NN;
    float* out_act = out;
    float* out_hid = out + total_act;
    long long stride = (long long)gridDim.x * blockDim.x;
    long long t0 = (long long)blockIdx.x * blockDim.x + threadIdx.x;

    for (long long i = t0; i < total_act; i += stride)
        out_act[i] = (slot2[i] >= 0) ? newact[i] : 0.0f;

    long long totalh4 = (long long)BB * NN * DD / 4;
    float4* oh4 = reinterpret_cast<float4*>(out_hid);
    const float4* nh4 = reinterpret_cast<const float4*>(newhid);
    for (long long e = t0; e < totalh4; e += stride) {
        long long r = e >> 6;  // 64 float4 per row
        oh4[e] = (slot2[r] >= 0) ? nh4[e] : make_float4(0.f, 0.f, 0.f, 0.f);
    }
}

// ------------------------- host launcher -------------------------
extern "C" void kernel_launch(void* const* d_in, const int* in_sizes, int n_in,
                              void* d_out, int out_size) {
    const float* act    = (const float*)d_in[0];
    const float* hidden = (const float*)d_in[1];
    const float* in_w   = (const float*)d_in[2];
    const float* in_b   = (const float*)d_in[3];
    const float* out_w  = (const float*)d_in[4];
    const float* out_b  = (const float*)d_in[5];
    const float* su_w1  = (const float*)d_in[6];
    const float* su_b1  = (const float*)d_in[7];
    const float* su_w2  = (const float*)d_in[8];
    const float* su_b2  = (const float*)d_in[9];
    const float* au_w1  = (const float*)d_in[10];
    const float* au_b1  = (const float*)d_in[11];
    const float* au_w2  = (const float*)d_in[12];
    const float* au_b2  = (const float*)d_in[13];
    const float* ln_g   = (const float*)d_in[14];
    const float* ln_b   = (const float*)d_in[15];
    const int*   kptr   = (const int*)d_in[16];

    int*   p_tidx;   cudaGetSymbolAddress((void**)&p_tidx,   g_topk_idx);
    float* p_tval;   cudaGetSymbolAddress((void**)&p_tval,   g_topk_val);
    int*   p_slot;   cudaGetSymbolAddress((void**)&p_slot,   g_slot);
    int*   p_slot2;  cudaGetSymbolAddress((void**)&p_slot2,  g_slot2);
    float* p_qkv;    cudaGetSymbolAddress((void**)&p_qkv,    g_qkv);
    float* p_attn;   cudaGetSymbolAddress((void**)&p_attn,   g_attn);
    float* p_msg;    cudaGetSymbolAddress((void**)&p_msg,    g_msg);
    float* p_h;      cudaGetSymbolAddress((void**)&p_h,      g_h);
    float* p_tmp;    cudaGetSymbolAddress((void**)&p_tmp,    g_tmp);
    float* p_newhid; cudaGetSymbolAddress((void**)&p_newhid, g_newhid);
    float* p_newact; cudaGetSymbolAddress((void**)&p_newact, g_newact);

    const int SMEM_G256 = (256 * 33 + 16 * 256) * 4;  // 50176
    const int SMEM_G512 = (512 * 33 + 16 * 256) * 4;  // 83968
    const int SMEM_ATTN = 2 * MSGK * HD * 4;          // 131072

    cudaFuncSetAttribute(gemm_kernel, cudaFuncAttributeMaxDynamicSharedMemorySize, SMEM_G512);
    cudaFuncSetAttribute(attn_kernel, cudaFuncAttributeMaxDynamicSharedMemorySize, SMEM_ATTN);

    // 1) top-k of activation (MSG_K=256): topk idx/val compact + slot map
    sort_topk_kernel<<<BB, 512>>>(act, nullptr, MSGK, p_tidx, p_tval, p_slot);

    // 2) QKV projection on gathered active states: [8192,256]@[256,768]^T
    gemm_kernel<<<dim3(BB * MSGK / GEMM_BM, 3), 256, SMEM_G256>>>(
        hidden, nullptr, p_tidx, nullptr, in_w, in_b, nullptr, p_qkv,
        256, 256, 8, 768, 0);

    // 3) attention per (b,h)
    attn_kernel<<<BB * NHEAD, 256, SMEM_ATTN>>>(p_qkv, p_attn);

    // 4) out-proj + scale by topk values
    gemm_kernel<<<dim3(BB * MSGK / GEMM_BM, 1), 256, SMEM_G256>>>(
        p_attn, nullptr, nullptr, nullptr, out_w, out_b, p_tval, p_msg,
        256, 256, 8, 256, 0);

    // 5) su stage 1: gelu([hidden | msg_slot]@su_w1^T + b1)  (K=512)
    gemm_kernel<<<dim3(BB * NN / GEMM_BM, 1), 256, SMEM_G512>>>(
        hidden, p_msg, nullptr, p_slot, su_w1, su_b1, nullptr, p_h,
        256, 512, 9, 256, 1);

    // 6) su stage 2: h@su_w2^T + b2
    gemm_kernel<<<dim3(BB * NN / GEMM_BM, 1), 256, SMEM_G256>>>(
        p_h, nullptr, nullptr, nullptr, su_w2, su_b2, nullptr, p_tmp,
        256, 256, 8, 256, 0);

    // 7) layernorm -> new_hidden
    ln_kernel<<<BB * NN / 8, 256>>>(p_tmp, ln_g, ln_b, p_newhid);

    // 8) au stage 1: gelu([hidden | new_hidden]@au_w1^T + b1)  (K=512)
    gemm_kernel<<<dim3(BB * NN / GEMM_BM, 1), 256, SMEM_G512>>>(
        hidden, p_newhid, nullptr, nullptr, au_w1, au_b1, nullptr, p_h,
        256, 512, 9, 256, 1);

    // 9) delta = sigmoid(h2 . au_w2 + b2); new_act = clip(0.7a + 0.3d)
    act_update_kernel<<<BB * NN / 8, 256>>>(p_h, au_w2, au_b2, act, p_newact);

    // 10) final top-k (k read on-device from sparsity_k) -> slot2 map
    sort_topk_kernel<<<BB, 512>>>(p_newact, kptr, 0, nullptr, nullptr, p_slot2);

    // 11) masked write of [sparse_act | sparse_hidden] into d_out
    finalize_kernel<<<2048, 256>>>(p_newact, p_newhid, p_slot2, (float*)d_out);
}

// round 3
// speedup vs baseline: 5.1738x; 5.1738x over previous
#include <cuda_runtime.h>
#include <math.h>

#define BB 32
#define NN 4096
#define DD 256
#define MSGK 256
#define HD 64

#define TBM 128
#define TBK 16
#define TTH 512

// ------------------------- device scratch -------------------------
__device__ int   g_tidx[BB * MSGK];
__device__ float g_tval[BB * MSGK];
__device__ int   g_slot[BB * NN];
__device__ int   g_slot2[BB * NN];
__device__ float g_qkv[BB * MSGK * 3 * DD];
__device__ float g_attn[BB * MSGK * DD];
__device__ float g_msg[BB * MSGK * DD];
__device__ float g_h[(size_t)BB * NN * DD];
__device__ float g_newhid[(size_t)BB * NN * DD];
__device__ float g_newact[BB * NN];
__device__ float g_wt_in[256 * 768];
__device__ float g_wt_out[256 * 256];
__device__ float g_wt_su1[512 * 256];
__device__ float g_wt_su2[256 * 256];
__device__ float g_wt_au1[512 * 256];

__device__ __forceinline__ float gelu_f(float x) {
    return 0.5f * x * (1.0f + erff(x * 0.70710678118654752440f));
}

__device__ __forceinline__ float wred(float v) {
#pragma unroll
    for (int o = 16; o; o >>= 1) v += __shfl_xor_sync(0xffffffffu, v, o);
    return v;
}

// ------------------------- weight transpose -------------------------
// Wt[k][n] = W[n][k].  W is [Nout][Kd] row-major.
__global__ void transpose_kernel(const float* __restrict__ W, float* __restrict__ Wt,
                                 int Nout, int Kd) {
    __shared__ float t[32][33];
    int k0 = blockIdx.x * 32, n0 = blockIdx.y * 32;
    int tx = threadIdx.x, ty = threadIdx.y;  // 32 x 8
#pragma unroll
    for (int i = 0; i < 32; i += 8)
        t[ty + i][tx] = W[(long long)(n0 + ty + i) * Kd + k0 + tx];
    __syncthreads();
#pragma unroll
    for (int i = 0; i < 32; i += 8)
        Wt[(long long)(k0 + ty + i) * Nout + n0 + tx] = t[tx][ty + i];
}

// ------------------------- top-k via bitonic sort -------------------------
__global__ void sort_topk_kernel(const float* __restrict__ act,
                                 const int* __restrict__ kptr, int kconst,
                                 int* __restrict__ idx_out, float* __restrict__ val_out,
                                 int* __restrict__ slotmap) {
    __shared__ float sv[NN];
    __shared__ int   si[NN];
    int b = blockIdx.x;
    int tid = threadIdx.x;
    int kk = kptr ? *kptr : kconst;
    if (kk > NN) kk = NN;
    if (kk < 0) kk = 0;

    for (int i = tid; i < NN; i += blockDim.x) { sv[i] = act[b * NN + i]; si[i] = i; }
    __syncthreads();

    for (int ksz = 2; ksz <= NN; ksz <<= 1) {
        for (int j = ksz >> 1; j > 0; j >>= 1) {
            for (int i = tid; i < NN; i += blockDim.x) {
                int ixj = i ^ j;
                if (ixj > i) {
                    bool dirDesc = ((i & ksz) == 0);
                    float vi = sv[i], vx = sv[ixj];
                    bool sw = dirDesc ? (vi < vx) : (vi > vx);
                    if (sw) {
                        sv[i] = vx; sv[ixj] = vi;
                        int t = si[i]; si[i] = si[ixj]; si[ixj] = t;
                    }
                }
            }
            __syncthreads();
        }
    }

    for (int i = tid; i < NN; i += blockDim.x) slotmap[b * NN + i] = -1;
    __syncthreads();
    for (int j = tid; j < kk; j += blockDim.x) {
        slotmap[b * NN + si[j]] = j;
        if (idx_out) { idx_out[b * kk + j] = si[j]; val_out[b * kk + j] = sv[j]; }
    }
}

// ------------------------- main GEMM -------------------------
// C[M, :] = epi( A@Wt + bias ), Wt is [Ktot][ldw] (pre-transposed, k-major).
// A row m: k<K1 from A1 (optionally row-gathered), k>=K1 from A2 (dense).
// Block: 128 rows x 256 cols, 512 threads, 8x8 microtile per thread.
// modes: 0 = bias (+rowscale) store
//        1 = bias + gelu store
//        2 = bias + layernorm store
//        3 = bias + gelu + dot(w2) + sigmoid blend -> act_out (no C store)
//        4 = accumulate into C (rows via cgather), no bias
__global__ __launch_bounds__(TTH, 1)
void gemm2(const float* __restrict__ A1, const float* __restrict__ A2,
           const int* __restrict__ gather,
           const float* __restrict__ Wt, int ldw,
           const float* __restrict__ bias,
           const float* __restrict__ rowscale,
           const float* __restrict__ lng, const float* __restrict__ lnb,
           const float* __restrict__ w2, const float* __restrict__ b2,
           const float* __restrict__ act_in, float* __restrict__ act_out,
           float* __restrict__ C, const int* __restrict__ cgather, int ldc,
           int K1, int Ktot, int a1_gelu, int mode) {
    extern __shared__ float sm[];
    float* As = sm;                 // [2][TBK][132]
    float* Ws = sm + 2 * TBK * 132; // [2][TBK][256]

    int tid = threadIdx.x;
    int r0 = blockIdx.x * TBM;
    int wcol0 = blockIdx.y * 256;

    // A staging: thread -> (row am, 4 consecutive k at ak)
    int am = tid >> 2;
    int ak = (tid & 3) << 2;
    int m_a = r0 + am;
    const float* a1row;
    if (gather) a1row = A1 + (long long)((m_a >> 8) * NN + gather[m_a]) * K1;
    else        a1row = A1 + (long long)m_a * K1;
    const float* a2row = A2 ? (A2 + (long long)m_a * (Ktot - K1)) : a1row;

    // W staging: thread -> (k-row wr, 8 cols at wc)
    int wr = tid >> 5;
    int wc = (tid & 31) << 3;
    const float* wbase = Wt + (long long)wr * ldw + wcol0 + wc;

    float4 av, wv0, wv1;

#define LOAD_STAGE(kb) do {                                                   \
        int k0_ = (kb) + ak;                                                  \
        if (k0_ < K1) av = *(const float4*)(a1row + k0_);                     \
        else          av = *(const float4*)(a2row + (k0_ - K1));              \
        if (a1_gelu) { av.x = gelu_f(av.x); av.y = gelu_f(av.y);              \
                       av.z = gelu_f(av.z); av.w = gelu_f(av.w); }            \
        const float* wp_ = wbase + (long long)(kb) * ldw;                     \
        wv0 = *(const float4*)(wp_);                                          \
        wv1 = *(const float4*)(wp_ + 4);                                      \
    } while (0)

#define STORE_STAGE(buf) do {                                                 \
        float* ap_ = As + (buf) * (TBK * 132);                                \
        ap_[(ak + 0) * 132 + am] = av.x;                                      \
        ap_[(ak + 1) * 132 + am] = av.y;                                      \
        ap_[(ak + 2) * 132 + am] = av.z;                                      \
        ap_[(ak + 3) * 132 + am] = av.w;                                      \
        float* wpS_ = Ws + (buf) * (TBK * 256) + wr * 256 + wc;               \
        *(float4*)wpS_ = wv0;                                                 \
        *(float4*)(wpS_ + 4) = wv1;                                           \
    } while (0)

    int lane = tid & 31, warp = tid >> 5;
    int row0 = warp << 3, col0 = lane << 3;

    float acc[8][8];
#pragma unroll
    for (int r = 0; r < 8; r++)
#pragma unroll
        for (int c = 0; c < 8; c++) acc[r][c] = 0.0f;

    LOAD_STAGE(0);
    STORE_STAGE(0);
    __syncthreads();

    int S = Ktot / TBK;
    for (int s = 0; s < S; s++) {
        int cur = s & 1;
        if (s + 1 < S) LOAD_STAGE((s + 1) * TBK);
        const float* ab = As + cur * (TBK * 132);
        const float* wb = Ws + cur * (TBK * 256);
#pragma unroll
        for (int k = 0; k < TBK; k++) {
            float4 a0 = *(const float4*)(ab + k * 132 + row0);
            float4 a1v = *(const float4*)(ab + k * 132 + row0 + 4);
            float4 b0 = *(const float4*)(wb + k * 256 + col0);
            float4 b1 = *(const float4*)(wb + k * 256 + col0 + 4);
            float aa[8] = {a0.x, a0.y, a0.z, a0.w, a1v.x, a1v.y, a1v.z, a1v.w};
            float bv[8] = {b0.x, b0.y, b0.z, b0.w, b1.x, b1.y, b1.z, b1.w};
#pragma unroll
            for (int r = 0; r < 8; r++)
#pragma unroll
                for (int c = 0; c < 8; c++) acc[r][c] += aa[r] * bv[c];
        }
        if (s + 1 < S) {
            STORE_STAGE((s + 1) & 1);
            __syncthreads();
        }
    }

    int cg0 = wcol0 + col0;

    if (mode == 4) {
#pragma unroll
        for (int r = 0; r < 8; r++) {
            int m = r0 + row0 + r;
            long long crow = cgather ? (long long)((m >> 8) * NN + cgather[m]) : m;
            float* cp = C + crow * ldc + cg0;
            float4 o0 = *(float4*)cp, o1 = *(float4*)(cp + 4);
            o0.x += acc[r][0]; o0.y += acc[r][1]; o0.z += acc[r][2]; o0.w += acc[r][3];
            o1.x += acc[r][4]; o1.y += acc[r][5]; o1.z += acc[r][6]; o1.w += acc[r][7];
            *(float4*)cp = o0; *(float4*)(cp + 4) = o1;
        }
        return;
    }

    // bias
    {
        float4 bb0 = *(const float4*)(bias + cg0);
        float4 bb1 = *(const float4*)(bias + cg0 + 4);
        float bb[8] = {bb0.x, bb0.y, bb0.z, bb0.w, bb1.x, bb1.y, bb1.z, bb1.w};
#pragma unroll
        for (int r = 0; r < 8; r++)
#pragma unroll
            for (int c = 0; c < 8; c++) acc[r][c] += bb[c];
    }

    if (mode == 1 || mode == 3) {
#pragma unroll
        for (int r = 0; r < 8; r++)
#pragma unroll
            for (int c = 0; c < 8; c++) acc[r][c] = gelu_f(acc[r][c]);
    }

    if (mode == 3) {
        float4 w20 = *(const float4*)(w2 + cg0);
        float4 w21 = *(const float4*)(w2 + cg0 + 4);
        float w2v[8] = {w20.x, w20.y, w20.z, w20.w, w21.x, w21.y, w21.z, w21.w};
        float b2v = b2[0];
#pragma unroll
        for (int r = 0; r < 8; r++) {
            float p = 0.0f;
#pragma unroll
            for (int c = 0; c < 8; c++) p += acc[r][c] * w2v[c];
            float red = wred(p);
            if (lane == r) {
                int m = r0 + row0 + r;
                float dl = 1.0f / (1.0f + expf(-(red + b2v)));
                float na = 0.7f * act_in[m] + 0.3f * dl;
                na = fminf(fmaxf(na, 0.0f), 1.0f);
                act_out[m] = na;
            }
        }
        return;
    }

    if (mode == 2) {
        float4 g0 = *(const float4*)(lng + cg0);
        float4 g1 = *(const float4*)(lng + cg0 + 4);
        float4 e0 = *(const float4*)(lnb + cg0);
        float4 e1 = *(const float4*)(lnb + cg0 + 4);
        float gv[8] = {g0.x, g0.y, g0.z, g0.w, g1.x, g1.y, g1.z, g1.w};
        float ev[8] = {e0.x, e0.y, e0.z, e0.w, e1.x, e1.y, e1.z, e1.w};
#pragma unroll
        for (int r = 0; r < 8; r++) {
            float s = 0.0f;
#pragma unroll
            for (int c = 0; c < 8; c++) s += acc[r][c];
            float mu = wred(s) * (1.0f / 256.0f);
            float v = 0.0f;
#pragma unroll
            for (int c = 0; c < 8; c++) { float d = acc[r][c] - mu; v += d * d; }
            float inv = rsqrtf(wred(v) * (1.0f / 256.0f) + 1e-5f);
#pragma unroll
            for (int c = 0; c < 8; c++) acc[r][c] = (acc[r][c] - mu) * inv * gv[c] + ev[c];
        }
    }

#pragma unroll
    for (int r = 0; r < 8; r++) {
        int m = r0 + row0 + r;
        float sc = rowscale ? rowscale[m] : 1.0f;
        float4 o0 = make_float4(acc[r][0] * sc, acc[r][1] * sc, acc[r][2] * sc, acc[r][3] * sc);
        float4 o1 = make_float4(acc[r][4] * sc, acc[r][5] * sc, acc[r][6] * sc, acc[r][7] * sc);
        float* cp = C + (long long)m * ldc + cg0;
        *(float4*)cp = o0;
        *(float4*)(cp + 4) = o1;
    }
}

// ------------------------- attention -------------------------
__global__ void attn_kernel(const float* __restrict__ qkv, float* __restrict__ out) {
    extern __shared__ float sm[];
    float* Ks = sm;
    float* Vs = sm + MSGK * HD;
    int bh = blockIdx.x;
    int b = bh >> 2;
    int h = bh & 3;
    int tid = threadIdx.x;
    const float* base = qkv + (long long)b * MSGK * 768;

    for (int t = tid; t < MSGK * HD; t += 256) {
        int j = t >> 6;
        int d = t & 63;
        Ks[t] = base[j * 768 + 256 + h * 64 + d];
        Vs[t] = base[j * 768 + 512 + h * 64 + d];
    }
    __syncthreads();

    float q[HD], o[HD];
#pragma unroll
    for (int d = 0; d < HD; d++) { q[d] = base[tid * 768 + h * 64 + d] * 0.125f; o[d] = 0.0f; }

    float mval = -1e30f, l = 0.0f;
    for (int j = 0; j < MSGK; j++) {
        float s = 0.0f;
#pragma unroll
        for (int d = 0; d < HD; d++) s += q[d] * Ks[j * 64 + d];
        float nm = fmaxf(mval, s);
        float corr = expf(mval - nm);
        float p = expf(s - nm);
        l = l * corr + p;
#pragma unroll
        for (int d = 0; d < HD; d++) o[d] = o[d] * corr + p * Vs[j * 64 + d];
        mval = nm;
    }
    float inv = 1.0f / l;
    float* op = out + ((long long)(b * MSGK + tid)) * DD + h * 64;
#pragma unroll
    for (int d = 0; d < HD; d++) op[d] = o[d] * inv;
}

// ------------------------- finalize -------------------------
__global__ void finalize_kernel(const float* __restrict__ newact, const float* __restrict__ newhid,
                                const int* __restrict__ slot2, float* __restrict__ out) {
    long long total_act = (long long)BB * NN;
    float* out_act = out;
    float* out_hid = out + total_act;
    long long stride = (long long)gridDim.x * blockDim.x;
    long long t0 = (long long)blockIdx.x * blockDim.x + threadIdx.x;

    for (long long i = t0; i < total_act; i += stride)
        out_act[i] = (slot2[i] >= 0) ? newact[i] : 0.0f;

    long long totalh4 = (long long)BB * NN * DD / 4;
    float4* oh4 = reinterpret_cast<float4*>(out_hid);
    const float4* nh4 = reinterpret_cast<const float4*>(newhid);
    for (long long e = t0; e < totalh4; e += stride) {
        long long r = e >> 6;
        oh4[e] = (slot2[r] >= 0) ? nh4[e] : make_float4(0.f, 0.f, 0.f, 0.f);
    }
}

// ------------------------- host launcher -------------------------
extern "C" void kernel_launch(void* const* d_in, const int* in_sizes, int n_in,
                              void* d_out, int out_size) {
    const float* act    = (const float*)d_in[0];
    const float* hidden = (const float*)d_in[1];
    const float* in_w   = (const float*)d_in[2];
    const float* in_b   = (const float*)d_in[3];
    const float* out_w  = (const float*)d_in[4];
    const float* out_b  = (const float*)d_in[5];
    const float* su_w1  = (const float*)d_in[6];
    const float* su_b1  = (const float*)d_in[7];
    const float* su_w2  = (const float*)d_in[8];
    const float* su_b2  = (const float*)d_in[9];
    const float* au_w1  = (const float*)d_in[10];
    const float* au_b1  = (const float*)d_in[11];
    const float* au_w2  = (const float*)d_in[12];
    const float* au_b2  = (const float*)d_in[13];
    const float* ln_g   = (const float*)d_in[14];
    const float* ln_b   = (const float*)d_in[15];
    const int*   kptr   = (const int*)d_in[16];

    int*   p_tidx;   cudaGetSymbolAddress((void**)&p_tidx,   g_tidx);
    float* p_tval;   cudaGetSymbolAddress((void**)&p_tval,   g_tval);
    int*   p_slot;   cudaGetSymbolAddress((void**)&p_slot,   g_slot);
    int*   p_slot2;  cudaGetSymbolAddress((void**)&p_slot2,  g_slot2);
    float* p_qkv;    cudaGetSymbolAddress((void**)&p_qkv,    g_qkv);
    float* p_attn;   cudaGetSymbolAddress((void**)&p_attn,   g_attn);
    float* p_msg;    cudaGetSymbolAddress((void**)&p_msg,    g_msg);
    float* p_h;      cudaGetSymbolAddress((void**)&p_h,      g_h);
    float* p_newhid; cudaGetSymbolAddress((void**)&p_newhid, g_newhid);
    float* p_newact; cudaGetSymbolAddress((void**)&p_newact, g_newact);
    float* wt_in;    cudaGetSymbolAddress((void**)&wt_in,    g_wt_in);
    float* wt_out;   cudaGetSymbolAddress((void**)&wt_out,   g_wt_out);
    float* wt_su1;   cudaGetSymbolAddress((void**)&wt_su1,   g_wt_su1);
    float* wt_su2;   cudaGetSymbolAddress((void**)&wt_su2,   g_wt_su2);
    float* wt_au1;   cudaGetSymbolAddress((void**)&wt_au1,   g_wt_au1);

    const int SMEM_GEMM = (2 * TBK * 132 + 2 * TBK * 256) * 4;  // 49664
    const int SMEM_ATTN = 2 * MSGK * HD * 4;                    // 131072

    cudaFuncSetAttribute(gemm2, cudaFuncAttributeMaxDynamicSharedMemorySize, SMEM_GEMM);
    cudaFuncSetAttribute(attn_kernel, cudaFuncAttributeMaxDynamicSharedMemorySize, SMEM_ATTN);

    dim3 t328(32, 8);
    // weight transposes (k-major layouts for the GEMM)
    transpose_kernel<<<dim3(8, 24),  t328>>>(in_w,  wt_in,  768, 256);
    transpose_kernel<<<dim3(8, 8),   t328>>>(out_w, wt_out, 256, 256);
    transpose_kernel<<<dim3(16, 8),  t328>>>(su_w1, wt_su1, 256, 512);
    transpose_kernel<<<dim3(8, 8),   t328>>>(su_w2, wt_su2, 256, 256);
    transpose_kernel<<<dim3(16, 8),  t328>>>(au_w1, wt_au1, 256, 512);

    // 1) top-k of activation -> compact idx/val
    sort_topk_kernel<<<BB, 1024>>>(act, nullptr, MSGK, p_tidx, p_tval, p_slot);

    // 2) QKV: [8192,256]@wt_in -> [8192,768], rows gathered from hidden
    gemm2<<<dim3(BB * MSGK / TBM, 3), TTH, SMEM_GEMM>>>(
        hidden, nullptr, p_tidx, wt_in, 768, in_b,
        nullptr, nullptr, nullptr, nullptr, nullptr, nullptr, nullptr,
        p_qkv, nullptr, 768, 256, 256, 0, 0);

    // 3) attention
    attn_kernel<<<BB * 4, 256, SMEM_ATTN>>>(p_qkv, p_attn);

    // 4) out-proj + per-row topk scale -> msg (compact [8192,256])
    gemm2<<<dim3(BB * MSGK / TBM, 1), TTH, SMEM_GEMM>>>(
        p_attn, nullptr, nullptr, wt_out, 256, out_b,
        p_tval, nullptr, nullptr, nullptr, nullptr, nullptr, nullptr,
        p_msg, nullptr, 256, 256, 256, 0, 0);

    // 5a) su1 dense half: pre = hidden @ W1a^T + b1   (K=256, all rows)
    gemm2<<<dim3(BB * NN / TBM, 1), TTH, SMEM_GEMM>>>(
        hidden, nullptr, nullptr, wt_su1, 256, su_b1,
        nullptr, nullptr, nullptr, nullptr, nullptr, nullptr, nullptr,
        p_h, nullptr, 256, 256, 256, 0, 0);

    // 5b) su1 sparse half: pre[active rows] += msg @ W1b^T  (8192 rows, scatter)
    gemm2<<<dim3(BB * MSGK / TBM, 1), TTH, SMEM_GEMM>>>(
        p_msg, nullptr, nullptr, wt_su1 + 256 * 256, 256, nullptr,
        nullptr, nullptr, nullptr, nullptr, nullptr, nullptr, nullptr,
        p_h, p_tidx, 256, 256, 256, 0, 4);

    // 6) su2: newhid = LN( gelu(pre) @ W2^T + b2 )   (gelu on A-load, LN epilogue)
    gemm2<<<dim3(BB * NN / TBM, 1), TTH, SMEM_GEMM>>>(
        p_h, nullptr, nullptr, wt_su2, 256, su_b2,
        nullptr, ln_g, ln_b, nullptr, nullptr, nullptr, nullptr,
        p_newhid, nullptr, 256, 256, 256, 1, 2);

    // 7) au1 fused: newact = clip(0.7a + 0.3*sigmoid(gelu([hidden|newhid]@W1^T+b1)·w2+b2))
    gemm2<<<dim3(BB * NN / TBM, 1), TTH, SMEM_GEMM>>>(
        hidden, p_newhid, nullptr, wt_au1, 256, au_b1,
        nullptr, nullptr, nullptr, au_w2, au_b2, act, p_newact,
        nullptr, nullptr, 256, 256, 512, 0, 3);

    // 8) final top-k (k from device sparsity_k) -> slot2
    sort_topk_kernel<<<BB, 1024>>>(p_newact, kptr, 0, nullptr, nullptr, p_slot2);

    // 9) masked write [sparse_act | sparse_hidden]
    finalize_kernel<<<2048, 256>>>(p_newact, p_newhid, p_slot2, (float*)d_out);
}

// round 5
// speedup vs baseline: 6.2335x; 1.2048x over previous
#include <cuda_runtime.h>
#include <cuda_bf16.h>
#include <math.h>

#define BB 32
#define NN 4096
#define DD 256
#define MSGK 256
#define HD 64

// scalar gemm (sparse scatter-accum only)
#define TBM 128
#define TBK 16
#define TTH 512

// ------------------------- device scratch -------------------------
__device__ int   g_tidx[BB * MSGK];
__device__ float g_tval[BB * MSGK];
__device__ int   g_slot[BB * NN];
__device__ int   g_slot2[BB * NN];
__device__ float g_qkv[BB * MSGK * 3 * DD];
__device__ float g_attn[BB * MSGK * DD];
__device__ float g_msg[BB * MSGK * DD];
__device__ float g_h[(size_t)BB * NN * DD];
__device__ float g_newhid[(size_t)BB * NN * DD];
__device__ float g_newact[BB * NN];
__device__ float g_wt_su1[512 * 256];

// bf16 3-way splits of weights
__device__ __nv_bfloat16 g_in0[768*256],  g_in1[768*256],  g_in2[768*256];
__device__ __nv_bfloat16 g_ow0[256*256],  g_ow1[256*256],  g_ow2[256*256];
__device__ __nv_bfloat16 g_s10[256*512],  g_s11[256*512],  g_s12[256*512];
__device__ __nv_bfloat16 g_s20[256*256],  g_s21[256*256],  g_s22[256*256];
__device__ __nv_bfloat16 g_a10[256*512],  g_a11[256*512],  g_a12[256*512];

__device__ __forceinline__ float gelu_f(float x) {
    return 0.5f * x * (1.0f + erff(x * 0.70710678118654752440f));
}

__device__ __forceinline__ unsigned smem_u32(const void* p) {
    unsigned a;
    asm("{ .reg .u64 t; cvta.to.shared.u64 t, %1; cvt.u32.u64 %0, t; }" : "=r"(a) : "l"(p));
    return a;
}

__device__ __forceinline__ void ldsm4(unsigned& r0, unsigned& r1, unsigned& r2, unsigned& r3,
                                      unsigned addr) {
    asm volatile("ldmatrix.sync.aligned.m8n8.x4.shared.b16 {%0,%1,%2,%3}, [%4];"
                 : "=r"(r0), "=r"(r1), "=r"(r2), "=r"(r3) : "r"(addr));
}

__device__ __forceinline__ void mma_bf16(float* c, unsigned a0, unsigned a1, unsigned a2,
                                         unsigned a3, unsigned b0, unsigned b1) {
    asm volatile("mma.sync.aligned.m16n8k16.row.col.f32.bf16.bf16.f32 "
                 "{%0,%1,%2,%3},{%4,%5,%6,%7},{%8,%9},{%0,%1,%2,%3};"
                 : "+f"(c[0]), "+f"(c[1]), "+f"(c[2]), "+f"(c[3])
                 : "r"(a0), "r"(a1), "r"(a2), "r"(a3), "r"(b0), "r"(b1));
}

// ------------------------- weight split -------------------------
__global__ void split3_kernel(const float* __restrict__ W, __nv_bfloat16* o0,
                              __nv_bfloat16* o1, __nv_bfloat16* o2, int n) {
    int i = blockIdx.x * 256 + threadIdx.x;
    if (i < n) {
        float v = W[i];
        __nv_bfloat16 b0 = __float2bfloat16_rn(v);
        float r = v - __bfloat162float(b0);
        __nv_bfloat16 b1 = __float2bfloat16_rn(r);
        float r2 = r - __bfloat162float(b1);
        o0[i] = b0; o1[i] = b1; o2[i] = __float2bfloat16_rn(r2);
    }
}

// ------------------------- weight transpose (scalar scatter gemm) ------------
__global__ void transpose_kernel(const float* __restrict__ W, float* __restrict__ Wt,
                                 int Nout, int Kd) {
    __shared__ float t[32][33];
    int k0 = blockIdx.x * 32, n0 = blockIdx.y * 32;
    int tx = threadIdx.x, ty = threadIdx.y;
#pragma unroll
    for (int i = 0; i < 32; i += 8)
        t[ty + i][tx] = W[(long long)(n0 + ty + i) * Kd + k0 + tx];
    __syncthreads();
#pragma unroll
    for (int i = 0; i < 32; i += 8)
        Wt[(long long)(k0 + ty + i) * Nout + n0 + tx] = t[tx][ty + i];
}

// ------------------------- top-k via bitonic sort -------------------------
__global__ void sort_topk_kernel(const float* __restrict__ act,
                                 const int* __restrict__ kptr, int kconst,
                                 int* __restrict__ idx_out, float* __restrict__ val_out,
                                 int* __restrict__ slotmap) {
    __shared__ float sv[NN];
    __shared__ int   si[NN];
    int b = blockIdx.x;
    int tid = threadIdx.x;
    int kk = kptr ? *kptr : kconst;
    if (kk > NN) kk = NN;
    if (kk < 0) kk = 0;

    for (int i = tid; i < NN; i += blockDim.x) { sv[i] = act[b * NN + i]; si[i] = i; }
    __syncthreads();

    for (int ksz = 2; ksz <= NN; ksz <<= 1) {
        for (int j = ksz >> 1; j > 0; j >>= 1) {
            for (int i = tid; i < NN; i += blockDim.x) {
                int ixj = i ^ j;
                if (ixj > i) {
                    bool dirDesc = ((i & ksz) == 0);
                    float vi = sv[i], vx = sv[ixj];
                    bool sw = dirDesc ? (vi < vx) : (vi > vx);
                    if (sw) {
                        sv[i] = vx; sv[ixj] = vi;
                        int t = si[i]; si[i] = si[ixj]; si[ixj] = t;
                    }
                }
            }
            __syncthreads();
        }
    }

    for (int i = tid; i < NN; i += blockDim.x) slotmap[b * NN + i] = -1;
    __syncthreads();
    for (int j = tid; j < kk; j += blockDim.x) {
        slotmap[b * NN + si[j]] = j;
        if (idx_out) { idx_out[b * kk + j] = si[j]; val_out[b * kk + j] = sv[j]; }
    }
}

// ======================= tensor-core GEMM (mma.sync bf16) =======================
// C[M,:] = epi( A @ W^T + bias ); W given as bf16 splits W0/W1/W2, [Nout][ldw] row-major.
// A row m: k<K1 from A1 (optional row-gather), k>=K1 from A2. fp32 A split on the fly.
// CTA tile: 128 rows x 256 cols, 512 threads, 16 warps (4m x 4n), warp tile 32x64.
// nterms: 3 -> products (00,01,10); 6 -> (00,01,10,11,02,20).
// mode: 0 bias(+rowscale) store; 2 bias+LayerNorm store; 3 bias+gelu+dot(w2)+sigmoid blend.
#define KC 64
#define A_TERM 16384
#define B_TERM 32768
#define AB_OFF 0
#define BB_OFF (3 * A_TERM)
#define TC_SMEM (3 * A_TERM + 3 * B_TERM)   // 147456

__global__ __launch_bounds__(512, 1)
void mma_gemm(const float* __restrict__ A1, const float* __restrict__ A2,
              const int* __restrict__ gather,
              const __nv_bfloat16* __restrict__ W0, const __nv_bfloat16* __restrict__ W1,
              const __nv_bfloat16* __restrict__ W2s, int ldw,
              const float* __restrict__ bias,
              const float* __restrict__ rowscale,
              const float* __restrict__ lng, const float* __restrict__ lnb,
              const float* __restrict__ w2, const float* __restrict__ b2,
              const float* __restrict__ act_in, float* __restrict__ act_out,
              float* __restrict__ C, int ldc,
              int K1, int Ktot, int a1_gelu, int nterms, int mode) {
    extern __shared__ char smem[];
    unsigned sbase = smem_u32(smem);
    int tid = threadIdx.x;
    int lane = tid & 31;
    int wid = tid >> 5;
    int wm = wid & 3;          // row group (32 rows)
    int wn = wid >> 2;         // col group (64 cols)
    int r0 = blockIdx.x * 128;
    int colbase = blockIdx.y * 256;

    // ---- staging maps ----
    int s_arow = tid >> 2;             // 0..127
    int s_aq   = tid & 3;              // 16-fp32 quarter
    int m_a = r0 + s_arow;
    const float* a1p;
    if (gather) a1p = A1 + (long long)((m_a >> 8) * NN + gather[m_a]) * K1;
    else        a1p = A1 + (long long)m_a * K1;
    const float* a2p = A2 ? (A2 + (long long)m_a * (Ktot - K1)) : (const float*)0;

    int s_bn = tid >> 1;               // 0..255
    int s_bh = tid & 1;                // k-half (32 elems)
    long long bro = (long long)(colbase + s_bn) * ldw + s_bh * 32;

    int nsplit = (nterms == 6) ? 3 : 2;
    const int ta6[6] = {0, 0, 1, 1, 0, 2};
    const int tb6[6] = {0, 1, 0, 1, 2, 0};

    // ---- mma fragment addresses ----
    // A: row = wm*32 + mt*16 + (lane&15); kbyte = ks*32 + (lane>>4)*16
    int a_r = wm * 32 + (lane & 15);
    unsigned a_sw = (unsigned)((a_r & 7) << 4);
    unsigned a_base0 = sbase + AB_OFF + (unsigned)a_r * 128;
    unsigned a_kb0 = (unsigned)((lane >> 4) << 4);
    // B: group g=lane>>3, r=lane&7; ntile-pair p: n = wn*64 + p*16 + (g>>1)*8 + r
    int b_g = lane >> 3, b_r = lane & 7;
    unsigned b_kb0 = (unsigned)((b_g & 1) << 4);

    float acc[2][8][4];
#pragma unroll
    for (int mt = 0; mt < 2; mt++)
#pragma unroll
        for (int nt = 0; nt < 8; nt++)
#pragma unroll
            for (int c = 0; c < 4; c++) acc[mt][nt][c] = 0.0f;

    int nchunks = Ktot >> 6;
    for (int ch = 0; ch < nchunks; ch++) {
        int kc = ch << 6;
        // ---------- stage A: 16 fp32 per thread -> split -> bf16 smem ----------
        {
            const float* src = (kc < K1) ? (a1p + kc + s_aq * 16)
                                         : (a2p + (kc - K1) + s_aq * 16);
            float v[16];
#pragma unroll
            for (int j = 0; j < 4; j++) {
                float4 t4 = *(const float4*)(src + j * 4);
                v[j*4+0] = t4.x; v[j*4+1] = t4.y; v[j*4+2] = t4.z; v[j*4+3] = t4.w;
            }
            if (a1_gelu) {
#pragma unroll
                for (int j = 0; j < 16; j++) v[j] = gelu_f(v[j]);
            }
            unsigned u0[8], u1[8], u2[8];
#pragma unroll
            for (int j = 0; j < 8; j++) {
                float x = v[2*j], y = v[2*j+1];
                __nv_bfloat16 bx0 = __float2bfloat16_rn(x);
                __nv_bfloat16 by0 = __float2bfloat16_rn(y);
                float rx = x - __bfloat162float(bx0);
                float ry = y - __bfloat162float(by0);
                __nv_bfloat16 bx1 = __float2bfloat16_rn(rx);
                __nv_bfloat16 by1 = __float2bfloat16_rn(ry);
                float rx2 = rx - __bfloat162float(bx1);
                float ry2 = ry - __bfloat162float(by1);
                __nv_bfloat16 bx2 = __float2bfloat16_rn(rx2);
                __nv_bfloat16 by2 = __float2bfloat16_rn(ry2);
                u0[j] = ((unsigned)*(unsigned short*)&by0 << 16) | *(unsigned short*)&bx0;
                u1[j] = ((unsigned)*(unsigned short*)&by1 << 16) | *(unsigned short*)&bx1;
                u2[j] = ((unsigned)*(unsigned short*)&by2 << 16) | *(unsigned short*)&bx2;
            }
            unsigned rsw = (unsigned)((s_arow & 7) << 4);
            unsigned rb = (unsigned)s_arow * 128;
#pragma unroll
            for (int j8 = 0; j8 < 4; j8++) {
                unsigned kb = (unsigned)(s_aq * 32 + j8 * 8) ^ rsw;
                *(uint2*)(smem + AB_OFF + rb + kb) = make_uint2(u0[2*j8], u0[2*j8+1]);
                *(uint2*)(smem + AB_OFF + A_TERM + rb + kb) = make_uint2(u1[2*j8], u1[2*j8+1]);
                if (nsplit == 3)
                    *(uint2*)(smem + AB_OFF + 2*A_TERM + rb + kb) = make_uint2(u2[2*j8], u2[2*j8+1]);
            }
        }
        // ---------- stage B: copy pre-split weights ----------
        {
            unsigned nsw = (unsigned)((s_bn & 7) << 4);
            unsigned nb = (unsigned)s_bn * 128;
            long long goff = bro + kc;
#pragma unroll
            for (int w = 0; w < 3; w++) {
                if (w >= nsplit) break;
                const __nv_bfloat16* Wsrc = (w == 0) ? W0 : ((w == 1) ? W1 : W2s);
                const uint4* sp = (const uint4*)(Wsrc + goff);
                char* dst = smem + BB_OFF + w * B_TERM;
#pragma unroll
                for (int i = 0; i < 4; i++) {
                    uint4 x = sp[i];
                    unsigned kb = (unsigned)(s_bh * 64 + i * 16) ^ nsw;
                    *(uint4*)(dst + nb + kb) = x;
                }
            }
        }
        __syncthreads();

        // ---------- mma ----------
        for (int p = 0; p < nterms; p++) {
            unsigned Ab = sbase + AB_OFF + ta6[p] * A_TERM;
            unsigned Bb = sbase + BB_OFF + tb6[p] * B_TERM;
#pragma unroll
            for (int ks = 0; ks < 4; ks++) {
                unsigned a0[4], a1r[4];
                unsigned akb = ((unsigned)(ks * 32) + a_kb0) ^ a_sw;
                ldsm4(a0[0], a0[1], a0[2], a0[3], Ab + (unsigned)a_r * 128 + akb);
                ldsm4(a1r[0], a1r[1], a1r[2], a1r[3], Ab + (unsigned)(a_r + 16) * 128 + akb);
#pragma unroll
                for (int np = 0; np < 4; np++) {
                    int n = wn * 64 + np * 16 + ((b_g >> 1) << 3) + b_r;
                    unsigned bkb = ((unsigned)(ks * 32) + b_kb0) ^ (unsigned)((n & 7) << 4);
                    unsigned b0, b1, b2, b3;
                    ldsm4(b0, b1, b2, b3, Bb + (unsigned)n * 128 + bkb);
                    mma_bf16(acc[0][2*np],   a0[0], a0[1], a0[2], a0[3], b0, b1);
                    mma_bf16(acc[0][2*np+1], a0[0], a0[1], a0[2], a0[3], b2, b3);
                    mma_bf16(acc[1][2*np],   a1r[0], a1r[1], a1r[2], a1r[3], b0, b1);
                    mma_bf16(acc[1][2*np+1], a1r[0], a1r[1], a1r[2], a1r[3], b2, b3);
                }
            }
        }
        __syncthreads();
    }

    // ================= epilogue =================
    // thread cols (local): nt*8 + 2*(lane&3) + {0,1}; rows: wm*32 + mt*16 + lane/4 + half*8
    int qd = lane & 3;
    int rql = lane >> 2;
    float bv[16];
#pragma unroll
    for (int nt = 0; nt < 8; nt++) {
        int cg = colbase + wn * 64 + nt * 8 + 2 * qd;
        float2 t2 = *(const float2*)(bias + cg);
        bv[2*nt] = t2.x; bv[2*nt+1] = t2.y;
    }

    if (mode == 0) {
#pragma unroll
        for (int mt = 0; mt < 2; mt++)
#pragma unroll
            for (int hf = 0; hf < 2; hf++) {
                int m = r0 + wm * 32 + mt * 16 + rql + hf * 8;
                float sc = rowscale ? rowscale[m] : 1.0f;
#pragma unroll
                for (int nt = 0; nt < 8; nt++) {
                    int cg = colbase + wn * 64 + nt * 8 + 2 * qd;
                    float2 o;
                    o.x = (acc[mt][nt][2*hf]   + bv[2*nt])   * sc;
                    o.y = (acc[mt][nt][2*hf+1] + bv[2*nt+1]) * sc;
                    *(float2*)(C + (long long)m * ldc + cg) = o;
                }
            }
        return;
    }

    // reductions across the 4 wn-warps via smem (A region reused)
    float* red = (float*)smem;          // [128][4] x2 planes
    float* red2 = red + 512;

    if (mode == 2) {
#pragma unroll
        for (int mt = 0; mt < 2; mt++)
#pragma unroll
            for (int hf = 0; hf < 2; hf++) {
                float s = 0.0f, sq = 0.0f;
#pragma unroll
                for (int nt = 0; nt < 8; nt++) {
                    float f0 = acc[mt][nt][2*hf]   + bv[2*nt];
                    float f1 = acc[mt][nt][2*hf+1] + bv[2*nt+1];
                    s += f0 + f1; sq += f0 * f0 + f1 * f1;
                }
                s  += __shfl_xor_sync(0xffffffffu, s, 1);
                s  += __shfl_xor_sync(0xffffffffu, s, 2);
                sq += __shfl_xor_sync(0xffffffffu, sq, 1);
                sq += __shfl_xor_sync(0xffffffffu, sq, 2);
                if (qd == 0) {
                    int rl = wm * 32 + mt * 16 + rql + hf * 8;
                    red[rl * 4 + wn] = s;
                    red2[rl * 4 + wn] = sq;
                }
            }
        __syncthreads();
        float* stats = red2 + 512;      // [128][2]
        if (tid < 128) {
            float s = red[tid*4] + red[tid*4+1] + red[tid*4+2] + red[tid*4+3];
            float sq = red2[tid*4] + red2[tid*4+1] + red2[tid*4+2] + red2[tid*4+3];
            float mu = s * (1.0f / 256.0f);
            float var = sq * (1.0f / 256.0f) - mu * mu;
            stats[tid*2] = mu;
            stats[tid*2+1] = rsqrtf(var + 1e-5f);
        }
        __syncthreads();
        float gv[16], ev[16];
#pragma unroll
        for (int nt = 0; nt < 8; nt++) {
            int cg = wn * 64 + nt * 8 + 2 * qd;
            float2 tg = *(const float2*)(lng + cg);
            float2 te = *(const float2*)(lnb + cg);
            gv[2*nt] = tg.x; gv[2*nt+1] = tg.y;
            ev[2*nt] = te.x; ev[2*nt+1] = te.y;
        }
#pragma unroll
        for (int mt = 0; mt < 2; mt++)
#pragma unroll
            for (int hf = 0; hf < 2; hf++) {
                int rl = wm * 32 + mt * 16 + rql + hf * 8;
                int m = r0 + rl;
                float mu = stats[rl*2], inv = stats[rl*2+1];
#pragma unroll
                for (int nt = 0; nt < 8; nt++) {
                    int cg = wn * 64 + nt * 8 + 2 * qd;
                    float2 o;
                    float f0 = acc[mt][nt][2*hf]   + bv[2*nt];
                    float f1 = acc[mt][nt][2*hf+1] + bv[2*nt+1];
                    o.x = (f0 - mu) * inv * gv[2*nt]   + ev[2*nt];
                    o.y = (f1 - mu) * inv * gv[2*nt+1] + ev[2*nt+1];
                    *(float2*)(C + (long long)m * ldc + cg) = o;
                }
            }
        return;
    }

    // mode 3: gelu + dot(w2) + sigmoid blend
    {
        float wv[16];
#pragma unroll
        for (int nt = 0; nt < 8; nt++) {
            int cg = wn * 64 + nt * 8 + 2 * qd;
            float2 tw = *(const float2*)(w2 + cg);
            wv[2*nt] = tw.x; wv[2*nt+1] = tw.y;
        }
#pragma unroll
        for (int mt = 0; mt < 2; mt++)
#pragma unroll
            for (int hf = 0; hf < 2; hf++) {
                float d = 0.0f;
#pragma unroll
                for (int nt = 0; nt < 8; nt++) {
                    float f0 = gelu_f(acc[mt][nt][2*hf]   + bv[2*nt]);
                    float f1 = gelu_f(acc[mt][nt][2*hf+1] + bv[2*nt+1]);
                    d += f0 * wv[2*nt] + f1 * wv[2*nt+1];
                }
                d += __shfl_xor_sync(0xffffffffu, d, 1);
                d += __shfl_xor_sync(0xffffffffu, d, 2);
                if (qd == 0) {
                    int rl = wm * 32 + mt * 16 + rql + hf * 8;
                    red[rl * 4 + wn] = d;
                }
            }
        __syncthreads();
        if (tid < 128) {
            float d = red[tid*4] + red[tid*4+1] + red[tid*4+2] + red[tid*4+3];
            float dl = 1.0f / (1.0f + expf(-(d + b2[0])));
            int m = r0 + tid;
            float na = 0.7f * act_in[m] + 0.3f * dl;
            na = fminf(fmaxf(na, 0.0f), 1.0f);
            act_out[m] = na;
        }
    }
}

// ------------------------- scalar GEMM (sparse scatter-accum) --------
__global__ __launch_bounds__(TTH, 1)
void gemm2(const float* __restrict__ A1,
           const float* __restrict__ Wt, int ldw,
           float* __restrict__ C, const int* __restrict__ cgather, int ldc,
           int Ktot) {
    extern __shared__ float sm[];
    float* As = sm;
    float* Ws = sm + 2 * TBK * 132;

    int tid = threadIdx.x;
    int r0 = blockIdx.x * TBM;

    int am = tid >> 2;
    int ak = (tid & 3) << 2;
    int m_a = r0 + am;
    const float* a1row = A1 + (long long)m_a * Ktot;

    int wr = tid >> 5;
    int wc = (tid & 31) << 3;
    const float* wbase = Wt + (long long)wr * ldw + wc;

    float4 av, wv0, wv1;
#define LOAD_ST(kb) do {                                                      \
        av = *(const float4*)(a1row + (kb) + ak);                             \
        const float* wp_ = wbase + (long long)(kb) * ldw;                     \
        wv0 = *(const float4*)(wp_);                                          \
        wv1 = *(const float4*)(wp_ + 4);                                      \
    } while (0)
#define STORE_ST(buf) do {                                                    \
        float* ap_ = As + (buf) * (TBK * 132);                                \
        ap_[(ak + 0) * 132 + am] = av.x;                                      \
        ap_[(ak + 1) * 132 + am] = av.y;                                      \
        ap_[(ak + 2) * 132 + am] = av.z;                                      \
        ap_[(ak + 3) * 132 + am] = av.w;                                      \
        float* wpS_ = Ws + (buf) * (TBK * 256) + wr * 256 + wc;               \
        *(float4*)wpS_ = wv0;                                                 \
        *(float4*)(wpS_ + 4) = wv1;                                           \
    } while (0)

    int lane = tid & 31, warp = tid >> 5;
    int row0 = warp << 3, col0 = lane << 3;

    float acc[8][8];
#pragma unroll
    for (int r = 0; r < 8; r++)
#pragma unroll
        for (int c = 0; c < 8; c++) acc[r][c] = 0.0f;

    LOAD_ST(0); STORE_ST(0);
    __syncthreads();

    int S = Ktot / TBK;
    for (int s = 0; s < S; s++) {
        int cur = s & 1;
        if (s + 1 < S) LOAD_ST((s + 1) * TBK);
        const float* ab = As + cur * (TBK * 132);
        const float* wb = Ws + cur * (TBK * 256);
#pragma unroll
        for (int k = 0; k < TBK; k++) {
            float4 a0 = *(const float4*)(ab + k * 132 + row0);
            float4 a1v = *(const float4*)(ab + k * 132 + row0 + 4);
            float4 b0 = *(const float4*)(wb + k * 256 + col0);
            float4 b1 = *(const float4*)(wb + k * 256 + col0 + 4);
            float aa[8] = {a0.x, a0.y, a0.z, a0.w, a1v.x, a1v.y, a1v.z, a1v.w};
            float bvv[8] = {b0.x, b0.y, b0.z, b0.w, b1.x, b1.y, b1.z, b1.w};
#pragma unroll
            for (int r = 0; r < 8; r++)
#pragma unroll
                for (int c = 0; c < 8; c++) acc[r][c] += aa[r] * bvv[c];
        }
        if (s + 1 < S) { STORE_ST((s + 1) & 1); __syncthreads(); }
    }

#pragma unroll
    for (int r = 0; r < 8; r++) {
        int m = r0 + row0 + r;
        long long crow = (long long)((m >> 8) * NN + cgather[m]);
        float* cp = C + crow * ldc + col0;
        float4 o0 = *(float4*)cp, o1 = *(float4*)(cp + 4);
        o0.x += acc[r][0]; o0.y += acc[r][1]; o0.z += acc[r][2]; o0.w += acc[r][3];
        o1.x += acc[r][4]; o1.y += acc[r][5]; o1.z += acc[r][6]; o1.w += acc[r][7];
        *(float4*)cp = o0; *(float4*)(cp + 4) = o1;
    }
}

// ------------------------- attention -------------------------
__global__ void attn_kernel(const float* __restrict__ qkv, float* __restrict__ out) {
    extern __shared__ float sm[];
    float* Ks = sm;
    float* Vs = sm + MSGK * HD;
    int bh = blockIdx.x;
    int b = bh >> 2;
    int h = bh & 3;
    int tid = threadIdx.x;
    const float* base = qkv + (long long)b * MSGK * 768;

    for (int t = tid; t < MSGK * HD; t += 256) {
        int j = t >> 6;
        int d = t & 63;
        Ks[t] = base[j * 768 + 256 + h * 64 + d];
        Vs[t] = base[j * 768 + 512 + h * 64 + d];
    }
    __syncthreads();

    float q[HD], o[HD];
#pragma unroll
    for (int d = 0; d < HD; d++) { q[d] = base[tid * 768 + h * 64 + d] * 0.125f; o[d] = 0.0f; }

    float mval = -1e30f, l = 0.0f;
    for (int j = 0; j < MSGK; j++) {
        float s = 0.0f;
#pragma unroll
        for (int d = 0; d < HD; d++) s += q[d] * Ks[j * 64 + d];
        float nm = fmaxf(mval, s);
        float corr = expf(mval - nm);
        float p = expf(s - nm);
        l = l * corr + p;
#pragma unroll
        for (int d = 0; d < HD; d++) o[d] = o[d] * corr + p * Vs[j * 64 + d];
        mval = nm;
    }
    float inv = 1.0f / l;
    float* op = out + ((long long)(b * MSGK + tid)) * DD + h * 64;
#pragma unroll
    for (int d = 0; d < HD; d++) op[d] = o[d] * inv;
}

// ------------------------- finalize -------------------------
__global__ void finalize_kernel(const float* __restrict__ newact, const float* __restrict__ newhid,
                                const int* __restrict__ slot2, float* __restrict__ out) {
    long long total_act = (long long)BB * NN;
    float* out_act = out;
    float* out_hid = out + total_act;
    long long stride = (long long)gridDim.x * blockDim.x;
    long long t0 = (long long)blockIdx.x * blockDim.x + threadIdx.x;

    for (long long i = t0; i < total_act; i += stride)
        out_act[i] = (slot2[i] >= 0) ? newact[i] : 0.0f;

    long long totalh4 = (long long)BB * NN * DD / 4;
    float4* oh4 = reinterpret_cast<float4*>(out_hid);
    const float4* nh4 = reinterpret_cast<const float4*>(newhid);
    for (long long e = t0; e < totalh4; e += stride) {
        long long r = e >> 6;
        oh4[e] = (slot2[r] >= 0) ? nh4[e] : make_float4(0.f, 0.f, 0.f, 0.f);
    }
}

// ------------------------- host launcher -------------------------
extern "C" void kernel_launch(void* const* d_in, const int* in_sizes, int n_in,
                              void* d_out, int out_size) {
    const float* act    = (const float*)d_in[0];
    const float* hidden = (const float*)d_in[1];
    const float* in_w   = (const float*)d_in[2];
    const float* in_b   = (const float*)d_in[3];
    const float* out_w  = (const float*)d_in[4];
    const float* out_b  = (const float*)d_in[5];
    const float* su_w1  = (const float*)d_in[6];
    const float* su_b1  = (const float*)d_in[7];
    const float* su_w2  = (const float*)d_in[8];
    const float* su_b2  = (const float*)d_in[9];
    const float* au_w1  = (const float*)d_in[10];
    const float* au_b1  = (const float*)d_in[11];
    const float* au_w2  = (const float*)d_in[12];
    const float* au_b2  = (const float*)d_in[13];
    const float* ln_g   = (const float*)d_in[14];
    const float* ln_b   = (const float*)d_in[15];
    const int*   kptr   = (const int*)d_in[16];

    int*   p_tidx;   cudaGetSymbolAddress((void**)&p_tidx,   g_tidx);
    float* p_tval;   cudaGetSymbolAddress((void**)&p_tval,   g_tval);
    int*   p_slot;   cudaGetSymbolAddress((void**)&p_slot,   g_slot);
    int*   p_slot2;  cudaGetSymbolAddress((void**)&p_slot2,  g_slot2);
    float* p_qkv;    cudaGetSymbolAddress((void**)&p_qkv,    g_qkv);
    float* p_attn;   cudaGetSymbolAddress((void**)&p_attn,   g_attn);
    float* p_msg;    cudaGetSymbolAddress((void**)&p_msg,    g_msg);
    float* p_h;      cudaGetSymbolAddress((void**)&p_h,      g_h);
    float* p_newhid; cudaGetSymbolAddress((void**)&p_newhid, g_newhid);
    float* p_newact; cudaGetSymbolAddress((void**)&p_newact, g_newact);
    float* wt_su1;   cudaGetSymbolAddress((void**)&wt_su1,   g_wt_su1);

    __nv_bfloat16 *in0,*in1,*in2, *ow0,*ow1,*ow2, *s10,*s11,*s12, *s20,*s21,*s22, *a10,*a11,*a12;
    cudaGetSymbolAddress((void**)&in0, g_in0); cudaGetSymbolAddress((void**)&in1, g_in1);
    cudaGetSymbolAddress((void**)&in2, g_in2);
    cudaGetSymbolAddress((void**)&ow0, g_ow0); cudaGetSymbolAddress((void**)&ow1, g_ow1);
    cudaGetSymbolAddress((void**)&ow2, g_ow2);
    cudaGetSymbolAddress((void**)&s10, g_s10); cudaGetSymbolAddress((void**)&s11, g_s11);
    cudaGetSymbolAddress((void**)&s12, g_s12);
    cudaGetSymbolAddress((void**)&s20, g_s20); cudaGetSymbolAddress((void**)&s21, g_s21);
    cudaGetSymbolAddress((void**)&s22, g_s22);
    cudaGetSymbolAddress((void**)&a10, g_a10); cudaGetSymbolAddress((void**)&a11, g_a11);
    cudaGetSymbolAddress((void**)&a12, g_a12);

    const int SMEM_GEMM2 = (2 * TBK * 132 + 2 * TBK * 256) * 4;
    const int SMEM_ATTN  = 2 * MSGK * HD * 4;

    cudaFuncSetAttribute(mma_gemm, cudaFuncAttributeMaxDynamicSharedMemorySize, TC_SMEM);
    cudaFuncSetAttribute(gemm2, cudaFuncAttributeMaxDynamicSharedMemorySize, SMEM_GEMM2);
    cudaFuncSetAttribute(attn_kernel, cudaFuncAttributeMaxDynamicSharedMemorySize, SMEM_ATTN);

    // 0) weight prep
    split3_kernel<<<768, 256>>>(in_w,  in0, in1, in2, 768 * 256);
    split3_kernel<<<256, 256>>>(out_w, ow0, ow1, ow2, 256 * 256);
    split3_kernel<<<512, 256>>>(su_w1, s10, s11, s12, 256 * 512);
    split3_kernel<<<256, 256>>>(su_w2, s20, s21, s22, 256 * 256);
    split3_kernel<<<512, 256>>>(au_w1, a10, a11, a12, 256 * 512);
    transpose_kernel<<<dim3(16, 8), dim3(32, 8)>>>(su_w1, wt_su1, 256, 512);

    // 1) top-k of activation
    sort_topk_kernel<<<BB, 1024>>>(act, nullptr, MSGK, p_tidx, p_tval, p_slot);

    // 2) QKV: gathered rows, [8192,256] @ in_w^T -> [8192,768]   (3-term)
    mma_gemm<<<dim3(64, 3), 512, TC_SMEM>>>(
        hidden, nullptr, p_tidx, in0, in1, in2, 256, in_b,
        nullptr, nullptr, nullptr, nullptr, nullptr, nullptr, nullptr,
        p_qkv, 768, 256, 256, 0, 3, 0);

    // 3) attention
    attn_kernel<<<BB * 4, 256, SMEM_ATTN>>>(p_qkv, p_attn);

    // 4) out-proj * topk_val -> msg   (3-term)
    mma_gemm<<<dim3(64, 1), 512, TC_SMEM>>>(
        p_attn, nullptr, nullptr, ow0, ow1, ow2, 256, out_b,
        p_tval, nullptr, nullptr, nullptr, nullptr, nullptr, nullptr,
        p_msg, 256, 256, 256, 0, 3, 0);

    // 5a) su1 dense: pre = hidden @ W1a^T + b1   (6-term)
    mma_gemm<<<dim3(1024, 1), 512, TC_SMEM>>>(
        hidden, nullptr, nullptr, s10, s11, s12, 512, su_b1,
        nullptr, nullptr, nullptr, nullptr, nullptr, nullptr, nullptr,
        p_h, 256, 256, 256, 0, 6, 0);

    // 5b) su1 sparse: pre[active] += msg @ W1b^T  (scalar fp32, exact)
    gemm2<<<dim3(64, 1), TTH, SMEM_GEMM2>>>(
        p_msg, wt_su1 + 256 * 256, 256, p_h, p_tidx, 256, 256);

    // 6) su2: newhid = LN( gelu(pre) @ W2^T + b2 )   (6-term, gelu on A-load)
    mma_gemm<<<dim3(1024, 1), 512, TC_SMEM>>>(
        p_h, nullptr, nullptr, s20, s21, s22, 256, su_b2,
        nullptr, ln_g, ln_b, nullptr, nullptr, nullptr, nullptr,
        p_newhid, 256, 256, 256, 1, 6, 2);

    // 7) au1 fused act update   (6-term)
    mma_gemm<<<dim3(1024, 1), 512, TC_SMEM>>>(
        hidden, p_newhid, nullptr, a10, a11, a12, 512, au_b1,
        nullptr, nullptr, nullptr, au_w2, au_b2, act, p_newact,
        nullptr, 256, 256, 512, 0, 6, 3);

    // 8) final top-k (k from device sparsity_k)
    sort_topk_kernel<<<BB, 1024>>>(p_newact, kptr, 0, nullptr, nullptr, p_slot2);

    // 9) masked write [sparse_act | sparse_hidden]
    finalize_kernel<<<2048, 256>>>(p_newact, p_newhid, p_slot2, (float*)d_out);
}

// round 8
// speedup vs baseline: 6.3343x; 1.0162x over previous
#include <cuda_runtime.h>
#include <cuda_bf16.h>
#include <math.h>

#define BB 32
#define NN 4096
#define DD 256
#define MSGK 256
#define HD 64

// scalar gemm (sparse scatter-accum only)
#define TBM 128
#define TBK 16
#define TTH 512

// ------------------------- device scratch -------------------------
__device__ int   g_tidx[BB * MSGK];
__device__ float g_tval[BB * MSGK];
__device__ int   g_slot[BB * NN];
__device__ int   g_slot2[BB * NN];
__device__ float g_qkv[BB * MSGK * 3 * DD];
__device__ float g_attn[BB * MSGK * DD];
__device__ float g_msg[BB * MSGK * DD];
__device__ float g_h[(size_t)BB * NN * DD];
__device__ float g_newhid[(size_t)BB * NN * DD];
__device__ float g_newact[BB * NN];
__device__ float g_wt_su1[512 * 256];

// bf16 3-way splits of weights
__device__ __nv_bfloat16 g_in0[768*256],  g_in1[768*256],  g_in2[768*256];
__device__ __nv_bfloat16 g_ow0[256*256],  g_ow1[256*256],  g_ow2[256*256];
__device__ __nv_bfloat16 g_s10[256*512],  g_s11[256*512],  g_s12[256*512];
__device__ __nv_bfloat16 g_s20[256*256],  g_s21[256*256],  g_s22[256*256];
__device__ __nv_bfloat16 g_a10[256*512],  g_a11[256*512],  g_a12[256*512];

// bf16 3-way splits of activations
__device__ __nv_bfloat16 g_h0[(size_t)BB*NN*DD], g_h1[(size_t)BB*NN*DD], g_h2[(size_t)BB*NN*DD];
__device__ __nv_bfloat16 g_n0[(size_t)BB*NN*DD], g_n1[(size_t)BB*NN*DD], g_n2[(size_t)BB*NN*DD];

__device__ __forceinline__ float gelu_f(float x) {
    return 0.5f * x * (1.0f + erff(x * 0.70710678118654752440f));
}

__device__ __forceinline__ unsigned smem_u32(const void* p) {
    unsigned a;
    asm("{ .reg .u64 t; cvta.to.shared.u64 t, %1; cvt.u32.u64 %0, t; }" : "=r"(a) : "l"(p));
    return a;
}

__device__ __forceinline__ void ldsm4(unsigned& r0, unsigned& r1, unsigned& r2, unsigned& r3,
                                      unsigned addr) {
    asm volatile("ldmatrix.sync.aligned.m8n8.x4.shared.b16 {%0,%1,%2,%3}, [%4];"
                 : "=r"(r0), "=r"(r1), "=r"(r2), "=r"(r3) : "r"(addr));
}

__device__ __forceinline__ void mma_bf16(float* c, unsigned a0, unsigned a1, unsigned a2,
                                         unsigned a3, unsigned b0, unsigned b1) {
    asm volatile("mma.sync.aligned.m16n8k16.row.col.f32.bf16.bf16.f32 "
                 "{%0,%1,%2,%3},{%4,%5,%6,%7},{%8,%9},{%0,%1,%2,%3};"
                 : "+f"(c[0]), "+f"(c[1]), "+f"(c[2]), "+f"(c[3])
                 : "r"(a0), "r"(a1), "r"(a2), "r"(a3), "r"(b0), "r"(b1));
}

#define CPASYNC16(dst, src) \
    asm volatile("cp.async.cg.shared.global [%0], [%1], 16;" :: "r"(dst), "l"(src) : "memory")
#define CPCOMMIT() asm volatile("cp.async.commit_group;" ::: "memory")
#define CPWAIT0() asm volatile("cp.async.wait_group 0;" ::: "memory")
#define CPWAIT1() asm volatile("cp.async.wait_group 1;" ::: "memory")

// ------------------------- weight split -------------------------
__global__ void split3_kernel(const float* __restrict__ W, __nv_bfloat16* o0,
                              __nv_bfloat16* o1, __nv_bfloat16* o2, int n) {
    int i = blockIdx.x * 256 + threadIdx.x;
    if (i < n) {
        float v = W[i];
        __nv_bfloat16 b0 = __float2bfloat16_rn(v);
        float r = v - __bfloat162float(b0);
        __nv_bfloat16 b1 = __float2bfloat16_rn(r);
        float r2 = r - __bfloat162float(b1);
        o0[i] = b0; o1[i] = b1; o2[i] = __float2bfloat16_rn(r2);
    }
}

// ------------------------- weight transpose (scalar scatter gemm) ------------
__global__ void transpose_kernel(const float* __restrict__ W, float* __restrict__ Wt,
                                 int Nout, int Kd) {
    __shared__ float t[32][33];
    int k0 = blockIdx.x * 32, n0 = blockIdx.y * 32;
    int tx = threadIdx.x, ty = threadIdx.y;
#pragma unroll
    for (int i = 0; i < 32; i += 8)
        t[ty + i][tx] = W[(long long)(n0 + ty + i) * Kd + k0 + tx];
    __syncthreads();
#pragma unroll
    for (int i = 0; i < 32; i += 8)
        Wt[(long long)(k0 + ty + i) * Nout + n0 + tx] = t[tx][ty + i];
}

// ------------------------- top-k via bitonic sort -------------------------
__global__ void sort_topk_kernel(const float* __restrict__ act,
                                 const int* __restrict__ kptr, int kconst,
                                 int* __restrict__ idx_out, float* __restrict__ val_out,
                                 int* __restrict__ slotmap) {
    __shared__ float sv[NN];
    __shared__ int   si[NN];
    int b = blockIdx.x;
    int tid = threadIdx.x;
    int kk = kptr ? *kptr : kconst;
    if (kk > NN) kk = NN;
    if (kk < 0) kk = 0;

    for (int i = tid; i < NN; i += blockDim.x) { sv[i] = act[b * NN + i]; si[i] = i; }
    __syncthreads();

    for (int ksz = 2; ksz <= NN; ksz <<= 1) {
        for (int j = ksz >> 1; j > 0; j >>= 1) {
            for (int i = tid; i < NN; i += blockDim.x) {
                int ixj = i ^ j;
                if (ixj > i) {
                    bool dirDesc = ((i & ksz) == 0);
                    float vi = sv[i], vx = sv[ixj];
                    bool sw = dirDesc ? (vi < vx) : (vi > vx);
                    if (sw) {
                        sv[i] = vx; sv[ixj] = vi;
                        int t = si[i]; si[i] = si[ixj]; si[ixj] = t;
                    }
                }
            }
            __syncthreads();
        }
    }

    for (int i = tid; i < NN; i += blockDim.x) slotmap[b * NN + i] = -1;
    __syncthreads();
    for (int j = tid; j < kk; j += blockDim.x) {
        slotmap[b * NN + si[j]] = j;
        if (idx_out) { idx_out[b * kk + j] = si[j]; val_out[b * kk + j] = sv[j]; }
    }
}

// ======================= pre-split pipelined tensor GEMM =======================
// A given as bf16 planes (3-way split). K1 part from A-planes (optional row gather),
// K2 part from Z-planes. W as bf16 planes. cp.async double-buffered, KC=32.
// CTA 128x256, 512 threads, 16 warps (4m x 4n).
// mode 0: bias store. mode 3: bias + gelu + dot(w2) + sigmoid blend -> act_out.
#define PS_KC 32
#define PS_AP 8192
#define PS_BOFF 24576
#define PS_BP 16384
#define PS_STAGE 73728
#define PS_SMEM (2 * PS_STAGE)   // 147456

__global__ __launch_bounds__(512, 1)
void mma_gemm_ps(const __nv_bfloat16* __restrict__ A0, const __nv_bfloat16* __restrict__ A1p,
                 const __nv_bfloat16* __restrict__ A2p,
                 const __nv_bfloat16* __restrict__ Z0, const __nv_bfloat16* __restrict__ Z1,
                 const __nv_bfloat16* __restrict__ Z2,
                 const int* __restrict__ gather,
                 const __nv_bfloat16* __restrict__ W0, const __nv_bfloat16* __restrict__ W1,
                 const __nv_bfloat16* __restrict__ W2s, int ldw,
                 const float* __restrict__ bias,
                 const float* __restrict__ w2, const float* __restrict__ b2,
                 const float* __restrict__ act_in, float* __restrict__ act_out,
                 float* __restrict__ C, int ldc,
                 int K1, int lda1, int lda2, int Ktot, int nterms, int mode) {
    extern __shared__ char smem[];
    unsigned sbase = smem_u32(smem);
    int tid = threadIdx.x;
    int lane = tid & 31;
    int wid = tid >> 5;
    int wm = wid & 3;
    int wn = wid >> 2;
    int r0 = blockIdx.x * 128;
    int colbase = blockIdx.y * 256;
    int nsplit = (nterms == 6) ? 3 : 2;

    // ---- staging maps ----
    int arow = tid >> 2, au = tid & 3;
    int m_a = r0 + arow;
    long long ridx1 = gather ? (long long)((m_a >> 8) * NN + gather[m_a]) : m_a;
    const char* a1b0 = (const char*)(A0 + ridx1 * lda1);
    const char* a1b1 = (const char*)(A1p + ridx1 * lda1);
    const char* a1b2 = A2p ? (const char*)(A2p + ridx1 * lda1) : a1b1;
    const char* a2b0 = Z0 ? (const char*)(Z0 + (long long)m_a * lda2) : a1b0;
    const char* a2b1 = Z1 ? (const char*)(Z1 + (long long)m_a * lda2) : a1b1;
    const char* a2b2 = Z2 ? (const char*)(Z2 + (long long)m_a * lda2) : a1b2;
    unsigned aswz = ((arow >> 1) & 3) << 4;
    unsigned adst0 = (unsigned)arow * 64 + ((au * 16) ^ aswz);

    int bn = tid >> 1;
    int bu0 = (tid & 1) * 2;
    unsigned bswz = ((bn >> 1) & 3) << 4;
    long long brow = (long long)(colbase + bn) * ldw;

    const int ta6[6] = {0, 0, 1, 1, 0, 2};
    const int tb6[6] = {0, 1, 0, 1, 2, 0};

    // ---- mma fragment addressing ----
    int a_r = wm * 32 + (lane & 15);
    unsigned a_k0 = (unsigned)((lane >> 4) << 4);
    unsigned a_sw = ((a_r >> 1) & 3) << 4;
    int b_g = lane >> 3, b_r = lane & 7;
    int b_n0 = wn * 64 + ((b_g >> 1) << 3) + b_r;
    unsigned b_k0 = (unsigned)((b_g & 1) << 4);

    float acc[2][8][4];
#pragma unroll
    for (int mt = 0; mt < 2; mt++)
#pragma unroll
        for (int nt = 0; nt < 8; nt++)
#pragma unroll
            for (int c = 0; c < 4; c++) acc[mt][nt][c] = 0.0f;

    int nc = Ktot >> 5;

#define PS_STAGE_FN(c_) do {                                                   \
        int buf_ = (c_) & 1;                                                   \
        unsigned stg_ = sbase + buf_ * PS_STAGE;                               \
        int kc_ = (c_) << 5;                                                   \
        const char *p0_, *p1_, *p2_; long long ko_;                            \
        if (kc_ < K1) { p0_ = a1b0; p1_ = a1b1; p2_ = a1b2; ko_ = kc_; }       \
        else          { p0_ = a2b0; p1_ = a2b1; p2_ = a2b2; ko_ = kc_ - K1; }  \
        long long ab_ = ko_ * 2 + au * 16;                                     \
        unsigned ad_ = stg_ + adst0;                                           \
        CPASYNC16(ad_, p0_ + ab_);                                             \
        CPASYNC16(ad_ + PS_AP, p1_ + ab_);                                     \
        if (nsplit == 3) CPASYNC16(ad_ + 2 * PS_AP, p2_ + ab_);                \
        long long bo_ = (brow + kc_) * 2;                                      \
        unsigned bd_ = stg_ + PS_BOFF + (unsigned)bn * 64;                     \
        unsigned k0_ = (unsigned)(bu0 * 16), k1_ = k0_ + 16;                   \
        CPASYNC16(bd_ + (k0_ ^ bswz), (const char*)W0 + bo_ + k0_);            \
        CPASYNC16(bd_ + (k1_ ^ bswz), (const char*)W0 + bo_ + k1_);            \
        CPASYNC16(bd_ + PS_BP + (k0_ ^ bswz), (const char*)W1 + bo_ + k0_);    \
        CPASYNC16(bd_ + PS_BP + (k1_ ^ bswz), (const char*)W1 + bo_ + k1_);    \
        if (nsplit == 3) {                                                     \
            CPASYNC16(bd_ + 2*PS_BP + (k0_ ^ bswz), (const char*)W2s + bo_ + k0_); \
            CPASYNC16(bd_ + 2*PS_BP + (k1_ ^ bswz), (const char*)W2s + bo_ + k1_); \
        }                                                                      \
    } while (0)

    PS_STAGE_FN(0);
    CPCOMMIT();

    for (int c = 0; c < nc; c++) {
        if (c + 1 < nc) { PS_STAGE_FN(c + 1); CPCOMMIT(); CPWAIT1(); }
        else            { CPWAIT0(); }
        __syncthreads();

        unsigned stg = sbase + (c & 1) * PS_STAGE;
        for (int p = 0; p < nterms; p++) {
            unsigned Ab = stg + ta6[p] * PS_AP;
            unsigned Bb = stg + PS_BOFF + tb6[p] * PS_BP;
#pragma unroll
            for (int ks = 0; ks < 2; ks++) {
                unsigned akb = ((unsigned)(ks << 5) + a_k0) ^ a_sw;
                unsigned a0[4], a1r[4];
                ldsm4(a0[0], a0[1], a0[2], a0[3], Ab + (unsigned)a_r * 64 + akb);
                ldsm4(a1r[0], a1r[1], a1r[2], a1r[3], Ab + (unsigned)(a_r + 16) * 64 + akb);
#pragma unroll
                for (int np = 0; np < 4; np++) {
                    int n = b_n0 + np * 16;
                    unsigned bkb = ((unsigned)(ks << 5) + b_k0) ^ (unsigned)(((n >> 1) & 3) << 4);
                    unsigned b0, b1, b2, b3;
                    ldsm4(b0, b1, b2, b3, Bb + (unsigned)n * 64 + bkb);
                    mma_bf16(acc[0][2*np],   a0[0], a0[1], a0[2], a0[3], b0, b1);
                    mma_bf16(acc[0][2*np+1], a0[0], a0[1], a0[2], a0[3], b2, b3);
                    mma_bf16(acc[1][2*np],   a1r[0], a1r[1], a1r[2], a1r[3], b0, b1);
                    mma_bf16(acc[1][2*np+1], a1r[0], a1r[1], a1r[2], a1r[3], b2, b3);
                }
            }
        }
        __syncthreads();
    }

    // ---------------- epilogue ----------------
    int qd = lane & 3;
    int rql = lane >> 2;
    float bv[16];
#pragma unroll
    for (int nt = 0; nt < 8; nt++) {
        int cg = colbase + wn * 64 + nt * 8 + 2 * qd;
        float2 t2 = *(const float2*)(bias + cg);
        bv[2*nt] = t2.x; bv[2*nt+1] = t2.y;
    }

    if (mode == 0) {
#pragma unroll
        for (int mt = 0; mt < 2; mt++)
#pragma unroll
            for (int hf = 0; hf < 2; hf++) {
                int m = r0 + wm * 32 + mt * 16 + rql + hf * 8;
#pragma unroll
                for (int nt = 0; nt < 8; nt++) {
                    int cg = colbase + wn * 64 + nt * 8 + 2 * qd;
                    float2 o;
                    o.x = acc[mt][nt][2*hf]   + bv[2*nt];
                    o.y = acc[mt][nt][2*hf+1] + bv[2*nt+1];
                    *(float2*)(C + (long long)m * ldc + cg) = o;
                }
            }
        return;
    }

    // mode 3: gelu + dot(w2) + sigmoid blend
    {
        float* red = (float*)smem;
        float wv[16];
#pragma unroll
        for (int nt = 0; nt < 8; nt++) {
            int cg = wn * 64 + nt * 8 + 2 * qd;
            float2 tw = *(const float2*)(w2 + cg);
            wv[2*nt] = tw.x; wv[2*nt+1] = tw.y;
        }
#pragma unroll
        for (int mt = 0; mt < 2; mt++)
#pragma unroll
            for (int hf = 0; hf < 2; hf++) {
                float d = 0.0f;
#pragma unroll
                for (int nt = 0; nt < 8; nt++) {
                    float f0 = gelu_f(acc[mt][nt][2*hf]   + bv[2*nt]);
                    float f1 = gelu_f(acc[mt][nt][2*hf+1] + bv[2*nt+1]);
                    d += f0 * wv[2*nt] + f1 * wv[2*nt+1];
                }
                d += __shfl_xor_sync(0xffffffffu, d, 1);
                d += __shfl_xor_sync(0xffffffffu, d, 2);
                if (qd == 0) {
                    int rl = wm * 32 + mt * 16 + rql + hf * 8;
                    red[rl * 4 + wn] = d;
                }
            }
        __syncthreads();
        if (tid < 128) {
            float d = red[tid*4] + red[tid*4+1] + red[tid*4+2] + red[tid*4+3];
            float dl = 1.0f / (1.0f + expf(-(d + b2[0])));
            int m = r0 + tid;
            float na = 0.7f * act_in[m] + 0.3f * dl;
            na = fminf(fmaxf(na, 0.0f), 1.0f);
            act_out[m] = na;
        }
    }
}

// ======================= convert-path tensor GEMM (fp32 A) =======================
#define A_TERM 16384
#define B_TERM 32768
#define AB_OFF 0
#define BB_OFF (3 * A_TERM)
#define TC_SMEM (3 * A_TERM + 3 * B_TERM)   // 147456

__global__ __launch_bounds__(512, 1)
void mma_gemm(const float* __restrict__ A1, const float* __restrict__ A2,
              const int* __restrict__ gather,
              const __nv_bfloat16* __restrict__ W0, const __nv_bfloat16* __restrict__ W1,
              const __nv_bfloat16* __restrict__ W2s, int ldw,
              const float* __restrict__ bias,
              const float* __restrict__ rowscale,
              const float* __restrict__ lng, const float* __restrict__ lnb,
              float* __restrict__ C, int ldc,
              __nv_bfloat16* __restrict__ n0p, __nv_bfloat16* __restrict__ n1p,
              __nv_bfloat16* __restrict__ n2p,
              int K1, int Ktot, int a1_gelu, int nterms, int mode) {
    extern __shared__ char smem[];
    unsigned sbase = smem_u32(smem);
    int tid = threadIdx.x;
    int lane = tid & 31;
    int wid = tid >> 5;
    int wm = wid & 3;
    int wn = wid >> 2;
    int r0 = blockIdx.x * 128;
    int colbase = blockIdx.y * 256;

    int s_arow = tid >> 2;
    int s_aq   = tid & 3;
    int m_a = r0 + s_arow;
    const float* a1p;
    if (gather) a1p = A1 + (long long)((m_a >> 8) * NN + gather[m_a]) * K1;
    else        a1p = A1 + (long long)m_a * K1;
    const float* a2p = A2 ? (A2 + (long long)m_a * (Ktot - K1)) : (const float*)0;

    int s_bn = tid >> 1;
    int s_bh = tid & 1;
    // NOTE: row base only — the k-half offset lives in kb (src AND dst).
    long long bro = (long long)(colbase + s_bn) * ldw;

    int nsplit = (nterms == 6) ? 3 : 2;
    const int ta6[6] = {0, 0, 1, 1, 0, 2};
    const int tb6[6] = {0, 1, 0, 1, 2, 0};

    int a_r = wm * 32 + (lane & 15);
    unsigned a_sw = (unsigned)((a_r & 7) << 4);
    unsigned a_kb0 = (unsigned)((lane >> 4) << 4);
    int b_g = lane >> 3, b_r = lane & 7;
    unsigned b_kb0 = (unsigned)((b_g & 1) << 4);

    float acc[2][8][4];
#pragma unroll
    for (int mt = 0; mt < 2; mt++)
#pragma unroll
        for (int nt = 0; nt < 8; nt++)
#pragma unroll
            for (int c = 0; c < 4; c++) acc[mt][nt][c] = 0.0f;

    int nchunks = Ktot >> 6;
    for (int ch = 0; ch < nchunks; ch++) {
        int kc = ch << 6;
        {
            const float* src = (kc < K1) ? (a1p + kc + s_aq * 16)
                                         : (a2p + (kc - K1) + s_aq * 16);
            float v[16];
#pragma unroll
            for (int j = 0; j < 4; j++) {
                float4 t4 = *(const float4*)(src + j * 4);
                v[j*4+0] = t4.x; v[j*4+1] = t4.y; v[j*4+2] = t4.z; v[j*4+3] = t4.w;
            }
            if (a1_gelu) {
#pragma unroll
                for (int j = 0; j < 16; j++) v[j] = gelu_f(v[j]);
            }
            unsigned u0[8], u1[8], u2[8];
#pragma unroll
            for (int j = 0; j < 8; j++) {
                float x = v[2*j], y = v[2*j+1];
                __nv_bfloat16 bx0 = __float2bfloat16_rn(x);
                __nv_bfloat16 by0 = __float2bfloat16_rn(y);
                float rx = x - __bfloat162float(bx0);
                float ry = y - __bfloat162float(by0);
                __nv_bfloat16 bx1 = __float2bfloat16_rn(rx);
                __nv_bfloat16 by1 = __float2bfloat16_rn(ry);
                float rx2 = rx - __bfloat162float(bx1);
                float ry2 = ry - __bfloat162float(by1);
                __nv_bfloat16 bx2 = __float2bfloat16_rn(rx2);
                __nv_bfloat16 by2 = __float2bfloat16_rn(ry2);
                u0[j] = ((unsigned)*(unsigned short*)&by0 << 16) | *(unsigned short*)&bx0;
                u1[j] = ((unsigned)*(unsigned short*)&by1 << 16) | *(unsigned short*)&bx1;
                u2[j] = ((unsigned)*(unsigned short*)&by2 << 16) | *(unsigned short*)&bx2;
            }
            unsigned rsw = (unsigned)((s_arow & 7) << 4);
            unsigned rb = (unsigned)s_arow * 128;
#pragma unroll
            for (int j8 = 0; j8 < 4; j8++) {
                unsigned kb = (unsigned)(s_aq * 32 + j8 * 8) ^ rsw;
                *(uint2*)(smem + AB_OFF + rb + kb) = make_uint2(u0[2*j8], u0[2*j8+1]);
                *(uint2*)(smem + AB_OFF + A_TERM + rb + kb) = make_uint2(u1[2*j8], u1[2*j8+1]);
                if (nsplit == 3)
                    *(uint2*)(smem + AB_OFF + 2*A_TERM + rb + kb) = make_uint2(u2[2*j8], u2[2*j8+1]);
            }
        }
        {
            unsigned nsw = (unsigned)((s_bn & 7) << 4);
            unsigned nb = (unsigned)s_bn * 128;
            long long goff = (bro + kc) * 2;
#pragma unroll
            for (int w = 0; w < 3; w++) {
                if (w >= nsplit) break;
                const char* Wsrc = (const char*)((w == 0) ? W0 : ((w == 1) ? W1 : W2s));
#pragma unroll
                for (int i = 0; i < 4; i++) {
                    unsigned kb = (unsigned)(s_bh * 64 + i * 16);
                    CPASYNC16(sbase + BB_OFF + w * B_TERM + nb + (kb ^ nsw), Wsrc + goff + kb);
                }
            }
        }
        CPCOMMIT();
        CPWAIT0();
        __syncthreads();

        for (int p = 0; p < nterms; p++) {
            unsigned Ab = sbase + AB_OFF + ta6[p] * A_TERM;
            unsigned Bb = sbase + BB_OFF + tb6[p] * B_TERM;
#pragma unroll
            for (int ks = 0; ks < 4; ks++) {
                unsigned a0[4], a1r[4];
                unsigned akb = ((unsigned)(ks * 32) + a_kb0) ^ a_sw;
                ldsm4(a0[0], a0[1], a0[2], a0[3], Ab + (unsigned)a_r * 128 + akb);
                ldsm4(a1r[0], a1r[1], a1r[2], a1r[3], Ab + (unsigned)(a_r + 16) * 128 + akb);
#pragma unroll
                for (int np = 0; np < 4; np++) {
                    int n = wn * 64 + np * 16 + ((b_g >> 1) << 3) + b_r;
                    unsigned bkb = ((unsigned)(ks * 32) + b_kb0) ^ (unsigned)((n & 7) << 4);
                    unsigned b0, b1, b2, b3;
                    ldsm4(b0, b1, b2, b3, Bb + (unsigned)n * 128 + bkb);
                    mma_bf16(acc[0][2*np],   a0[0], a0[1], a0[2], a0[3], b0, b1);
                    mma_bf16(acc[0][2*np+1], a0[0], a0[1], a0[2], a0[3], b2, b3);
                    mma_bf16(acc[1][2*np],   a1r[0], a1r[1], a1r[2], a1r[3], b0, b1);
                    mma_bf16(acc[1][2*np+1], a1r[0], a1r[1], a1r[2], a1r[3], b2, b3);
                }
            }
        }
        __syncthreads();
    }

    int qd = lane & 3;
    int rql = lane >> 2;
    float bv[16];
#pragma unroll
    for (int nt = 0; nt < 8; nt++) {
        int cg = colbase + wn * 64 + nt * 8 + 2 * qd;
        float2 t2 = *(const float2*)(bias + cg);
        bv[2*nt] = t2.x; bv[2*nt+1] = t2.y;
    }

    if (mode == 0) {
#pragma unroll
        for (int mt = 0; mt < 2; mt++)
#pragma unroll
            for (int hf = 0; hf < 2; hf++) {
                int m = r0 + wm * 32 + mt * 16 + rql + hf * 8;
                float sc = rowscale ? rowscale[m] : 1.0f;
#pragma unroll
                for (int nt = 0; nt < 8; nt++) {
                    int cg = colbase + wn * 64 + nt * 8 + 2 * qd;
                    float2 o;
                    o.x = (acc[mt][nt][2*hf]   + bv[2*nt])   * sc;
                    o.y = (acc[mt][nt][2*hf+1] + bv[2*nt+1]) * sc;
                    *(float2*)(C + (long long)m * ldc + cg) = o;
                }
            }
        return;
    }

    // mode 2: layernorm (+ optional bf16 plane outputs)
    float* red = (float*)smem;
    float* red2 = red + 512;
#pragma unroll
    for (int mt = 0; mt < 2; mt++)
#pragma unroll
        for (int hf = 0; hf < 2; hf++) {
            float s = 0.0f, sq = 0.0f;
#pragma unroll
            for (int nt = 0; nt < 8; nt++) {
                float f0 = acc[mt][nt][2*hf]   + bv[2*nt];
                float f1 = acc[mt][nt][2*hf+1] + bv[2*nt+1];
                s += f0 + f1; sq += f0 * f0 + f1 * f1;
            }
            s  += __shfl_xor_sync(0xffffffffu, s, 1);
            s  += __shfl_xor_sync(0xffffffffu, s, 2);
            sq += __shfl_xor_sync(0xffffffffu, sq, 1);
            sq += __shfl_xor_sync(0xffffffffu, sq, 2);
            if (qd == 0) {
                int rl = wm * 32 + mt * 16 + rql + hf * 8;
                red[rl * 4 + wn] = s;
                red2[rl * 4 + wn] = sq;
            }
        }
    __syncthreads();
    float* stats = red2 + 512;
    if (tid < 128) {
        float s = red[tid*4] + red[tid*4+1] + red[tid*4+2] + red[tid*4+3];
        float sq = red2[tid*4] + red2[tid*4+1] + red2[tid*4+2] + red2[tid*4+3];
        float mu = s * (1.0f / 256.0f);
        float var = sq * (1.0f / 256.0f) - mu * mu;
        stats[tid*2] = mu;
        stats[tid*2+1] = rsqrtf(var + 1e-5f);
    }
    __syncthreads();
    float gv[16], ev[16];
#pragma unroll
    for (int nt = 0; nt < 8; nt++) {
        int cg = wn * 64 + nt * 8 + 2 * qd;
        float2 tg = *(const float2*)(lng + cg);
        float2 te = *(const float2*)(lnb + cg);
        gv[2*nt] = tg.x; gv[2*nt+1] = tg.y;
        ev[2*nt] = te.x; ev[2*nt+1] = te.y;
    }
#pragma unroll
    for (int mt = 0; mt < 2; mt++)
#pragma unroll
        for (int hf = 0; hf < 2; hf++) {
            int rl = wm * 32 + mt * 16 + rql + hf * 8;
            int m = r0 + rl;
            float mu = stats[rl*2], inv = stats[rl*2+1];
#pragma unroll
            for (int nt = 0; nt < 8; nt++) {
                int cg = wn * 64 + nt * 8 + 2 * qd;
                float2 o;
                float f0 = acc[mt][nt][2*hf]   + bv[2*nt];
                float f1 = acc[mt][nt][2*hf+1] + bv[2*nt+1];
                o.x = (f0 - mu) * inv * gv[2*nt]   + ev[2*nt];
                o.y = (f1 - mu) * inv * gv[2*nt+1] + ev[2*nt+1];
                *(float2*)(C + (long long)m * ldc + cg) = o;
                if (n0p) {
                    long long e = (long long)m * 256 + cg;
                    __nv_bfloat16 x0 = __float2bfloat16_rn(o.x);
                    float rx = o.x - __bfloat162float(x0);
                    __nv_bfloat16 x1 = __float2bfloat16_rn(rx);
                    __nv_bfloat16 x2 = __float2bfloat16_rn(rx - __bfloat162float(x1));
                    __nv_bfloat16 y0 = __float2bfloat16_rn(o.y);
                    float ry = o.y - __bfloat162float(y0);
                    __nv_bfloat16 y1 = __float2bfloat16_rn(ry);
                    __nv_bfloat16 y2 = __float2bfloat16_rn(ry - __bfloat162float(y1));
                    *(unsigned*)(n0p + e) = ((unsigned)*(unsigned short*)&y0 << 16) | *(unsigned short*)&x0;
                    *(unsigned*)(n1p + e) = ((unsigned)*(unsigned short*)&y1 << 16) | *(unsigned short*)&x1;
                    *(unsigned*)(n2p + e) = ((unsigned)*(unsigned short*)&y2 << 16) | *(unsigned short*)&x2;
                }
            }
        }
}

// ------------------------- scalar GEMM (sparse scatter-accum) --------
__global__ __launch_bounds__(TTH, 1)
void gemm2(const float* __restrict__ A1,
           const float* __restrict__ Wt, int ldw,
           float* __restrict__ C, const int* __restrict__ cgather, int ldc,
           int Ktot) {
    extern __shared__ float sm[];
    float* As = sm;
    float* Ws = sm + 2 * TBK * 132;

    int tid = threadIdx.x;
    int r0 = blockIdx.x * TBM;

    int am = tid >> 2;
    int ak = (tid & 3) << 2;
    int m_a = r0 + am;
    const float* a1row = A1 + (long long)m_a * Ktot;

    int wr = tid >> 5;
    int wc = (tid & 31) << 3;
    const float* wbase = Wt + (long long)wr * ldw + wc;

    float4 av, wv0, wv1;
#define LOAD_ST(kb) do {                                                      \
        av = *(const float4*)(a1row + (kb) + ak);                             \
        const float* wp_ = wbase + (long long)(kb) * ldw;                     \
        wv0 = *(const float4*)(wp_);                                          \
        wv1 = *(const float4*)(wp_ + 4);                                      \
    } while (0)
#define STORE_ST(buf) do {                                                    \
        float* ap_ = As + (buf) * (TBK * 132);                                \
        ap_[(ak + 0) * 132 + am] = av.x;                                      \
        ap_[(ak + 1) * 132 + am] = av.y;                                      \
        ap_[(ak + 2) * 132 + am] = av.z;                                      \
        ap_[(ak + 3) * 132 + am] = av.w;                                      \
        float* wpS_ = Ws + (buf) * (TBK * 256) + wr * 256 + wc;               \
        *(float4*)wpS_ = wv0;                                                 \
        *(float4*)(wpS_ + 4) = wv1;                                           \
    } while (0)

    int lane = tid & 31, warp = tid >> 5;
    int row0 = warp << 3, col0 = lane << 3;

    float acc[8][8];
#pragma unroll
    for (int r = 0; r < 8; r++)
#pragma unroll
        for (int c = 0; c < 8; c++) acc[r][c] = 0.0f;

    LOAD_ST(0); STORE_ST(0);
    __syncthreads();

    int S = Ktot / TBK;
    for (int s = 0; s < S; s++) {
        int cur = s & 1;
        if (s + 1 < S) LOAD_ST((s + 1) * TBK);
        const float* ab = As + cur * (TBK * 132);
        const float* wb = Ws + cur * (TBK * 256);
#pragma unroll
        for (int k = 0; k < TBK; k++) {
            float4 a0 = *(const float4*)(ab + k * 132 + row0);
            float4 a1v = *(const float4*)(ab + k * 132 + row0 + 4);
            float4 b0 = *(const float4*)(wb + k * 256 + col0);
            float4 b1 = *(const float4*)(wb + k * 256 + col0 + 4);
            float aa[8] = {a0.x, a0.y, a0.z, a0.w, a1v.x, a1v.y, a1v.z, a1v.w};
            float bvv[8] = {b0.x, b0.y, b0.z, b0.w, b1.x, b1.y, b1.z, b1.w};
#pragma unroll
            for (int r = 0; r < 8; r++)
#pragma unroll
                for (int c = 0; c < 8; c++) acc[r][c] += aa[r] * bvv[c];
        }
        if (s + 1 < S) { STORE_ST((s + 1) & 1); __syncthreads(); }
    }

#pragma unroll
    for (int r = 0; r < 8; r++) {
        int m = r0 + row0 + r;
        long long crow = (long long)((m >> 8) * NN + cgather[m]);
        float* cp = C + crow * ldc + col0;
        float4 o0 = *(float4*)cp, o1 = *(float4*)(cp + 4);
        o0.x += acc[r][0]; o0.y += acc[r][1]; o0.z += acc[r][2]; o0.w += acc[r][3];
        o1.x += acc[r][4]; o1.y += acc[r][5]; o1.z += acc[r][6]; o1.w += acc[r][7];
        *(float4*)cp = o0; *(float4*)(cp + 4) = o1;
    }
}

// ------------------------- attention -------------------------
__global__ void attn_kernel(const float* __restrict__ qkv, float* __restrict__ out) {
    extern __shared__ float sm[];
    float* Ks = sm;
    float* Vs = sm + MSGK * HD;
    int bh = blockIdx.x;
    int b = bh >> 2;
    int h = bh & 3;
    int tid = threadIdx.x;
    const float* base = qkv + (long long)b * MSGK * 768;

    for (int t = tid; t < MSGK * HD; t += 256) {
        int j = t >> 6;
        int d = t & 63;
        Ks[t] = base[j * 768 + 256 + h * 64 + d];
        Vs[t] = base[j * 768 + 512 + h * 64 + d];
    }
    __syncthreads();

    float q[HD], o[HD];
#pragma unroll
    for (int d = 0; d < HD; d++) { q[d] = base[tid * 768 + h * 64 + d] * 0.125f; o[d] = 0.0f; }

    float mval = -1e30f, l = 0.0f;
    for (int j = 0; j < MSGK; j++) {
        float s = 0.0f;
#pragma unroll
        for (int d = 0; d < HD; d++) s += q[d] * Ks[j * 64 + d];
        float nm = fmaxf(mval, s);
        float corr = expf(mval - nm);
        float p = expf(s - nm);
        l = l * corr + p;
#pragma unroll
        for (int d = 0; d < HD; d++) o[d] = o[d] * corr + p * Vs[j * 64 + d];
        mval = nm;
    }
    float inv = 1.0f / l;
    float* op = out + ((long long)(b * MSGK + tid)) * DD + h * 64;
#pragma unroll
    for (int d = 0; d < HD; d++) op[d] = o[d] * inv;
}

// ------------------------- finalize -------------------------
__global__ void finalize_kernel(const float* __restrict__ newact, const float* __restrict__ newhid,
                                const int* __restrict__ slot2, float* __restrict__ out) {
    long long total_act = (long long)BB * NN;
    float* out_act = out;
    float* out_hid = out + total_act;
    long long stride = (long long)gridDim.x * blockDim.x;
    long long t0 = (long long)blockIdx.x * blockDim.x + threadIdx.x;

    for (long long i = t0; i < total_act; i += stride)
        out_act[i] = (slot2[i] >= 0) ? newact[i] : 0.0f;

    long long totalh4 = (long long)BB * NN * DD / 4;
    float4* oh4 = reinterpret_cast<float4*>(out_hid);
    const float4* nh4 = reinterpret_cast<const float4*>(newhid);
    for (long long e = t0; e < totalh4; e += stride) {
        long long r = e >> 6;
        oh4[e] = (slot2[r] >= 0) ? nh4[e] : make_float4(0.f, 0.f, 0.f, 0.f);
    }
}

// ------------------------- host launcher -------------------------
extern "C" void kernel_launch(void* const* d_in, const int* in_sizes, int n_in,
                              void* d_out, int out_size) {
    const float* act    = (const float*)d_in[0];
    const float* hidden = (const float*)d_in[1];
    const float* in_w   = (const float*)d_in[2];
    const float* in_b   = (const float*)d_in[3];
    const float* out_w  = (const float*)d_in[4];
    const float* out_b  = (const float*)d_in[5];
    const float* su_w1  = (const float*)d_in[6];
    const float* su_b1  = (const float*)d_in[7];
    const float* su_w2  = (const float*)d_in[8];
    const float* su_b2  = (const float*)d_in[9];
    const float* au_w1  = (const float*)d_in[10];
    const float* au_b1  = (const float*)d_in[11];
    const float* au_w2  = (const float*)d_in[12];
    const float* au_b2  = (const float*)d_in[13];
    const float* ln_g   = (const float*)d_in[14];
    const float* ln_b   = (const float*)d_in[15];
    const int*   kptr   = (const int*)d_in[16];

    int*   p_tidx;   cudaGetSymbolAddress((void**)&p_tidx,   g_tidx);
    float* p_tval;   cudaGetSymbolAddress((void**)&p_tval,   g_tval);
    int*   p_slot;   cudaGetSymbolAddress((void**)&p_slot,   g_slot);
    int*   p_slot2;  cudaGetSymbolAddress((void**)&p_slot2,  g_slot2);
    float* p_qkv;    cudaGetSymbolAddress((void**)&p_qkv,    g_qkv);
    float* p_attn;   cudaGetSymbolAddress((void**)&p_attn,   g_attn);
    float* p_msg;    cudaGetSymbolAddress((void**)&p_msg,    g_msg);
    float* p_h;      cudaGetSymbolAddress((void**)&p_h,      g_h);
    float* p_newhid; cudaGetSymbolAddress((void**)&p_newhid, g_newhid);
    float* p_newact; cudaGetSymbolAddress((void**)&p_newact, g_newact);
    float* wt_su1;   cudaGetSymbolAddress((void**)&wt_su1,   g_wt_su1);

    __nv_bfloat16 *in0,*in1,*in2, *ow0,*ow1,*ow2, *s10,*s11,*s12, *s20,*s21,*s22, *a10,*a11,*a12;
    __nv_bfloat16 *h0,*h1,*h2, *n0,*n1,*n2;
    cudaGetSymbolAddress((void**)&in0, g_in0); cudaGetSymbolAddress((void**)&in1, g_in1);
    cudaGetSymbolAddress((void**)&in2, g_in2);
    cudaGetSymbolAddress((void**)&ow0, g_ow0); cudaGetSymbolAddress((void**)&ow1, g_ow1);
    cudaGetSymbolAddress((void**)&ow2, g_ow2);
    cudaGetSymbolAddress((void**)&s10, g_s10); cudaGetSymbolAddress((void**)&s11, g_s11);
    cudaGetSymbolAddress((void**)&s12, g_s12);
    cudaGetSymbolAddress((void**)&s20, g_s20); cudaGetSymbolAddress((void**)&s21, g_s21);
    cudaGetSymbolAddress((void**)&s22, g_s22);
    cudaGetSymbolAddress((void**)&a10, g_a10); cudaGetSymbolAddress((void**)&a11, g_a11);
    cudaGetSymbolAddress((void**)&a12, g_a12);
    cudaGetSymbolAddress((void**)&h0, g_h0); cudaGetSymbolAddress((void**)&h1, g_h1);
    cudaGetSymbolAddress((void**)&h2, g_h2);
    cudaGetSymbolAddress((void**)&n0, g_n0); cudaGetSymbolAddress((void**)&n1, g_n1);
    cudaGetSymbolAddress((void**)&n2, g_n2);

    const int SMEM_GEMM2 = (2 * TBK * 132 + 2 * TBK * 256) * 4;
    const int SMEM_ATTN  = 2 * MSGK * HD * 4;

    cudaFuncSetAttribute(mma_gemm, cudaFuncAttributeMaxDynamicSharedMemorySize, TC_SMEM);
    cudaFuncSetAttribute(mma_gemm_ps, cudaFuncAttributeMaxDynamicSharedMemorySize, PS_SMEM);
    cudaFuncSetAttribute(gemm2, cudaFuncAttributeMaxDynamicSharedMemorySize, SMEM_GEMM2);
    cudaFuncSetAttribute(attn_kernel, cudaFuncAttributeMaxDynamicSharedMemorySize, SMEM_ATTN);

    // 0) weight + activation prep
    split3_kernel<<<768, 256>>>(in_w,  in0, in1, in2, 768 * 256);
    split3_kernel<<<256, 256>>>(out_w, ow0, ow1, ow2, 256 * 256);
    split3_kernel<<<512, 256>>>(su_w1, s10, s11, s12, 256 * 512);
    split3_kernel<<<256, 256>>>(su_w2, s20, s21, s22, 256 * 256);
    split3_kernel<<<512, 256>>>(au_w1, a10, a11, a12, 256 * 512);
    transpose_kernel<<<dim3(16, 8), dim3(32, 8)>>>(su_w1, wt_su1, 256, 512);
    split3_kernel<<<BB * NN * DD / 256, 256>>>(hidden, h0, h1, h2, BB * NN * DD);

    // 1) top-k of activation
    sort_topk_kernel<<<BB, 1024>>>(act, nullptr, MSGK, p_tidx, p_tval, p_slot);

    // 2) QKV: gathered rows from hidden planes, 3-term, pipelined
    mma_gemm_ps<<<dim3(64, 3), 512, PS_SMEM>>>(
        h0, h1, h2, nullptr, nullptr, nullptr, p_tidx,
        in0, in1, in2, 256, in_b,
        nullptr, nullptr, nullptr, nullptr,
        p_qkv, 768, 256, 256, 256, 256, 3, 0);

    // 3) attention
    attn_kernel<<<BB * 4, 256, SMEM_ATTN>>>(p_qkv, p_attn);

    // 4) out-proj * topk_val -> msg   (convert path, 3-term)
    mma_gemm<<<dim3(64, 1), 512, TC_SMEM>>>(
        p_attn, nullptr, nullptr, ow0, ow1, ow2, 256, out_b,
        p_tval, nullptr, nullptr,
        p_msg, 256, nullptr, nullptr, nullptr,
        256, 256, 0, 3, 0);

    // 5a) su1 dense: pre = hidden @ W1a^T + b1   (6-term, pipelined)
    mma_gemm_ps<<<dim3(1024, 1), 512, PS_SMEM>>>(
        h0, h1, h2, nullptr, nullptr, nullptr, nullptr,
        s10, s11, s12, 512, su_b1,
        nullptr, nullptr, nullptr, nullptr,
        p_h, 256, 256, 256, 256, 256, 6, 0);

    // 5b) su1 sparse: pre[active] += msg @ W1b^T  (scalar fp32, exact)
    gemm2<<<dim3(64, 1), TTH, SMEM_GEMM2>>>(
        p_msg, wt_su1 + 256 * 256, 256, p_h, p_tidx, 256, 256);

    // 6) su2: newhid = LN( gelu(pre) @ W2^T + b2 ); also emit newhid bf16 planes
    mma_gemm<<<dim3(1024, 1), 512, TC_SMEM>>>(
        p_h, nullptr, nullptr, s20, s21, s22, 256, su_b2,
        nullptr, ln_g, ln_b,
        p_newhid, 256, n0, n1, n2,
        256, 256, 1, 6, 2);

    // 7) au1 fused act update (6-term, pipelined, A = [hidden|newhid] planes)
    mma_gemm_ps<<<dim3(1024, 1), 512, PS_SMEM>>>(
        h0, h1, h2, n0, n1, n2, nullptr,
        a10, a11, a12, 512, au_b1,
        au_w2, au_b2, act, p_newact,
        nullptr, 256, 256, 256, 256, 512, 6, 3);

    // 8) final top-k (k from device sparsity_k)
    sort_topk_kernel<<<BB, 1024>>>(p_newact, kptr, 0, nullptr, nullptr, p_slot2);

    // 9) masked write [sparse_act | sparse_hidden]
    finalize_kernel<<<2048, 256>>>(p_newact, p_newhid, p_slot2, (float*)d_out);
}

// round 11
// speedup vs baseline: 8.1592x; 1.2881x over previous
#include <cuda_runtime.h>
#include <cuda_fp16.h>
#include <math.h>

#define BB 32
#define NN 4096
#define DD 256
#define MSGK 256
#define HD 64

// scalar gemm (sparse scatter-accum only)
#define TBM 128
#define TBK 16
#define TTH 512

// ------------------------- device scratch -------------------------
__device__ int   g_tidx[BB * MSGK];
__device__ float g_tval[BB * MSGK];
__device__ int   g_slot[BB * NN];
__device__ int   g_slot2[BB * NN];
__device__ float g_qkv[BB * MSGK * 3 * DD];
__device__ float g_attn[BB * MSGK * DD];
__device__ float g_msg[BB * MSGK * DD];
__device__ float g_h[(size_t)BB * NN * DD];
__device__ float g_newhid[(size_t)BB * NN * DD];
__device__ float g_newact[BB * NN];
__device__ float g_wt_su1[512 * 256];

// fp16 2-way splits of weights
__device__ __half g_in0[768*256],  g_in1[768*256];
__device__ __half g_ow0[256*256],  g_ow1[256*256];
__device__ __half g_s10[256*512],  g_s11[256*512];
__device__ __half g_s20[256*256],  g_s21[256*256];
__device__ __half g_a10[256*512],  g_a11[256*512];

// fp16 2-way splits of activations
__device__ __half g_h0[(size_t)BB*NN*DD], g_h1[(size_t)BB*NN*DD];
__device__ __half g_n0[(size_t)BB*NN*DD], g_n1[(size_t)BB*NN*DD];

__device__ __forceinline__ float gelu_f(float x) {
    return 0.5f * x * (1.0f + erff(x * 0.70710678118654752440f));
}

__device__ __forceinline__ unsigned smem_u32(const void* p) {
    unsigned a;
    asm("{ .reg .u64 t; cvta.to.shared.u64 t, %1; cvt.u32.u64 %0, t; }" : "=r"(a) : "l"(p));
    return a;
}

__device__ __forceinline__ void ldsm4(unsigned& r0, unsigned& r1, unsigned& r2, unsigned& r3,
                                      unsigned addr) {
    asm volatile("ldmatrix.sync.aligned.m8n8.x4.shared.b16 {%0,%1,%2,%3}, [%4];"
                 : "=r"(r0), "=r"(r1), "=r"(r2), "=r"(r3) : "r"(addr));
}

__device__ __forceinline__ void mma_f16(float* c, unsigned a0, unsigned a1, unsigned a2,
                                        unsigned a3, unsigned b0, unsigned b1) {
    asm volatile("mma.sync.aligned.m16n8k16.row.col.f32.f16.f16.f32 "
                 "{%0,%1,%2,%3},{%4,%5,%6,%7},{%8,%9},{%0,%1,%2,%3};"
                 : "+f"(c[0]), "+f"(c[1]), "+f"(c[2]), "+f"(c[3])
                 : "r"(a0), "r"(a1), "r"(a2), "r"(a3), "r"(b0), "r"(b1));
}

#define CPASYNC16(dst, src) \
    asm volatile("cp.async.cg.shared.global [%0], [%1], 16;" :: "r"(dst), "l"(src) : "memory")
#define CPCOMMIT() asm volatile("cp.async.commit_group;" ::: "memory")
#define CPWAIT0() asm volatile("cp.async.wait_group 0;" ::: "memory")
#define CPWAIT1() asm volatile("cp.async.wait_group 1;" ::: "memory")

__device__ __forceinline__ unsigned short hbits(__half h) {
    return *(unsigned short*)&h;
}

// ------------------------- weight split (fp16 2-way) -------------------------
__global__ void split2_kernel(const float* __restrict__ W, __half* o0, __half* o1, int n) {
    int i = blockIdx.x * 256 + threadIdx.x;
    if (i < n) {
        float v = W[i];
        __half a = __float2half_rn(v);
        float r = v - __half2float(a);
        o0[i] = a; o1[i] = __float2half_rn(r);
    }
}

// ------------------------- weight transpose (scalar scatter gemm) ------------
__global__ void transpose_kernel(const float* __restrict__ W, float* __restrict__ Wt,
                                 int Nout, int Kd) {
    __shared__ float t[32][33];
    int k0 = blockIdx.x * 32, n0 = blockIdx.y * 32;
    int tx = threadIdx.x, ty = threadIdx.y;
#pragma unroll
    for (int i = 0; i < 32; i += 8)
        t[ty + i][tx] = W[(long long)(n0 + ty + i) * Kd + k0 + tx];
    __syncthreads();
#pragma unroll
    for (int i = 0; i < 32; i += 8)
        Wt[(long long)(k0 + ty + i) * Nout + n0 + tx] = t[tx][ty + i];
}

// ------------------------- top-k via bitonic sort -------------------------
__global__ void sort_topk_kernel(const float* __restrict__ act,
                                 const int* __restrict__ kptr, int kconst,
                                 int* __restrict__ idx_out, float* __restrict__ val_out,
                                 int* __restrict__ slotmap) {
    __shared__ float sv[NN];
    __shared__ int   si[NN];
    int b = blockIdx.x;
    int tid = threadIdx.x;
    int kk = kptr ? *kptr : kconst;
    if (kk > NN) kk = NN;
    if (kk < 0) kk = 0;

    for (int i = tid; i < NN; i += blockDim.x) { sv[i] = act[b * NN + i]; si[i] = i; }
    __syncthreads();

    for (int ksz = 2; ksz <= NN; ksz <<= 1) {
        for (int j = ksz >> 1; j > 0; j >>= 1) {
            for (int i = tid; i < NN; i += blockDim.x) {
                int ixj = i ^ j;
                if (ixj > i) {
                    bool dirDesc = ((i & ksz) == 0);
                    float vi = sv[i], vx = sv[ixj];
                    bool sw = dirDesc ? (vi < vx) : (vi > vx);
                    if (sw) {
                        sv[i] = vx; sv[ixj] = vi;
                        int t = si[i]; si[i] = si[ixj]; si[ixj] = t;
                    }
                }
            }
            __syncthreads();
        }
    }

    for (int i = tid; i < NN; i += blockDim.x) slotmap[b * NN + i] = -1;
    __syncthreads();
    for (int j = tid; j < kk; j += blockDim.x) {
        slotmap[b * NN + si[j]] = j;
        if (idx_out) { idx_out[b * kk + j] = si[j]; val_out[b * kk + j] = sv[j]; }
    }
}

// ======================= pre-split pipelined tensor GEMM (fp16, 3-term) =======
// A as fp16 planes (2-way split). k<K1 from A planes (optional gather), k>=K1
// from Z planes. cp.async double-buffered, KC=32. CTA 128x256, 512 threads.
// mode 0: bias store. mode 3: bias + gelu + dot(w2) + sigmoid blend -> act_out.
#define PS_AP 8192
#define PS_BOFF 16384
#define PS_BP 16384
#define PS_STAGE 49152
#define PS_SMEM (2 * PS_STAGE)   // 98304

__global__ __launch_bounds__(512, 1)
void mma_gemm_ps(const __half* __restrict__ A0, const __half* __restrict__ A1p,
                 const __half* __restrict__ Z0, const __half* __restrict__ Z1,
                 const int* __restrict__ gather,
                 const __half* __restrict__ W0, const __half* __restrict__ W1, int ldw,
                 const float* __restrict__ bias,
                 const float* __restrict__ w2, const float* __restrict__ b2,
                 const float* __restrict__ act_in, float* __restrict__ act_out,
                 float* __restrict__ C, int ldc,
                 int K1, int lda1, int lda2, int Ktot, int mode) {
    extern __shared__ char smem[];
    unsigned sbase = smem_u32(smem);
    int tid = threadIdx.x;
    int lane = tid & 31;
    int wid = tid >> 5;
    int wm = wid & 3;
    int wn = wid >> 2;
    int r0 = blockIdx.x * 128;
    int colbase = blockIdx.y * 256;

    // ---- staging maps ----
    int arow = tid >> 2, au = tid & 3;
    int m_a = r0 + arow;
    long long ridx1 = gather ? (long long)((m_a >> 8) * NN + gather[m_a]) : m_a;
    const char* a1b0 = (const char*)(A0 + ridx1 * lda1);
    const char* a1b1 = (const char*)(A1p + ridx1 * lda1);
    const char* a2b0 = Z0 ? (const char*)(Z0 + (long long)m_a * lda2) : a1b0;
    const char* a2b1 = Z1 ? (const char*)(Z1 + (long long)m_a * lda2) : a1b1;
    unsigned aswz = ((arow >> 1) & 3) << 4;
    unsigned adst0 = (unsigned)arow * 64 + ((au * 16) ^ aswz);

    int bn = tid >> 1;
    int bu0 = (tid & 1) * 2;
    unsigned bswz = ((bn >> 1) & 3) << 4;
    long long brow = (long long)(colbase + bn) * ldw;

    const int ta3[3] = {0, 0, 1};
    const int tb3[3] = {0, 1, 0};

    // ---- mma fragment addressing ----
    int a_r = wm * 32 + (lane & 15);
    unsigned a_k0 = (unsigned)((lane >> 4) << 4);
    unsigned a_sw = ((a_r >> 1) & 3) << 4;
    int b_g = lane >> 3, b_r = lane & 7;
    int b_n0 = wn * 64 + ((b_g >> 1) << 3) + b_r;
    unsigned b_k0 = (unsigned)((b_g & 1) << 4);

    float acc[2][8][4];
#pragma unroll
    for (int mt = 0; mt < 2; mt++)
#pragma unroll
        for (int nt = 0; nt < 8; nt++)
#pragma unroll
            for (int c = 0; c < 4; c++) acc[mt][nt][c] = 0.0f;

    int nc = Ktot >> 5;

#define PS_STAGE_FN(c_) do {                                                   \
        int buf_ = (c_) & 1;                                                   \
        unsigned stg_ = sbase + buf_ * PS_STAGE;                               \
        int kc_ = (c_) << 5;                                                   \
        const char *p0_, *p1_; long long ko_;                                  \
        if (kc_ < K1) { p0_ = a1b0; p1_ = a1b1; ko_ = kc_; }                   \
        else          { p0_ = a2b0; p1_ = a2b1; ko_ = kc_ - K1; }              \
        long long ab_ = ko_ * 2 + au * 16;                                     \
        unsigned ad_ = stg_ + adst0;                                           \
        CPASYNC16(ad_, p0_ + ab_);                                             \
        CPASYNC16(ad_ + PS_AP, p1_ + ab_);                                     \
        long long bo_ = (brow + kc_) * 2;                                      \
        unsigned bd_ = stg_ + PS_BOFF + (unsigned)bn * 64;                     \
        unsigned k0_ = (unsigned)(bu0 * 16), k1_ = k0_ + 16;                   \
        CPASYNC16(bd_ + (k0_ ^ bswz), (const char*)W0 + bo_ + k0_);            \
        CPASYNC16(bd_ + (k1_ ^ bswz), (const char*)W0 + bo_ + k1_);            \
        CPASYNC16(bd_ + PS_BP + (k0_ ^ bswz), (const char*)W1 + bo_ + k0_);    \
        CPASYNC16(bd_ + PS_BP + (k1_ ^ bswz), (const char*)W1 + bo_ + k1_);    \
    } while (0)

    PS_STAGE_FN(0);
    CPCOMMIT();

    for (int c = 0; c < nc; c++) {
        if (c + 1 < nc) { PS_STAGE_FN(c + 1); CPCOMMIT(); CPWAIT1(); }
        else            { CPWAIT0(); }
        __syncthreads();

        unsigned stg = sbase + (c & 1) * PS_STAGE;
#pragma unroll
        for (int p = 0; p < 3; p++) {
            unsigned Ab = stg + ta3[p] * PS_AP;
            unsigned Bb = stg + PS_BOFF + tb3[p] * PS_BP;
#pragma unroll
            for (int ks = 0; ks < 2; ks++) {
                unsigned akb = ((unsigned)(ks << 5) + a_k0) ^ a_sw;
                unsigned a0[4], a1r[4];
                ldsm4(a0[0], a0[1], a0[2], a0[3], Ab + (unsigned)a_r * 64 + akb);
                ldsm4(a1r[0], a1r[1], a1r[2], a1r[3], Ab + (unsigned)(a_r + 16) * 64 + akb);
#pragma unroll
                for (int np = 0; np < 4; np++) {
                    int n = b_n0 + np * 16;
                    unsigned bkb = ((unsigned)(ks << 5) + b_k0) ^ (unsigned)(((n >> 1) & 3) << 4);
                    unsigned b0, b1, b2, b3;
                    ldsm4(b0, b1, b2, b3, Bb + (unsigned)n * 64 + bkb);
                    mma_f16(acc[0][2*np],   a0[0], a0[1], a0[2], a0[3], b0, b1);
                    mma_f16(acc[0][2*np+1], a0[0], a0[1], a0[2], a0[3], b2, b3);
                    mma_f16(acc[1][2*np],   a1r[0], a1r[1], a1r[2], a1r[3], b0, b1);
                    mma_f16(acc[1][2*np+1], a1r[0], a1r[1], a1r[2], a1r[3], b2, b3);
                }
            }
        }
        __syncthreads();
    }

    // ---------------- epilogue ----------------
    int qd = lane & 3;
    int rql = lane >> 2;
    float bv[16];
#pragma unroll
    for (int nt = 0; nt < 8; nt++) {
        int cg = colbase + wn * 64 + nt * 8 + 2 * qd;
        float2 t2 = *(const float2*)(bias + cg);
        bv[2*nt] = t2.x; bv[2*nt+1] = t2.y;
    }

    if (mode == 0) {
#pragma unroll
        for (int mt = 0; mt < 2; mt++)
#pragma unroll
            for (int hf = 0; hf < 2; hf++) {
                int m = r0 + wm * 32 + mt * 16 + rql + hf * 8;
#pragma unroll
                for (int nt = 0; nt < 8; nt++) {
                    int cg = colbase + wn * 64 + nt * 8 + 2 * qd;
                    float2 o;
                    o.x = acc[mt][nt][2*hf]   + bv[2*nt];
                    o.y = acc[mt][nt][2*hf+1] + bv[2*nt+1];
                    *(float2*)(C + (long long)m * ldc + cg) = o;
                }
            }
        return;
    }

    // mode 3: gelu + dot(w2) + sigmoid blend
    {
        float* red = (float*)smem;
        float wv[16];
#pragma unroll
        for (int nt = 0; nt < 8; nt++) {
            int cg = wn * 64 + nt * 8 + 2 * qd;
            float2 tw = *(const float2*)(w2 + cg);
            wv[2*nt] = tw.x; wv[2*nt+1] = tw.y;
        }
#pragma unroll
        for (int mt = 0; mt < 2; mt++)
#pragma unroll
            for (int hf = 0; hf < 2; hf++) {
                float d = 0.0f;
#pragma unroll
                for (int nt = 0; nt < 8; nt++) {
                    float f0 = gelu_f(acc[mt][nt][2*hf]   + bv[2*nt]);
                    float f1 = gelu_f(acc[mt][nt][2*hf+1] + bv[2*nt+1]);
                    d += f0 * wv[2*nt] + f1 * wv[2*nt+1];
                }
                d += __shfl_xor_sync(0xffffffffu, d, 1);
                d += __shfl_xor_sync(0xffffffffu, d, 2);
                if (qd == 0) {
                    int rl = wm * 32 + mt * 16 + rql + hf * 8;
                    red[rl * 4 + wn] = d;
                }
            }
        __syncthreads();
        if (tid < 128) {
            float d = red[tid*4] + red[tid*4+1] + red[tid*4+2] + red[tid*4+3];
            float dl = 1.0f / (1.0f + expf(-(d + b2[0])));
            int m = r0 + tid;
            float na = 0.7f * act_in[m] + 0.3f * dl;
            na = fminf(fmaxf(na, 0.0f), 1.0f);
            act_out[m] = na;
        }
    }
}

// ======================= convert-path tensor GEMM (fp32 A, fp16 3-term) =======
#define A_TERM 16384
#define B_TERM 32768
#define BB_OFF (2 * A_TERM)
#define TC_SMEM (2 * A_TERM + 2 * B_TERM)   // 98304

__global__ __launch_bounds__(512, 1)
void mma_gemm(const float* __restrict__ A1,
              const __half* __restrict__ W0, const __half* __restrict__ W1, int ldw,
              const float* __restrict__ bias,
              const float* __restrict__ rowscale,
              const float* __restrict__ lng, const float* __restrict__ lnb,
              float* __restrict__ C, int ldc,
              __half* __restrict__ n0p, __half* __restrict__ n1p,
              int Ktot, int a1_gelu, int mode) {
    extern __shared__ char smem[];
    unsigned sbase = smem_u32(smem);
    int tid = threadIdx.x;
    int lane = tid & 31;
    int wid = tid >> 5;
    int wm = wid & 3;
    int wn = wid >> 2;
    int r0 = blockIdx.x * 128;
    int colbase = blockIdx.y * 256;

    int s_arow = tid >> 2;
    int s_aq   = tid & 3;
    int m_a = r0 + s_arow;
    const float* a1p = A1 + (long long)m_a * Ktot;

    int s_bn = tid >> 1;
    int s_bh = tid & 1;
    long long bro = (long long)(colbase + s_bn) * ldw;

    const int ta3[3] = {0, 0, 1};
    const int tb3[3] = {0, 1, 0};

    int a_r = wm * 32 + (lane & 15);
    unsigned a_sw = (unsigned)((a_r & 7) << 4);
    unsigned a_kb0 = (unsigned)((lane >> 4) << 4);
    int b_g = lane >> 3, b_r = lane & 7;
    unsigned b_kb0 = (unsigned)((b_g & 1) << 4);

    float acc[2][8][4];
#pragma unroll
    for (int mt = 0; mt < 2; mt++)
#pragma unroll
        for (int nt = 0; nt < 8; nt++)
#pragma unroll
            for (int c = 0; c < 4; c++) acc[mt][nt][c] = 0.0f;

    int nchunks = Ktot >> 6;
    for (int ch = 0; ch < nchunks; ch++) {
        int kc = ch << 6;
        {
            const float* src = a1p + kc + s_aq * 16;
            float v[16];
#pragma unroll
            for (int j = 0; j < 4; j++) {
                float4 t4 = *(const float4*)(src + j * 4);
                v[j*4+0] = t4.x; v[j*4+1] = t4.y; v[j*4+2] = t4.z; v[j*4+3] = t4.w;
            }
            if (a1_gelu) {
#pragma unroll
                for (int j = 0; j < 16; j++) v[j] = gelu_f(v[j]);
            }
            unsigned u0[8], u1[8];
#pragma unroll
            for (int j = 0; j < 8; j++) {
                float x = v[2*j], y = v[2*j+1];
                __half hx0 = __float2half_rn(x);
                __half hy0 = __float2half_rn(y);
                __half hx1 = __float2half_rn(x - __half2float(hx0));
                __half hy1 = __float2half_rn(y - __half2float(hy0));
                u0[j] = ((unsigned)hbits(hy0) << 16) | hbits(hx0);
                u1[j] = ((unsigned)hbits(hy1) << 16) | hbits(hx1);
            }
            unsigned rsw = (unsigned)((s_arow & 7) << 4);
            unsigned rb = (unsigned)s_arow * 128;
#pragma unroll
            for (int j8 = 0; j8 < 4; j8++) {
                unsigned kb = (unsigned)(s_aq * 32 + j8 * 8) ^ rsw;
                *(uint2*)(smem + rb + kb) = make_uint2(u0[2*j8], u0[2*j8+1]);
                *(uint2*)(smem + A_TERM + rb + kb) = make_uint2(u1[2*j8], u1[2*j8+1]);
            }
        }
        {
            unsigned nsw = (unsigned)((s_bn & 7) << 4);
            unsigned nb = (unsigned)s_bn * 128;
            long long goff = (bro + kc) * 2;
#pragma unroll
            for (int w = 0; w < 2; w++) {
                const char* Wsrc = (const char*)((w == 0) ? W0 : W1);
#pragma unroll
                for (int i = 0; i < 4; i++) {
                    unsigned kb = (unsigned)(s_bh * 64 + i * 16);
                    CPASYNC16(sbase + BB_OFF + w * B_TERM + nb + (kb ^ nsw), Wsrc + goff + kb);
                }
            }
        }
        CPCOMMIT();
        CPWAIT0();
        __syncthreads();

#pragma unroll
        for (int p = 0; p < 3; p++) {
            unsigned Ab = sbase + ta3[p] * A_TERM;
            unsigned Bb = sbase + BB_OFF + tb3[p] * B_TERM;
#pragma unroll
            for (int ks = 0; ks < 4; ks++) {
                unsigned a0[4], a1r[4];
                unsigned akb = ((unsigned)(ks * 32) + a_kb0) ^ a_sw;
                ldsm4(a0[0], a0[1], a0[2], a0[3], Ab + (unsigned)a_r * 128 + akb);
                ldsm4(a1r[0], a1r[1], a1r[2], a1r[3], Ab + (unsigned)(a_r + 16) * 128 + akb);
#pragma unroll
                for (int np = 0; np < 4; np++) {
                    int n = wn * 64 + np * 16 + ((b_g >> 1) << 3) + b_r;
                    unsigned bkb = ((unsigned)(ks * 32) + b_kb0) ^ (unsigned)((n & 7) << 4);
                    unsigned b0, b1, b2, b3;
                    ldsm4(b0, b1, b2, b3, Bb + (unsigned)n * 128 + bkb);
                    mma_f16(acc[0][2*np],   a0[0], a0[1], a0[2], a0[3], b0, b1);
                    mma_f16(acc[0][2*np+1], a0[0], a0[1], a0[2], a0[3], b2, b3);
                    mma_f16(acc[1][2*np],   a1r[0], a1r[1], a1r[2], a1r[3], b0, b1);
                    mma_f16(acc[1][2*np+1], a1r[0], a1r[1], a1r[2], a1r[3], b2, b3);
                }
            }
        }
        __syncthreads();
    }

    int qd = lane & 3;
    int rql = lane >> 2;
    float bv[16];
#pragma unroll
    for (int nt = 0; nt < 8; nt++) {
        int cg = colbase + wn * 64 + nt * 8 + 2 * qd;
        float2 t2 = *(const float2*)(bias + cg);
        bv[2*nt] = t2.x; bv[2*nt+1] = t2.y;
    }

    if (mode == 0) {
#pragma unroll
        for (int mt = 0; mt < 2; mt++)
#pragma unroll
            for (int hf = 0; hf < 2; hf++) {
                int m = r0 + wm * 32 + mt * 16 + rql + hf * 8;
                float sc = rowscale ? rowscale[m] : 1.0f;
#pragma unroll
                for (int nt = 0; nt < 8; nt++) {
                    int cg = colbase + wn * 64 + nt * 8 + 2 * qd;
                    float2 o;
                    o.x = (acc[mt][nt][2*hf]   + bv[2*nt])   * sc;
                    o.y = (acc[mt][nt][2*hf+1] + bv[2*nt+1]) * sc;
                    *(float2*)(C + (long long)m * ldc + cg) = o;
                }
            }
        return;
    }

    // mode 2: layernorm (+ fp16 plane outputs)
    float* red = (float*)smem;
    float* red2 = red + 512;
#pragma unroll
    for (int mt = 0; mt < 2; mt++)
#pragma unroll
        for (int hf = 0; hf < 2; hf++) {
            float s = 0.0f, sq = 0.0f;
#pragma unroll
            for (int nt = 0; nt < 8; nt++) {
                float f0 = acc[mt][nt][2*hf]   + bv[2*nt];
                float f1 = acc[mt][nt][2*hf+1] + bv[2*nt+1];
                s += f0 + f1; sq += f0 * f0 + f1 * f1;
            }
            s  += __shfl_xor_sync(0xffffffffu, s, 1);
            s  += __shfl_xor_sync(0xffffffffu, s, 2);
            sq += __shfl_xor_sync(0xffffffffu, sq, 1);
            sq += __shfl_xor_sync(0xffffffffu, sq, 2);
            if (qd == 0) {
                int rl = wm * 32 + mt * 16 + rql + hf * 8;
                red[rl * 4 + wn] = s;
                red2[rl * 4 + wn] = sq;
            }
        }
    __syncthreads();
    float* stats = red2 + 512;
    if (tid < 128) {
        float s = red[tid*4] + red[tid*4+1] + red[tid*4+2] + red[tid*4+3];
        float sq = red2[tid*4] + red2[tid*4+1] + red2[tid*4+2] + red2[tid*4+3];
        float mu = s * (1.0f / 256.0f);
        float var = sq * (1.0f / 256.0f) - mu * mu;
        stats[tid*2] = mu;
        stats[tid*2+1] = rsqrtf(var + 1e-5f);
    }
    __syncthreads();
    float gv[16], ev[16];
#pragma unroll
    for (int nt = 0; nt < 8; nt++) {
        int cg = wn * 64 + nt * 8 + 2 * qd;
        float2 tg = *(const float2*)(lng + cg);
        float2 te = *(const float2*)(lnb + cg);
        gv[2*nt] = tg.x; gv[2*nt+1] = tg.y;
        ev[2*nt] = te.x; ev[2*nt+1] = te.y;
    }
#pragma unroll
    for (int mt = 0; mt < 2; mt++)
#pragma unroll
        for (int hf = 0; hf < 2; hf++) {
            int rl = wm * 32 + mt * 16 + rql + hf * 8;
            int m = r0 + rl;
            float mu = stats[rl*2], inv = stats[rl*2+1];
#pragma unroll
            for (int nt = 0; nt < 8; nt++) {
                int cg = wn * 64 + nt * 8 + 2 * qd;
                float2 o;
                float f0 = acc[mt][nt][2*hf]   + bv[2*nt];
                float f1 = acc[mt][nt][2*hf+1] + bv[2*nt+1];
                o.x = (f0 - mu) * inv * gv[2*nt]   + ev[2*nt];
                o.y = (f1 - mu) * inv * gv[2*nt+1] + ev[2*nt+1];
                *(float2*)(C + (long long)m * ldc + cg) = o;
                {
                    long long e = (long long)m * 256 + cg;
                    __half x0 = __float2half_rn(o.x);
                    __half x1 = __float2half_rn(o.x - __half2float(x0));
                    __half y0 = __float2half_rn(o.y);
                    __half y1 = __float2half_rn(o.y - __half2float(y0));
                    *(unsigned*)(n0p + e) = ((unsigned)hbits(y0) << 16) | hbits(x0);
                    *(unsigned*)(n1p + e) = ((unsigned)hbits(y1) << 16) | hbits(x1);
                }
            }
        }
}

// ------------------------- scalar GEMM (sparse scatter-accum) --------
__global__ __launch_bounds__(TTH, 1)
void gemm2(const float* __restrict__ A1,
           const float* __restrict__ Wt, int ldw,
           float* __restrict__ C, const int* __restrict__ cgather, int ldc,
           int Ktot) {
    extern __shared__ float sm[];
    float* As = sm;
    float* Ws = sm + 2 * TBK * 132;

    int tid = threadIdx.x;
    int r0 = blockIdx.x * TBM;

    int am = tid >> 2;
    int ak = (tid & 3) << 2;
    int m_a = r0 + am;
    const float* a1row = A1 + (long long)m_a * Ktot;

    int wr = tid >> 5;
    int wc = (tid & 31) << 3;
    const float* wbase = Wt + (long long)wr * ldw + wc;

    float4 av, wv0, wv1;
#define LOAD_ST(kb) do {                                                      \
        av = *(const float4*)(a1row + (kb) + ak);                             \
        const float* wp_ = wbase + (long long)(kb) * ldw;                     \
        wv0 = *(const float4*)(wp_);                                          \
        wv1 = *(const float4*)(wp_ + 4);                                      \
    } while (0)
#define STORE_ST(buf) do {                                                    \
        float* ap_ = As + (buf) * (TBK * 132);                                \
        ap_[(ak + 0) * 132 + am] = av.x;                                      \
        ap_[(ak + 1) * 132 + am] = av.y;                                      \
        ap_[(ak + 2) * 132 + am] = av.z;                                      \
        ap_[(ak + 3) * 132 + am] = av.w;                                      \
        float* wpS_ = Ws + (buf) * (TBK * 256) + wr * 256 + wc;               \
        *(float4*)wpS_ = wv0;                                                 \
        *(float4*)(wpS_ + 4) = wv1;                                           \
    } while (0)

    int lane = tid & 31, warp = tid >> 5;
    int row0 = warp << 3, col0 = lane << 3;

    float acc[8][8];
#pragma unroll
    for (int r = 0; r < 8; r++)
#pragma unroll
        for (int c = 0; c < 8; c++) acc[r][c] = 0.0f;

    LOAD_ST(0); STORE_ST(0);
    __syncthreads();

    int S = Ktot / TBK;
    for (int s = 0; s < S; s++) {
        int cur = s & 1;
        if (s + 1 < S) LOAD_ST((s + 1) * TBK);
        const float* ab = As + cur * (TBK * 132);
        const float* wb = Ws + cur * (TBK * 256);
#pragma unroll
        for (int k = 0; k < TBK; k++) {
            float4 a0 = *(const float4*)(ab + k * 132 + row0);
            float4 a1v = *(const float4*)(ab + k * 132 + row0 + 4);
            float4 b0 = *(const float4*)(wb + k * 256 + col0);
            float4 b1 = *(const float4*)(wb + k * 256 + col0 + 4);
            float aa[8] = {a0.x, a0.y, a0.z, a0.w, a1v.x, a1v.y, a1v.z, a1v.w};
            float bvv[8] = {b0.x, b0.y, b0.z, b0.w, b1.x, b1.y, b1.z, b1.w};
#pragma unroll
            for (int r = 0; r < 8; r++)
#pragma unroll
                for (int c = 0; c < 8; c++) acc[r][c] += aa[r] * bvv[c];
        }
        if (s + 1 < S) { STORE_ST((s + 1) & 1); __syncthreads(); }
    }

#pragma unroll
    for (int r = 0; r < 8; r++) {
        int m = r0 + row0 + r;
        long long crow = (long long)((m >> 8) * NN + cgather[m]);
        float* cp = C + crow * ldc + col0;
        float4 o0 = *(float4*)cp, o1 = *(float4*)(cp + 4);
        o0.x += acc[r][0]; o0.y += acc[r][1]; o0.z += acc[r][2]; o0.w += acc[r][3];
        o1.x += acc[r][4]; o1.y += acc[r][5]; o1.z += acc[r][6]; o1.w += acc[r][7];
        *(float4*)cp = o0; *(float4*)(cp + 4) = o1;
    }
}

// ------------------------- attention -------------------------
__global__ void attn_kernel(const float* __restrict__ qkv, float* __restrict__ out) {
    extern __shared__ float sm[];
    float* Ks = sm;
    float* Vs = sm + MSGK * HD;
    int bh = blockIdx.x;
    int b = bh >> 2;
    int h = bh & 3;
    int tid = threadIdx.x;
    const float* base = qkv + (long long)b * MSGK * 768;

    for (int t = tid; t < MSGK * HD; t += 256) {
        int j = t >> 6;
        int d = t & 63;
        Ks[t] = base[j * 768 + 256 + h * 64 + d];
        Vs[t] = base[j * 768 + 512 + h * 64 + d];
    }
    __syncthreads();

    float q[HD], o[HD];
#pragma unroll
    for (int d = 0; d < HD; d++) { q[d] = base[tid * 768 + h * 64 + d] * 0.125f; o[d] = 0.0f; }

    float mval = -1e30f, l = 0.0f;
    for (int j = 0; j < MSGK; j++) {
        float s = 0.0f;
#pragma unroll
        for (int d = 0; d < HD; d++) s += q[d] * Ks[j * 64 + d];
        float nm = fmaxf(mval, s);
        float corr = expf(mval - nm);
        float p = expf(s - nm);
        l = l * corr + p;
#pragma unroll
        for (int d = 0; d < HD; d++) o[d] = o[d] * corr + p * Vs[j * 64 + d];
        mval = nm;
    }
    float inv = 1.0f / l;
    float* op = out + ((long long)(b * MSGK + tid)) * DD + h * 64;
#pragma unroll
    for (int d = 0; d < HD; d++) op[d] = o[d] * inv;
}

// ------------------------- finalize -------------------------
__global__ void finalize_kernel(const float* __restrict__ newact, const float* __restrict__ newhid,
                                const int* __restrict__ slot2, float* __restrict__ out) {
    long long total_act = (long long)BB * NN;
    float* out_act = out;
    float* out_hid = out + total_act;
    long long stride = (long long)gridDim.x * blockDim.x;
    long long t0 = (long long)blockIdx.x * blockDim.x + threadIdx.x;

    for (long long i = t0; i < total_act; i += stride)
        out_act[i] = (slot2[i] >= 0) ? newact[i] : 0.0f;

    long long totalh4 = (long long)BB * NN * DD / 4;
    float4* oh4 = reinterpret_cast<float4*>(out_hid);
    const float4* nh4 = reinterpret_cast<const float4*>(newhid);
    for (long long e = t0; e < totalh4; e += stride) {
        long long r = e >> 6;
        oh4[e] = (slot2[r] >= 0) ? nh4[e] : make_float4(0.f, 0.f, 0.f, 0.f);
    }
}

// ------------------------- host launcher -------------------------
extern "C" void kernel_launch(void* const* d_in, const int* in_sizes, int n_in,
                              void* d_out, int out_size) {
    const float* act    = (const float*)d_in[0];
    const float* hidden = (const float*)d_in[1];
    const float* in_w   = (const float*)d_in[2];
    const float* in_b   = (const float*)d_in[3];
    const float* out_w  = (const float*)d_in[4];
    const float* out_b  = (const float*)d_in[5];
    const float* su_w1  = (const float*)d_in[6];
    const float* su_b1  = (const float*)d_in[7];
    const float* su_w2  = (const float*)d_in[8];
    const float* su_b2  = (const float*)d_in[9];
    const float* au_w1  = (const float*)d_in[10];
    const float* au_b1  = (const float*)d_in[11];
    const float* au_w2  = (const float*)d_in[12];
    const float* au_b2  = (const float*)d_in[13];
    const float* ln_g   = (const float*)d_in[14];
    const float* ln_b   = (const float*)d_in[15];
    const int*   kptr   = (const int*)d_in[16];

    int*   p_tidx;   cudaGetSymbolAddress((void**)&p_tidx,   g_tidx);
    float* p_tval;   cudaGetSymbolAddress((void**)&p_tval,   g_tval);
    int*   p_slot;   cudaGetSymbolAddress((void**)&p_slot,   g_slot);
    int*   p_slot2;  cudaGetSymbolAddress((void**)&p_slot2,  g_slot2);
    float* p_qkv;    cudaGetSymbolAddress((void**)&p_qkv,    g_qkv);
    float* p_attn;   cudaGetSymbolAddress((void**)&p_attn,   g_attn);
    float* p_msg;    cudaGetSymbolAddress((void**)&p_msg,    g_msg);
    float* p_h;      cudaGetSymbolAddress((void**)&p_h,      g_h);
    float* p_newhid; cudaGetSymbolAddress((void**)&p_newhid, g_newhid);
    float* p_newact; cudaGetSymbolAddress((void**)&p_newact, g_newact);
    float* wt_su1;   cudaGetSymbolAddress((void**)&wt_su1,   g_wt_su1);

    __half *in0,*in1, *ow0,*ow1, *s10,*s11, *s20,*s21, *a10,*a11;
    __half *h0,*h1, *n0,*n1;
    cudaGetSymbolAddress((void**)&in0, g_in0); cudaGetSymbolAddress((void**)&in1, g_in1);
    cudaGetSymbolAddress((void**)&ow0, g_ow0); cudaGetSymbolAddress((void**)&ow1, g_ow1);
    cudaGetSymbolAddress((void**)&s10, g_s10); cudaGetSymbolAddress((void**)&s11, g_s11);
    cudaGetSymbolAddress((void**)&s20, g_s20); cudaGetSymbolAddress((void**)&s21, g_s21);
    cudaGetSymbolAddress((void**)&a10, g_a10); cudaGetSymbolAddress((void**)&a11, g_a11);
    cudaGetSymbolAddress((void**)&h0, g_h0); cudaGetSymbolAddress((void**)&h1, g_h1);
    cudaGetSymbolAddress((void**)&n0, g_n0); cudaGetSymbolAddress((void**)&n1, g_n1);

    const int SMEM_GEMM2 = (2 * TBK * 132 + 2 * TBK * 256) * 4;
    const int SMEM_ATTN  = 2 * MSGK * HD * 4;

    cudaFuncSetAttribute(mma_gemm, cudaFuncAttributeMaxDynamicSharedMemorySize, TC_SMEM);
    cudaFuncSetAttribute(mma_gemm_ps, cudaFuncAttributeMaxDynamicSharedMemorySize, PS_SMEM);
    cudaFuncSetAttribute(gemm2, cudaFuncAttributeMaxDynamicSharedMemorySize, SMEM_GEMM2);
    cudaFuncSetAttribute(attn_kernel, cudaFuncAttributeMaxDynamicSharedMemorySize, SMEM_ATTN);

    // 0) weight + activation prep (fp16 2-way splits)
    split2_kernel<<<768, 256>>>(in_w,  in0, in1, 768 * 256);
    split2_kernel<<<256, 256>>>(out_w, ow0, ow1, 256 * 256);
    split2_kernel<<<512, 256>>>(su_w1, s10, s11, 256 * 512);
    split2_kernel<<<256, 256>>>(su_w2, s20, s21, 256 * 256);
    split2_kernel<<<512, 256>>>(au_w1, a10, a11, 256 * 512);
    transpose_kernel<<<dim3(16, 8), dim3(32, 8)>>>(su_w1, wt_su1, 256, 512);
    split2_kernel<<<BB * NN * DD / 256, 256>>>(hidden, h0, h1, BB * NN * DD);

    // 1) top-k of activation
    sort_topk_kernel<<<BB, 1024>>>(act, nullptr, MSGK, p_tidx, p_tval, p_slot);

    // 2) QKV: gathered rows from hidden planes, 3-term fp16, pipelined
    mma_gemm_ps<<<dim3(64, 3), 512, PS_SMEM>>>(
        h0, h1, nullptr, nullptr, p_tidx,
        in0, in1, 256, in_b,
        nullptr, nullptr, nullptr, nullptr,
        p_qkv, 768, 256, 256, 256, 256, 0);

    // 3) attention
    attn_kernel<<<BB * 4, 256, SMEM_ATTN>>>(p_qkv, p_attn);

    // 4) out-proj * topk_val -> msg   (convert path, 3-term fp16)
    mma_gemm<<<dim3(64, 1), 512, TC_SMEM>>>(
        p_attn, ow0, ow1, 256, out_b,
        p_tval, nullptr, nullptr,
        p_msg, 256, nullptr, nullptr,
        256, 0, 0);

    // 5a) su1 dense: pre = hidden @ W1a^T + b1   (3-term fp16, pipelined)
    mma_gemm_ps<<<dim3(1024, 1), 512, PS_SMEM>>>(
        h0, h1, nullptr, nullptr, nullptr,
        s10, s11, 512, su_b1,
        nullptr, nullptr, nullptr, nullptr,
        p_h, 256, 256, 256, 256, 256, 0);

    // 5b) su1 sparse: pre[active] += msg @ W1b^T  (scalar fp32, exact)
    gemm2<<<dim3(64, 1), TTH, SMEM_GEMM2>>>(
        p_msg, wt_su1 + 256 * 256, 256, p_h, p_tidx, 256, 256);

    // 6) su2: newhid = LN( gelu(pre) @ W2^T + b2 ); emit newhid fp16 planes
    mma_gemm<<<dim3(1024, 1), 512, TC_SMEM>>>(
        p_h, s20, s21, 256, su_b2,
        nullptr, ln_g, ln_b,
        p_newhid, 256, n0, n1,
        256, 1, 2);

    // 7) au1 fused act update (3-term fp16, pipelined, A = [hidden|newhid] planes)
    mma_gemm_ps<<<dim3(1024, 1), 512, PS_SMEM>>>(
        h0, h1, n0, n1, nullptr,
        a10, a11, 512, au_b1,
        au_w2, au_b2, act, p_newact,
        nullptr, 256, 256, 256, 256, 512, 3);

    // 8) final top-k (k from device sparsity_k)
    sort_topk_kernel<<<BB, 1024>>>(p_newact, kptr, 0, nullptr, nullptr, p_slot2);

    // 9) masked write [sparse_act | sparse_hidden]
    finalize_kernel<<<2048, 256>>>(p_newact, p_newhid, p_slot2, (float*)d_out);
}

// round 12
// speedup vs baseline: 8.6808x; 1.0639x over previous
#include <cuda_runtime.h>
#include <cuda_fp16.h>
#include <math.h>

#define BB 32
#define NN 4096
#define DD 256
#define MSGK 256
#define HD 64

// scalar gemm (sparse scatter-accum only)
#define TBM 128
#define TBK 16
#define TTH 512

// ------------------------- device scratch -------------------------
__device__ int   g_tidx[BB * MSGK];
__device__ float g_tval[BB * MSGK];
__device__ int   g_slot[BB * NN];
__device__ int   g_slot2[BB * NN];
__device__ float g_qkv[BB * MSGK * 3 * DD];
__device__ float g_attn[BB * MSGK * DD];
__device__ float g_msg[BB * MSGK * DD];
__device__ float g_h[(size_t)BB * NN * DD];
__device__ float g_newact[BB * NN];
__device__ float g_wt_su1[512 * 256];

// fp16 2-way splits of weights
__device__ __half g_in0[768*256],  g_in1[768*256];
__device__ __half g_ow0[256*256],  g_ow1[256*256];
__device__ __half g_s10[256*512],  g_s11[256*512];
__device__ __half g_s20[256*256],  g_s21[256*256];
__device__ __half g_a10[256*512],  g_a11[256*512];

// fp16 2-way splits of activations
__device__ __half g_h0[(size_t)BB*NN*DD], g_h1[(size_t)BB*NN*DD];
__device__ __half g_n0[(size_t)BB*NN*DD], g_n1[(size_t)BB*NN*DD];

__device__ __forceinline__ float gelu_f(float x) {
    return 0.5f * x * (1.0f + erff(x * 0.70710678118654752440f));
}

__device__ __forceinline__ unsigned smem_u32(const void* p) {
    unsigned a;
    asm("{ .reg .u64 t; cvta.to.shared.u64 t, %1; cvt.u32.u64 %0, t; }" : "=r"(a) : "l"(p));
    return a;
}

__device__ __forceinline__ void ldsm4(unsigned& r0, unsigned& r1, unsigned& r2, unsigned& r3,
                                      unsigned addr) {
    asm volatile("ldmatrix.sync.aligned.m8n8.x4.shared.b16 {%0,%1,%2,%3}, [%4];"
                 : "=r"(r0), "=r"(r1), "=r"(r2), "=r"(r3) : "r"(addr));
}

__device__ __forceinline__ void mma_f16(float* c, unsigned a0, unsigned a1, unsigned a2,
                                        unsigned a3, unsigned b0, unsigned b1) {
    asm volatile("mma.sync.aligned.m16n8k16.row.col.f32.f16.f16.f32 "
                 "{%0,%1,%2,%3},{%4,%5,%6,%7},{%8,%9},{%0,%1,%2,%3};"
                 : "+f"(c[0]), "+f"(c[1]), "+f"(c[2]), "+f"(c[3])
                 : "r"(a0), "r"(a1), "r"(a2), "r"(a3), "r"(b0), "r"(b1));
}

#define CPASYNC16(dst, src) \
    asm volatile("cp.async.cg.shared.global [%0], [%1], 16;" :: "r"(dst), "l"(src) : "memory")
#define CPCOMMIT() asm volatile("cp.async.commit_group;" ::: "memory")
#define CPWAIT0() asm volatile("cp.async.wait_group 0;" ::: "memory")
#define CPWAIT1() asm volatile("cp.async.wait_group 1;" ::: "memory")

__device__ __forceinline__ unsigned short hbits(__half h) {
    return *(unsigned short*)&h;
}

// ------------------------- weight split (fp16 2-way) -------------------------
__global__ void split2_kernel(const float* __restrict__ W, __half* o0, __half* o1, int n) {
    int i = blockIdx.x * 256 + threadIdx.x;
    if (i < n) {
        float v = W[i];
        __half a = __float2half_rn(v);
        float r = v - __half2float(a);
        o0[i] = a; o1[i] = __float2half_rn(r);
    }
}

// ------------------------- weight transpose (scalar scatter gemm) ------------
__global__ void transpose_kernel(const float* __restrict__ W, float* __restrict__ Wt,
                                 int Nout, int Kd) {
    __shared__ float t[32][33];
    int k0 = blockIdx.x * 32, n0 = blockIdx.y * 32;
    int tx = threadIdx.x, ty = threadIdx.y;
#pragma unroll
    for (int i = 0; i < 32; i += 8)
        t[ty + i][tx] = W[(long long)(n0 + ty + i) * Kd + k0 + tx];
    __syncthreads();
#pragma unroll
    for (int i = 0; i < 32; i += 8)
        Wt[(long long)(k0 + ty + i) * Nout + n0 + tx] = t[tx][ty + i];
}

// ------------------------- top-k via bitonic sort -------------------------
__global__ void sort_topk_kernel(const float* __restrict__ act,
                                 const int* __restrict__ kptr, int kconst,
                                 int* __restrict__ idx_out, float* __restrict__ val_out,
                                 int* __restrict__ slotmap) {
    __shared__ float sv[NN];
    __shared__ int   si[NN];
    int b = blockIdx.x;
    int tid = threadIdx.x;
    int kk = kptr ? *kptr : kconst;
    if (kk > NN) kk = NN;
    if (kk < 0) kk = 0;

    for (int i = tid; i < NN; i += blockDim.x) { sv[i] = act[b * NN + i]; si[i] = i; }
    __syncthreads();

    for (int ksz = 2; ksz <= NN; ksz <<= 1) {
        for (int j = ksz >> 1; j > 0; j >>= 1) {
            for (int i = tid; i < NN; i += blockDim.x) {
                int ixj = i ^ j;
                if (ixj > i) {
                    bool dirDesc = ((i & ksz) == 0);
                    float vi = sv[i], vx = sv[ixj];
                    bool sw = dirDesc ? (vi < vx) : (vi > vx);
                    if (sw) {
                        sv[i] = vx; sv[ixj] = vi;
                        int t = si[i]; si[i] = si[ixj]; si[ixj] = t;
                    }
                }
            }
            __syncthreads();
        }
    }

    for (int i = tid; i < NN; i += blockDim.x) slotmap[b * NN + i] = -1;
    __syncthreads();
    for (int j = tid; j < kk; j += blockDim.x) {
        slotmap[b * NN + si[j]] = j;
        if (idx_out) { idx_out[b * kk + j] = si[j]; val_out[b * kk + j] = sv[j]; }
    }
}

// ======================= pre-split pipelined tensor GEMM (fp16, 3-term) =======
#define PS_AP 8192
#define PS_BOFF 16384
#define PS_BP 16384
#define PS_STAGE 49152
#define PS_SMEM (2 * PS_STAGE)   // 98304

__global__ __launch_bounds__(512, 1)
void mma_gemm_ps(const __half* __restrict__ A0, const __half* __restrict__ A1p,
                 const __half* __restrict__ Z0, const __half* __restrict__ Z1,
                 const int* __restrict__ gather,
                 const __half* __restrict__ W0, const __half* __restrict__ W1, int ldw,
                 const float* __restrict__ bias,
                 const float* __restrict__ w2, const float* __restrict__ b2,
                 const float* __restrict__ act_in, float* __restrict__ act_out,
                 float* __restrict__ C, int ldc,
                 int K1, int lda1, int lda2, int Ktot, int mode) {
    extern __shared__ char smem[];
    unsigned sbase = smem_u32(smem);
    int tid = threadIdx.x;
    int lane = tid & 31;
    int wid = tid >> 5;
    int wm = wid & 3;
    int wn = wid >> 2;
    int r0 = blockIdx.x * 128;
    int colbase = blockIdx.y * 256;

    // ---- staging maps ----
    int arow = tid >> 2, au = tid & 3;
    int m_a = r0 + arow;
    long long ridx1 = gather ? (long long)((m_a >> 8) * NN + gather[m_a]) : m_a;
    const char* a1b0 = (const char*)(A0 + ridx1 * lda1);
    const char* a1b1 = (const char*)(A1p + ridx1 * lda1);
    const char* a2b0 = Z0 ? (const char*)(Z0 + (long long)m_a * lda2) : a1b0;
    const char* a2b1 = Z1 ? (const char*)(Z1 + (long long)m_a * lda2) : a1b1;
    unsigned aswz = ((arow >> 1) & 3) << 4;
    unsigned adst0 = (unsigned)arow * 64 + ((au * 16) ^ aswz);

    int bn = tid >> 1;
    int bu0 = (tid & 1) * 2;
    unsigned bswz = ((bn >> 1) & 3) << 4;
    long long brow = (long long)(colbase + bn) * ldw;

    const int ta3[3] = {0, 0, 1};
    const int tb3[3] = {0, 1, 0};

    // ---- mma fragment addressing ----
    int a_r = wm * 32 + (lane & 15);
    unsigned a_k0 = (unsigned)((lane >> 4) << 4);
    unsigned a_sw = ((a_r >> 1) & 3) << 4;
    int b_g = lane >> 3, b_r = lane & 7;
    int b_n0 = wn * 64 + ((b_g >> 1) << 3) + b_r;
    unsigned b_k0 = (unsigned)((b_g & 1) << 4);

    float acc[2][8][4];
#pragma unroll
    for (int mt = 0; mt < 2; mt++)
#pragma unroll
        for (int nt = 0; nt < 8; nt++)
#pragma unroll
            for (int c = 0; c < 4; c++) acc[mt][nt][c] = 0.0f;

    int nc = Ktot >> 5;

#define PS_STAGE_FN(c_) do {                                                   \
        int buf_ = (c_) & 1;                                                   \
        unsigned stg_ = sbase + buf_ * PS_STAGE;                               \
        int kc_ = (c_) << 5;                                                   \
        const char *p0_, *p1_; long long ko_;                                  \
        if (kc_ < K1) { p0_ = a1b0; p1_ = a1b1; ko_ = kc_; }                   \
        else          { p0_ = a2b0; p1_ = a2b1; ko_ = kc_ - K1; }              \
        long long ab_ = ko_ * 2 + au * 16;                                     \
        unsigned ad_ = stg_ + adst0;                                           \
        CPASYNC16(ad_, p0_ + ab_);                                             \
        CPASYNC16(ad_ + PS_AP, p1_ + ab_);                                     \
        long long bo_ = (brow + kc_) * 2;                                      \
        unsigned bd_ = stg_ + PS_BOFF + (unsigned)bn * 64;                     \
        unsigned k0_ = (unsigned)(bu0 * 16), k1_ = k0_ + 16;                   \
        CPASYNC16(bd_ + (k0_ ^ bswz), (const char*)W0 + bo_ + k0_);            \
        CPASYNC16(bd_ + (k1_ ^ bswz), (const char*)W0 + bo_ + k1_);            \
        CPASYNC16(bd_ + PS_BP + (k0_ ^ bswz), (const char*)W1 + bo_ + k0_);    \
        CPASYNC16(bd_ + PS_BP + (k1_ ^ bswz), (const char*)W1 + bo_ + k1_);    \
    } while (0)

    PS_STAGE_FN(0);
    CPCOMMIT();

    for (int c = 0; c < nc; c++) {
        if (c + 1 < nc) { PS_STAGE_FN(c + 1); CPCOMMIT(); CPWAIT1(); }
        else            { CPWAIT0(); }
        __syncthreads();

        unsigned stg = sbase + (c & 1) * PS_STAGE;
#pragma unroll
        for (int p = 0; p < 3; p++) {
            unsigned Ab = stg + ta3[p] * PS_AP;
            unsigned Bb = stg + PS_BOFF + tb3[p] * PS_BP;
#pragma unroll
            for (int ks = 0; ks < 2; ks++) {
                unsigned akb = ((unsigned)(ks << 5) + a_k0) ^ a_sw;
                unsigned a0[4], a1r[4];
                ldsm4(a0[0], a0[1], a0[2], a0[3], Ab + (unsigned)a_r * 64 + akb);
                ldsm4(a1r[0], a1r[1], a1r[2], a1r[3], Ab + (unsigned)(a_r + 16) * 64 + akb);
#pragma unroll
                for (int np = 0; np < 4; np++) {
                    int n = b_n0 + np * 16;
                    unsigned bkb = ((unsigned)(ks << 5) + b_k0) ^ (unsigned)(((n >> 1) & 3) << 4);
                    unsigned b0, b1, b2, b3;
                    ldsm4(b0, b1, b2, b3, Bb + (unsigned)n * 64 + bkb);
                    mma_f16(acc[0][2*np],   a0[0], a0[1], a0[2], a0[3], b0, b1);
                    mma_f16(acc[0][2*np+1], a0[0], a0[1], a0[2], a0[3], b2, b3);
                    mma_f16(acc[1][2*np],   a1r[0], a1r[1], a1r[2], a1r[3], b0, b1);
                    mma_f16(acc[1][2*np+1], a1r[0], a1r[1], a1r[2], a1r[3], b2, b3);
                }
            }
        }
        __syncthreads();
    }

    // ---------------- epilogue ----------------
    int qd = lane & 3;
    int rql = lane >> 2;
    float bv[16];
#pragma unroll
    for (int nt = 0; nt < 8; nt++) {
        int cg = colbase + wn * 64 + nt * 8 + 2 * qd;
        float2 t2 = *(const float2*)(bias + cg);
        bv[2*nt] = t2.x; bv[2*nt+1] = t2.y;
    }

    if (mode == 0) {
#pragma unroll
        for (int mt = 0; mt < 2; mt++)
#pragma unroll
            for (int hf = 0; hf < 2; hf++) {
                int m = r0 + wm * 32 + mt * 16 + rql + hf * 8;
#pragma unroll
                for (int nt = 0; nt < 8; nt++) {
                    int cg = colbase + wn * 64 + nt * 8 + 2 * qd;
                    float2 o;
                    o.x = acc[mt][nt][2*hf]   + bv[2*nt];
                    o.y = acc[mt][nt][2*hf+1] + bv[2*nt+1];
                    *(float2*)(C + (long long)m * ldc + cg) = o;
                }
            }
        return;
    }

    // mode 3: gelu + dot(w2) + sigmoid blend
    {
        float* red = (float*)smem;
        float wv[16];
#pragma unroll
        for (int nt = 0; nt < 8; nt++) {
            int cg = wn * 64 + nt * 8 + 2 * qd;
            float2 tw = *(const float2*)(w2 + cg);
            wv[2*nt] = tw.x; wv[2*nt+1] = tw.y;
        }
#pragma unroll
        for (int mt = 0; mt < 2; mt++)
#pragma unroll
            for (int hf = 0; hf < 2; hf++) {
                float d = 0.0f;
#pragma unroll
                for (int nt = 0; nt < 8; nt++) {
                    float f0 = gelu_f(acc[mt][nt][2*hf]   + bv[2*nt]);
                    float f1 = gelu_f(acc[mt][nt][2*hf+1] + bv[2*nt+1]);
                    d += f0 * wv[2*nt] + f1 * wv[2*nt+1];
                }
                d += __shfl_xor_sync(0xffffffffu, d, 1);
                d += __shfl_xor_sync(0xffffffffu, d, 2);
                if (qd == 0) {
                    int rl = wm * 32 + mt * 16 + rql + hf * 8;
                    red[rl * 4 + wn] = d;
                }
            }
        __syncthreads();
        if (tid < 128) {
            float d = red[tid*4] + red[tid*4+1] + red[tid*4+2] + red[tid*4+3];
            float dl = 1.0f / (1.0f + expf(-(d + b2[0])));
            int m = r0 + tid;
            float na = 0.7f * act_in[m] + 0.3f * dl;
            na = fminf(fmaxf(na, 0.0f), 1.0f);
            act_out[m] = na;
        }
    }
}

// ======================= convert-path tensor GEMM (fp32 A, fp16 3-term) =======
#define A_TERM 16384
#define B_TERM 32768
#define BB_OFF (2 * A_TERM)
#define TC_SMEM (2 * A_TERM + 2 * B_TERM)   // 98304

__global__ __launch_bounds__(512, 1)
void mma_gemm(const float* __restrict__ A1,
              const __half* __restrict__ W0, const __half* __restrict__ W1, int ldw,
              const float* __restrict__ bias,
              const float* __restrict__ rowscale,
              const float* __restrict__ lng, const float* __restrict__ lnb,
              float* __restrict__ C, int ldc,
              __half* __restrict__ n0p, __half* __restrict__ n1p,
              int Ktot, int a1_gelu, int mode) {
    extern __shared__ char smem[];
    unsigned sbase = smem_u32(smem);
    int tid = threadIdx.x;
    int lane = tid & 31;
    int wid = tid >> 5;
    int wm = wid & 3;
    int wn = wid >> 2;
    int r0 = blockIdx.x * 128;
    int colbase = blockIdx.y * 256;

    int s_arow = tid >> 2;
    int s_aq   = tid & 3;
    int m_a = r0 + s_arow;
    const float* a1p = A1 + (long long)m_a * Ktot;

    int s_bn = tid >> 1;
    int s_bh = tid & 1;
    long long bro = (long long)(colbase + s_bn) * ldw;

    const int ta3[3] = {0, 0, 1};
    const int tb3[3] = {0, 1, 0};

    int a_r = wm * 32 + (lane & 15);
    unsigned a_sw = (unsigned)((a_r & 7) << 4);
    unsigned a_kb0 = (unsigned)((lane >> 4) << 4);
    int b_g = lane >> 3, b_r = lane & 7;
    unsigned b_kb0 = (unsigned)((b_g & 1) << 4);

    float acc[2][8][4];
#pragma unroll
    for (int mt = 0; mt < 2; mt++)
#pragma unroll
        for (int nt = 0; nt < 8; nt++)
#pragma unroll
            for (int c = 0; c < 4; c++) acc[mt][nt][c] = 0.0f;

    int nchunks = Ktot >> 6;
    for (int ch = 0; ch < nchunks; ch++) {
        int kc = ch << 6;
        {
            const float* src = a1p + kc + s_aq * 16;
            float v[16];
#pragma unroll
            for (int j = 0; j < 4; j++) {
                float4 t4 = *(const float4*)(src + j * 4);
                v[j*4+0] = t4.x; v[j*4+1] = t4.y; v[j*4+2] = t4.z; v[j*4+3] = t4.w;
            }
            if (a1_gelu) {
#pragma unroll
                for (int j = 0; j < 16; j++) v[j] = gelu_f(v[j]);
            }
            unsigned u0[8], u1[8];
#pragma unroll
            for (int j = 0; j < 8; j++) {
                float x = v[2*j], y = v[2*j+1];
                __half hx0 = __float2half_rn(x);
                __half hy0 = __float2half_rn(y);
                __half hx1 = __float2half_rn(x - __half2float(hx0));
                __half hy1 = __float2half_rn(y - __half2float(hy0));
                u0[j] = ((unsigned)hbits(hy0) << 16) | hbits(hx0);
                u1[j] = ((unsigned)hbits(hy1) << 16) | hbits(hx1);
            }
            unsigned rsw = (unsigned)((s_arow & 7) << 4);
            unsigned rb = (unsigned)s_arow * 128;
#pragma unroll
            for (int j8 = 0; j8 < 4; j8++) {
                unsigned kb = (unsigned)(s_aq * 32 + j8 * 8) ^ rsw;
                *(uint2*)(smem + rb + kb) = make_uint2(u0[2*j8], u0[2*j8+1]);
                *(uint2*)(smem + A_TERM + rb + kb) = make_uint2(u1[2*j8], u1[2*j8+1]);
            }
        }
        {
            unsigned nsw = (unsigned)((s_bn & 7) << 4);
            unsigned nb = (unsigned)s_bn * 128;
            long long goff = (bro + kc) * 2;
#pragma unroll
            for (int w = 0; w < 2; w++) {
                const char* Wsrc = (const char*)((w == 0) ? W0 : W1);
#pragma unroll
                for (int i = 0; i < 4; i++) {
                    unsigned kb = (unsigned)(s_bh * 64 + i * 16);
                    CPASYNC16(sbase + BB_OFF + w * B_TERM + nb + (kb ^ nsw), Wsrc + goff + kb);
                }
            }
        }
        CPCOMMIT();
        CPWAIT0();
        __syncthreads();

#pragma unroll
        for (int p = 0; p < 3; p++) {
            unsigned Ab = sbase + ta3[p] * A_TERM;
            unsigned Bb = sbase + BB_OFF + tb3[p] * B_TERM;
#pragma unroll
            for (int ks = 0; ks < 4; ks++) {
                unsigned a0[4], a1r[4];
                unsigned akb = ((unsigned)(ks * 32) + a_kb0) ^ a_sw;
                ldsm4(a0[0], a0[1], a0[2], a0[3], Ab + (unsigned)a_r * 128 + akb);
                ldsm4(a1r[0], a1r[1], a1r[2], a1r[3], Ab + (unsigned)(a_r + 16) * 128 + akb);
#pragma unroll
                for (int np = 0; np < 4; np++) {
                    int n = wn * 64 + np * 16 + ((b_g >> 1) << 3) + b_r;
                    unsigned bkb = ((unsigned)(ks * 32) + b_kb0) ^ (unsigned)((n & 7) << 4);
                    unsigned b0, b1, b2, b3;
                    ldsm4(b0, b1, b2, b3, Bb + (unsigned)n * 128 + bkb);
                    mma_f16(acc[0][2*np],   a0[0], a0[1], a0[2], a0[3], b0, b1);
                    mma_f16(acc[0][2*np+1], a0[0], a0[1], a0[2], a0[3], b2, b3);
                    mma_f16(acc[1][2*np],   a1r[0], a1r[1], a1r[2], a1r[3], b0, b1);
                    mma_f16(acc[1][2*np+1], a1r[0], a1r[1], a1r[2], a1r[3], b2, b3);
                }
            }
        }
        __syncthreads();
    }

    int qd = lane & 3;
    int rql = lane >> 2;
    float bv[16];
#pragma unroll
    for (int nt = 0; nt < 8; nt++) {
        int cg = colbase + wn * 64 + nt * 8 + 2 * qd;
        float2 t2 = *(const float2*)(bias + cg);
        bv[2*nt] = t2.x; bv[2*nt+1] = t2.y;
    }

    if (mode == 0) {
#pragma unroll
        for (int mt = 0; mt < 2; mt++)
#pragma unroll
            for (int hf = 0; hf < 2; hf++) {
                int m = r0 + wm * 32 + mt * 16 + rql + hf * 8;
                float sc = rowscale ? rowscale[m] : 1.0f;
#pragma unroll
                for (int nt = 0; nt < 8; nt++) {
                    int cg = colbase + wn * 64 + nt * 8 + 2 * qd;
                    float2 o;
                    o.x = (acc[mt][nt][2*hf]   + bv[2*nt])   * sc;
                    o.y = (acc[mt][nt][2*hf+1] + bv[2*nt+1]) * sc;
                    *(float2*)(C + (long long)m * ldc + cg) = o;
                }
            }
        return;
    }

    // mode 2: layernorm -> fp16 plane outputs (fp32 store optional via C)
    float* red = (float*)smem;
    float* red2 = red + 512;
#pragma unroll
    for (int mt = 0; mt < 2; mt++)
#pragma unroll
        for (int hf = 0; hf < 2; hf++) {
            float s = 0.0f, sq = 0.0f;
#pragma unroll
            for (int nt = 0; nt < 8; nt++) {
                float f0 = acc[mt][nt][2*hf]   + bv[2*nt];
                float f1 = acc[mt][nt][2*hf+1] + bv[2*nt+1];
                s += f0 + f1; sq += f0 * f0 + f1 * f1;
            }
            s  += __shfl_xor_sync(0xffffffffu, s, 1);
            s  += __shfl_xor_sync(0xffffffffu, s, 2);
            sq += __shfl_xor_sync(0xffffffffu, sq, 1);
            sq += __shfl_xor_sync(0xffffffffu, sq, 2);
            if (qd == 0) {
                int rl = wm * 32 + mt * 16 + rql + hf * 8;
                red[rl * 4 + wn] = s;
                red2[rl * 4 + wn] = sq;
            }
        }
    __syncthreads();
    float* stats = red2 + 512;
    if (tid < 128) {
        float s = red[tid*4] + red[tid*4+1] + red[tid*4+2] + red[tid*4+3];
        float sq = red2[tid*4] + red2[tid*4+1] + red2[tid*4+2] + red2[tid*4+3];
        float mu = s * (1.0f / 256.0f);
        float var = sq * (1.0f / 256.0f) - mu * mu;
        stats[tid*2] = mu;
        stats[tid*2+1] = rsqrtf(var + 1e-5f);
    }
    __syncthreads();
    float gv[16], ev[16];
#pragma unroll
    for (int nt = 0; nt < 8; nt++) {
        int cg = wn * 64 + nt * 8 + 2 * qd;
        float2 tg = *(const float2*)(lng + cg);
        float2 te = *(const float2*)(lnb + cg);
        gv[2*nt] = tg.x; gv[2*nt+1] = tg.y;
        ev[2*nt] = te.x; ev[2*nt+1] = te.y;
    }
#pragma unroll
    for (int mt = 0; mt < 2; mt++)
#pragma unroll
        for (int hf = 0; hf < 2; hf++) {
            int rl = wm * 32 + mt * 16 + rql + hf * 8;
            int m = r0 + rl;
            float mu = stats[rl*2], inv = stats[rl*2+1];
#pragma unroll
            for (int nt = 0; nt < 8; nt++) {
                int cg = wn * 64 + nt * 8 + 2 * qd;
                float2 o;
                float f0 = acc[mt][nt][2*hf]   + bv[2*nt];
                float f1 = acc[mt][nt][2*hf+1] + bv[2*nt+1];
                o.x = (f0 - mu) * inv * gv[2*nt]   + ev[2*nt];
                o.y = (f1 - mu) * inv * gv[2*nt+1] + ev[2*nt+1];
                if (C) *(float2*)(C + (long long)m * ldc + cg) = o;
                {
                    long long e = (long long)m * 256 + cg;
                    __half x0 = __float2half_rn(o.x);
                    __half x1 = __float2half_rn(o.x - __half2float(x0));
                    __half y0 = __float2half_rn(o.y);
                    __half y1 = __float2half_rn(o.y - __half2float(y0));
                    *(unsigned*)(n0p + e) = ((unsigned)hbits(y0) << 16) | hbits(x0);
                    *(unsigned*)(n1p + e) = ((unsigned)hbits(y1) << 16) | hbits(x1);
                }
            }
        }
}

// ------------------------- scalar GEMM (sparse scatter-accum) --------
__global__ __launch_bounds__(TTH, 1)
void gemm2(const float* __restrict__ A1,
           const float* __restrict__ Wt, int ldw,
           float* __restrict__ C, const int* __restrict__ cgather, int ldc,
           int Ktot) {
    extern __shared__ float sm[];
    float* As = sm;
    float* Ws = sm + 2 * TBK * 132;

    int tid = threadIdx.x;
    int r0 = blockIdx.x * TBM;

    int am = tid >> 2;
    int ak = (tid & 3) << 2;
    int m_a = r0 + am;
    const float* a1row = A1 + (long long)m_a * Ktot;

    int wr = tid >> 5;
    int wc = (tid & 31) << 3;
    const float* wbase = Wt + (long long)wr * ldw + wc;

    float4 av, wv0, wv1;
#define LOAD_ST(kb) do {                                                      \
        av = *(const float4*)(a1row + (kb) + ak);                             \
        const float* wp_ = wbase + (long long)(kb) * ldw;                     \
        wv0 = *(const float4*)(wp_);                                          \
        wv1 = *(const float4*)(wp_ + 4);                                      \
    } while (0)
#define STORE_ST(buf) do {                                                    \
        float* ap_ = As + (buf) * (TBK * 132);                                \
        ap_[(ak + 0) * 132 + am] = av.x;                                      \
        ap_[(ak + 1) * 132 + am] = av.y;                                      \
        ap_[(ak + 2) * 132 + am] = av.z;                                      \
        ap_[(ak + 3) * 132 + am] = av.w;                                      \
        float* wpS_ = Ws + (buf) * (TBK * 256) + wr * 256 + wc;               \
        *(float4*)wpS_ = wv0;                                                 \
        *(float4*)(wpS_ + 4) = wv1;                                           \
    } while (0)

    int lane = tid & 31, warp = tid >> 5;
    int row0 = warp << 3, col0 = lane << 3;

    float acc[8][8];
#pragma unroll
    for (int r = 0; r < 8; r++)
#pragma unroll
        for (int c = 0; c < 8; c++) acc[r][c] = 0.0f;

    LOAD_ST(0); STORE_ST(0);
    __syncthreads();

    int S = Ktot / TBK;
    for (int s = 0; s < S; s++) {
        int cur = s & 1;
        if (s + 1 < S) LOAD_ST((s + 1) * TBK);
        const float* ab = As + cur * (TBK * 132);
        const float* wb = Ws + cur * (TBK * 256);
#pragma unroll
        for (int k = 0; k < TBK; k++) {
            float4 a0 = *(const float4*)(ab + k * 132 + row0);
            float4 a1v = *(const float4*)(ab + k * 132 + row0 + 4);
            float4 b0 = *(const float4*)(wb + k * 256 + col0);
            float4 b1 = *(const float4*)(wb + k * 256 + col0 + 4);
            float aa[8] = {a0.x, a0.y, a0.z, a0.w, a1v.x, a1v.y, a1v.z, a1v.w};
            float bvv[8] = {b0.x, b0.y, b0.z, b0.w, b1.x, b1.y, b1.z, b1.w};
#pragma unroll
            for (int r = 0; r < 8; r++)
#pragma unroll
                for (int c = 0; c < 8; c++) acc[r][c] += aa[r] * bvv[c];
        }
        if (s + 1 < S) { STORE_ST((s + 1) & 1); __syncthreads(); }
    }

#pragma unroll
    for (int r = 0; r < 8; r++) {
        int m = r0 + row0 + r;
        long long crow = (long long)((m >> 8) * NN + cgather[m]);
        float* cp = C + crow * ldc + col0;
        float4 o0 = *(float4*)cp, o1 = *(float4*)(cp + 4);
        o0.x += acc[r][0]; o0.y += acc[r][1]; o0.z += acc[r][2]; o0.w += acc[r][3];
        o1.x += acc[r][4]; o1.y += acc[r][5]; o1.z += acc[r][6]; o1.w += acc[r][7];
        *(float4*)cp = o0; *(float4*)(cp + 4) = o1;
    }
}

// ------------------------- attention -------------------------
__global__ void attn_kernel(const float* __restrict__ qkv, float* __restrict__ out) {
    extern __shared__ float sm[];
    float* Ks = sm;
    float* Vs = sm + MSGK * HD;
    int bh = blockIdx.x;
    int b = bh >> 2;
    int h = bh & 3;
    int tid = threadIdx.x;
    const float* base = qkv + (long long)b * MSGK * 768;

    for (int t = tid; t < MSGK * HD; t += 256) {
        int j = t >> 6;
        int d = t & 63;
        Ks[t] = base[j * 768 + 256 + h * 64 + d];
        Vs[t] = base[j * 768 + 512 + h * 64 + d];
    }
    __syncthreads();

    float q[HD], o[HD];
#pragma unroll
    for (int d = 0; d < HD; d++) { q[d] = base[tid * 768 + h * 64 + d] * 0.125f; o[d] = 0.0f; }

    float mval = -1e30f, l = 0.0f;
    for (int j = 0; j < MSGK; j++) {
        float s = 0.0f;
#pragma unroll
        for (int d = 0; d < HD; d++) s += q[d] * Ks[j * 64 + d];
        float nm = fmaxf(mval, s);
        float corr = expf(mval - nm);
        float p = expf(s - nm);
        l = l * corr + p;
#pragma unroll
        for (int d = 0; d < HD; d++) o[d] = o[d] * corr + p * Vs[j * 64 + d];
        mval = nm;
    }
    float inv = 1.0f / l;
    float* op = out + ((long long)(b * MSGK + tid)) * DD + h * 64;
#pragma unroll
    for (int d = 0; d < HD; d++) op[d] = o[d] * inv;
}

// ------------------------- finalize (reconstruct newhid from fp16 planes) ----
__global__ void finalize_kernel(const float* __restrict__ newact,
                                const __half* __restrict__ n0p, const __half* __restrict__ n1p,
                                const int* __restrict__ slot2, float* __restrict__ out) {
    long long total_act = (long long)BB * NN;
    float* out_act = out;
    float* out_hid = out + total_act;
    long long stride = (long long)gridDim.x * blockDim.x;
    long long t0 = (long long)blockIdx.x * blockDim.x + threadIdx.x;

    for (long long i = t0; i < total_act; i += stride)
        out_act[i] = (slot2[i] >= 0) ? newact[i] : 0.0f;

    long long totalh4 = (long long)BB * NN * DD / 4;
    float4* oh4 = reinterpret_cast<float4*>(out_hid);
    for (long long e = t0; e < totalh4; e += stride) {
        long long r = e >> 6;
        if (slot2[r] >= 0) {
            uint2 u0 = *(const uint2*)(n0p + e * 4);
            uint2 u1 = *(const uint2*)(n1p + e * 4);
            float2 a0 = __half22float2(*(const __half2*)&u0.x);
            float2 a1 = __half22float2(*(const __half2*)&u0.y);
            float2 b0 = __half22float2(*(const __half2*)&u1.x);
            float2 b1 = __half22float2(*(const __half2*)&u1.y);
            oh4[e] = make_float4(a0.x + b0.x, a0.y + b0.y, a1.x + b1.x, a1.y + b1.y);
        } else {
            oh4[e] = make_float4(0.f, 0.f, 0.f, 0.f);
        }
    }
}

// ------------------------- host launcher -------------------------
extern "C" void kernel_launch(void* const* d_in, const int* in_sizes, int n_in,
                              void* d_out, int out_size) {
    const float* act    = (const float*)d_in[0];
    const float* hidden = (const float*)d_in[1];
    const float* in_w   = (const float*)d_in[2];
    const float* in_b   = (const float*)d_in[3];
    const float* out_w  = (const float*)d_in[4];
    const float* out_b  = (const float*)d_in[5];
    const float* su_w1  = (const float*)d_in[6];
    const float* su_b1  = (const float*)d_in[7];
    const float* su_w2  = (const float*)d_in[8];
    const float* su_b2  = (const float*)d_in[9];
    const float* au_w1  = (const float*)d_in[10];
    const float* au_b1  = (const float*)d_in[11];
    const float* au_w2  = (const float*)d_in[12];
    const float* au_b2  = (const float*)d_in[13];
    const float* ln_g   = (const float*)d_in[14];
    const float* ln_b   = (const float*)d_in[15];
    const int*   kptr   = (const int*)d_in[16];

    int*   p_tidx;   cudaGetSymbolAddress((void**)&p_tidx,   g_tidx);
    float* p_tval;   cudaGetSymbolAddress((void**)&p_tval,   g_tval);
    int*   p_slot;   cudaGetSymbolAddress((void**)&p_slot,   g_slot);
    int*   p_slot2;  cudaGetSymbolAddress((void**)&p_slot2,  g_slot2);
    float* p_qkv;    cudaGetSymbolAddress((void**)&p_qkv,    g_qkv);
    float* p_attn;   cudaGetSymbolAddress((void**)&p_attn,   g_attn);
    float* p_msg;    cudaGetSymbolAddress((void**)&p_msg,    g_msg);
    float* p_h;      cudaGetSymbolAddress((void**)&p_h,      g_h);
    float* p_newact; cudaGetSymbolAddress((void**)&p_newact, g_newact);
    float* wt_su1;   cudaGetSymbolAddress((void**)&wt_su1,   g_wt_su1);

    __half *in0,*in1, *ow0,*ow1, *s10,*s11, *s20,*s21, *a10,*a11;
    __half *h0,*h1, *n0,*n1;
    cudaGetSymbolAddress((void**)&in0, g_in0); cudaGetSymbolAddress((void**)&in1, g_in1);
    cudaGetSymbolAddress((void**)&ow0, g_ow0); cudaGetSymbolAddress((void**)&ow1, g_ow1);
    cudaGetSymbolAddress((void**)&s10, g_s10); cudaGetSymbolAddress((void**)&s11, g_s11);
    cudaGetSymbolAddress((void**)&s20, g_s20); cudaGetSymbolAddress((void**)&s21, g_s21);
    cudaGetSymbolAddress((void**)&a10, g_a10); cudaGetSymbolAddress((void**)&a11, g_a11);
    cudaGetSymbolAddress((void**)&h0, g_h0); cudaGetSymbolAddress((void**)&h1, g_h1);
    cudaGetSymbolAddress((void**)&n0, g_n0); cudaGetSymbolAddress((void**)&n1, g_n1);

    const int SMEM_GEMM2 = (2 * TBK * 132 + 2 * TBK * 256) * 4;
    const int SMEM_ATTN  = 2 * MSGK * HD * 4;

    cudaFuncSetAttribute(mma_gemm, cudaFuncAttributeMaxDynamicSharedMemorySize, TC_SMEM);
    cudaFuncSetAttribute(mma_gemm_ps, cudaFuncAttributeMaxDynamicSharedMemorySize, PS_SMEM);
    cudaFuncSetAttribute(gemm2, cudaFuncAttributeMaxDynamicSharedMemorySize, SMEM_GEMM2);
    cudaFuncSetAttribute(attn_kernel, cudaFuncAttributeMaxDynamicSharedMemorySize, SMEM_ATTN);

    // side stream + events for graph fork/join (created fresh per call; no device allocs)
    cudaStream_t s2;
    cudaStreamCreateWithFlags(&s2, cudaStreamNonBlocking);
    cudaEvent_t evF, evS, evJ;
    cudaEventCreateWithFlags(&evF, cudaEventDisableTiming);
    cudaEventCreateWithFlags(&evS, cudaEventDisableTiming);
    cudaEventCreateWithFlags(&evJ, cudaEventDisableTiming);

    // ---- fork: topk1 depends only on `act` ----
    cudaEventRecord(evF, 0);
    cudaStreamWaitEvent(s2, evF, 0);
    sort_topk_kernel<<<BB, 1024, 0, s2>>>(act, nullptr, MSGK, p_tidx, p_tval, p_slot);

    // ---- main: weight + activation prep (fp16 2-way splits) ----
    split2_kernel<<<768, 256>>>(in_w,  in0, in1, 768 * 256);
    split2_kernel<<<256, 256>>>(out_w, ow0, ow1, 256 * 256);
    split2_kernel<<<512, 256>>>(su_w1, s10, s11, 256 * 512);
    split2_kernel<<<256, 256>>>(su_w2, s20, s21, 256 * 256);
    split2_kernel<<<512, 256>>>(au_w1, a10, a11, 256 * 512);
    transpose_kernel<<<dim3(16, 8), dim3(32, 8)>>>(su_w1, wt_su1, 256, 512);
    split2_kernel<<<BB * NN * DD / 256, 256>>>(hidden, h0, h1, BB * NN * DD);
    cudaEventRecord(evS, 0);

    // ---- side stream: qkv -> attn -> out-proj (needs splits) ----
    cudaStreamWaitEvent(s2, evS, 0);
    mma_gemm_ps<<<dim3(64, 3), 512, PS_SMEM, s2>>>(
        h0, h1, nullptr, nullptr, p_tidx,
        in0, in1, 256, in_b,
        nullptr, nullptr, nullptr, nullptr,
        p_qkv, 768, 256, 256, 256, 256, 0);
    attn_kernel<<<BB * 4, 256, SMEM_ATTN, s2>>>(p_qkv, p_attn);
    mma_gemm<<<dim3(64, 1), 512, TC_SMEM, s2>>>(
        p_attn, ow0, ow1, 256, out_b,
        p_tval, nullptr, nullptr,
        p_msg, 256, nullptr, nullptr,
        256, 0, 0);
    cudaEventRecord(evJ, s2);

    // ---- main (concurrent with side stream): su1 dense ----
    mma_gemm_ps<<<dim3(1024, 1), 512, PS_SMEM>>>(
        h0, h1, nullptr, nullptr, nullptr,
        s10, s11, 512, su_b1,
        nullptr, nullptr, nullptr, nullptr,
        p_h, 256, 256, 256, 256, 256, 0);

    // ---- join, then serial tail ----
    cudaStreamWaitEvent(0, evJ, 0);

    // su1 sparse: pre[active] += msg @ W1b^T  (scalar fp32, exact)
    gemm2<<<dim3(64, 1), TTH, SMEM_GEMM2>>>(
        p_msg, wt_su1 + 256 * 256, 256, p_h, p_tidx, 256, 256);

    // su2: newhid = LN( gelu(pre) @ W2^T + b2 ) -> fp16 planes only
    mma_gemm<<<dim3(1024, 1), 512, TC_SMEM>>>(
        p_h, s20, s21, 256, su_b2,
        nullptr, ln_g, ln_b,
        nullptr, 256, n0, n1,
        256, 1, 2);

    // au1 fused act update (3-term fp16, pipelined, A = [hidden|newhid] planes)
    mma_gemm_ps<<<dim3(1024, 1), 512, PS_SMEM>>>(
        h0, h1, n0, n1, nullptr,
        a10, a11, 512, au_b1,
        au_w2, au_b2, act, p_newact,
        nullptr, 256, 256, 256, 256, 512, 3);

    // final top-k (k from device sparsity_k)
    sort_topk_kernel<<<BB, 1024>>>(p_newact, kptr, 0, nullptr, nullptr, p_slot2);

    // masked write [sparse_act | sparse_hidden] with fp16-plane reconstruction
    finalize_kernel<<<2048, 256>>>(p_newact, n0, n1, p_slot2, (float*)d_out);
}

// round 13
// speedup vs baseline: 9.3401x; 1.0760x over previous
#include <cuda_runtime.h>
#include <cuda_fp16.h>
#include <math.h>

#define BB 32
#define NN 4096
#define DD 256
#define MSGK 256
#define HD 64

// scalar gemm (sparse scatter-accum only)
#define TBM 128
#define TBK 16
#define TTH 512

// ------------------------- device scratch -------------------------
__device__ int   g_tidx[BB * MSGK];
__device__ float g_tval[BB * MSGK];
__device__ int   g_slot2[BB * NN];
__device__ float g_qkv[BB * MSGK * 3 * DD];
__device__ float g_attn[BB * MSGK * DD];
__device__ float g_msg[BB * MSGK * DD];
__device__ float g_h[(size_t)BB * NN * DD];
__device__ float g_newact[BB * NN];
__device__ float g_wt_su1[512 * 256];

// fp16 2-way splits of weights
__device__ __half g_in0[768*256],  g_in1[768*256];
__device__ __half g_ow0[256*256],  g_ow1[256*256];
__device__ __half g_s10[256*512],  g_s11[256*512];
__device__ __half g_s20[256*256],  g_s21[256*256];
__device__ __half g_a10[256*512],  g_a11[256*512];

// fp16 2-way splits of activations
__device__ __half g_h0[(size_t)BB*NN*DD], g_h1[(size_t)BB*NN*DD];
__device__ __half g_n0[(size_t)BB*NN*DD], g_n1[(size_t)BB*NN*DD];

__device__ __forceinline__ float gelu_f(float x) {
    return 0.5f * x * (1.0f + erff(x * 0.70710678118654752440f));
}

__device__ __forceinline__ unsigned smem_u32(const void* p) {
    unsigned a;
    asm("{ .reg .u64 t; cvta.to.shared.u64 t, %1; cvt.u32.u64 %0, t; }" : "=r"(a) : "l"(p));
    return a;
}

__device__ __forceinline__ void ldsm4(unsigned& r0, unsigned& r1, unsigned& r2, unsigned& r3,
                                      unsigned addr) {
    asm volatile("ldmatrix.sync.aligned.m8n8.x4.shared.b16 {%0,%1,%2,%3}, [%4];"
                 : "=r"(r0), "=r"(r1), "=r"(r2), "=r"(r3) : "r"(addr));
}

__device__ __forceinline__ void mma_f16(float* c, unsigned a0, unsigned a1, unsigned a2,
                                        unsigned a3, unsigned b0, unsigned b1) {
    asm volatile("mma.sync.aligned.m16n8k16.row.col.f32.f16.f16.f32 "
                 "{%0,%1,%2,%3},{%4,%5,%6,%7},{%8,%9},{%0,%1,%2,%3};"
                 : "+f"(c[0]), "+f"(c[1]), "+f"(c[2]), "+f"(c[3])
                 : "r"(a0), "r"(a1), "r"(a2), "r"(a3), "r"(b0), "r"(b1));
}

#define CPASYNC16(dst, src) \
    asm volatile("cp.async.cg.shared.global [%0], [%1], 16;" :: "r"(dst), "l"(src) : "memory")
#define CPCOMMIT() asm volatile("cp.async.commit_group;" ::: "memory")
#define CPWAIT0() asm volatile("cp.async.wait_group 0;" ::: "memory")
#define CPWAIT1() asm volatile("cp.async.wait_group 1;" ::: "memory")

__device__ __forceinline__ unsigned short hbits(__half h) {
    return *(unsigned short*)&h;
}

// ------------------------- merged weight split (fp16 2-way) -------------------
#define SZ_IN  196608
#define SZ_OW  65536
#define SZ_S1  131072
#define SZ_S2  65536
#define SZ_A1  131072
#define SZ_TOT (SZ_IN + SZ_OW + SZ_S1 + SZ_S2 + SZ_A1)   // 589824

__global__ void split_weights_kernel(
    const float* __restrict__ in_w, const float* __restrict__ out_w,
    const float* __restrict__ su_w1, const float* __restrict__ su_w2,
    const float* __restrict__ au_w1,
    __half* in0, __half* in1, __half* ow0, __half* ow1,
    __half* s10, __half* s11, __half* s20, __half* s21,
    __half* a10, __half* a11) {
    int i = blockIdx.x * 256 + threadIdx.x;
    const float* src; __half *d0, *d1; int off;
    if (i < SZ_IN)                          { src = in_w;  d0 = in0; d1 = in1; off = i; }
    else if (i < SZ_IN+SZ_OW)               { src = out_w; d0 = ow0; d1 = ow1; off = i - SZ_IN; }
    else if (i < SZ_IN+SZ_OW+SZ_S1)         { src = su_w1; d0 = s10; d1 = s11; off = i - SZ_IN - SZ_OW; }
    else if (i < SZ_IN+SZ_OW+SZ_S1+SZ_S2)   { src = su_w2; d0 = s20; d1 = s21; off = i - SZ_IN - SZ_OW - SZ_S1; }
    else if (i < SZ_TOT)                    { src = au_w1; d0 = a10; d1 = a11; off = i - SZ_IN - SZ_OW - SZ_S1 - SZ_S2; }
    else return;
    float v = src[off];
    __half a = __float2half_rn(v);
    d0[off] = a;
    d1[off] = __float2half_rn(v - __half2float(a));
}

// ------------------------- vectorized activation split (x8) -------------------
__global__ void split2v_kernel(const float* __restrict__ W, __half* o0, __half* o1) {
    long long i = ((long long)blockIdx.x * 256 + threadIdx.x) * 8;
    float4 v0 = *(const float4*)(W + i);
    float4 v1 = *(const float4*)(W + i + 4);
    float v[8] = {v0.x, v0.y, v0.z, v0.w, v1.x, v1.y, v1.z, v1.w};
    unsigned short p0[8], p1[8];
#pragma unroll
    for (int j = 0; j < 8; j++) {
        __half a = __float2half_rn(v[j]);
        p0[j] = hbits(a);
        p1[j] = hbits(__float2half_rn(v[j] - __half2float(a)));
    }
    uint4 u0 = make_uint4(((unsigned)p0[1]<<16)|p0[0], ((unsigned)p0[3]<<16)|p0[2],
                          ((unsigned)p0[5]<<16)|p0[4], ((unsigned)p0[7]<<16)|p0[6]);
    uint4 u1 = make_uint4(((unsigned)p1[1]<<16)|p1[0], ((unsigned)p1[3]<<16)|p1[2],
                          ((unsigned)p1[5]<<16)|p1[4], ((unsigned)p1[7]<<16)|p1[6]);
    *(uint4*)(o0 + i) = u0;
    *(uint4*)(o1 + i) = u1;
}

// ------------------------- weight transpose (scalar scatter gemm) ------------
__global__ void transpose_kernel(const float* __restrict__ W, float* __restrict__ Wt,
                                 int Nout, int Kd) {
    __shared__ float t[32][33];
    int k0 = blockIdx.x * 32, n0 = blockIdx.y * 32;
    int tx = threadIdx.x, ty = threadIdx.y;
#pragma unroll
    for (int i = 0; i < 32; i += 8)
        t[ty + i][tx] = W[(long long)(n0 + ty + i) * Kd + k0 + tx];
    __syncthreads();
#pragma unroll
    for (int i = 0; i < 32; i += 8)
        Wt[(long long)(k0 + ty + i) * Nout + n0 + tx] = t[tx][ty + i];
}

// ------------------------- radix-select top-k -------------------------
// One block per batch row, 256 threads. Non-negative floats -> bit-monotonic.
// Finds exact k-th threshold in 4 byte passes over smem-cached bits, then
// marks membership (slotmap: 0 / -1) and/or compacts (idx,val) in any order
// (order-free: scatter targets are unique; GEMM rowscale pairs with compaction).
__global__ void radix_topk_kernel(const float* __restrict__ act,
                                  const int* __restrict__ kptr, int kconst,
                                  int* __restrict__ idx_out, float* __restrict__ val_out,
                                  int* __restrict__ slotmap) {
    __shared__ unsigned bits[NN];   // 16 KB
    __shared__ unsigned hist[256];
    __shared__ unsigned s_sel[2];   // [0]=bin, [1]=count-above
    __shared__ int s_cnt;
    int b = blockIdx.x;
    int tid = threadIdx.x;          // 256
    int kk = kptr ? *kptr : kconst;
    if (kk > NN) kk = NN;
    if (kk < 0) kk = 0;

    const float* row = act + b * NN;
    for (int i = tid; i < NN; i += 256) bits[i] = __float_as_uint(row[i]);

    if (kk == 0) {
        if (slotmap) for (int i = tid; i < NN; i += 256) slotmap[b * NN + i] = -1;
        return;
    }
    __syncthreads();

    unsigned need = (unsigned)kk;
    unsigned prefix = 0;
    unsigned lastE = 0;
    for (int pass = 3; pass >= 0; pass--) {
        hist[tid] = 0;
        __syncthreads();
        int sh = pass * 8;
        for (int i = tid; i < NN; i += 256) {
            unsigned ub = bits[i];
            if ((pass == 3) || ((ub >> (sh + 8)) == prefix))
                atomicAdd(&hist[(ub >> sh) & 255], 1u);
        }
        __syncthreads();
        if (tid == 0) {
            unsigned cum = 0;
            int bsel = 0;
            for (int bin2 = 255; bin2 >= 0; bin2--) {
                unsigned c = hist[bin2];
                if (cum + c >= need) { bsel = bin2; break; }
                cum += c;
            }
            s_sel[0] = (unsigned)bsel;
            s_sel[1] = cum;
        }
        __syncthreads();
        lastE = hist[s_sel[0]];
        need -= s_sel[1];
        prefix = (prefix << 8) | s_sel[0];
        __syncthreads();
    }
    unsigned thr = prefix;
    bool exactAll = (lastE == need);   // all threshold-equal values fit exactly

    if (tid == 0) s_cnt = 0;
    __syncthreads();
    for (int i = tid; i < NN; i += 256) {
        unsigned ub = bits[i];
        bool in = (ub > thr) || (exactAll && ub == thr);
        if (slotmap) slotmap[b * NN + i] = in ? 0 : -1;
        if (in && idx_out) {
            int s = atomicAdd(&s_cnt, 1);
            idx_out[b * kk + s] = i;
            val_out[b * kk + s] = row[i];
        }
    }
    if (!exactAll) {
        // rare duplicate-threshold path: deterministic first-index tie-break
        __syncthreads();
        if (tid == 0) {
            int take = (int)need;
            for (int i = 0; i < NN && take > 0; i++) {
                if (bits[i] == thr) {
                    if (slotmap) slotmap[b * NN + i] = 0;
                    if (idx_out) {
                        int s = s_cnt++;
                        idx_out[b * kk + s] = i;
                        val_out[b * kk + s] = row[i];
                    }
                    take--;
                }
            }
        }
    }
}

// ======================= pre-split pipelined tensor GEMM (fp16, 3-term) =======
#define PS_AP 8192
#define PS_BOFF 16384
#define PS_BP 16384
#define PS_STAGE 49152
#define PS_SMEM (2 * PS_STAGE)   // 98304

__global__ __launch_bounds__(512, 1)
void mma_gemm_ps(const __half* __restrict__ A0, const __half* __restrict__ A1p,
                 const __half* __restrict__ Z0, const __half* __restrict__ Z1,
                 const int* __restrict__ gather,
                 const __half* __restrict__ W0, const __half* __restrict__ W1, int ldw,
                 const float* __restrict__ bias,
                 const float* __restrict__ w2, const float* __restrict__ b2,
                 const float* __restrict__ act_in, float* __restrict__ act_out,
                 float* __restrict__ C, int ldc,
                 int K1, int lda1, int lda2, int Ktot, int mode) {
    extern __shared__ char smem[];
    unsigned sbase = smem_u32(smem);
    int tid = threadIdx.x;
    int lane = tid & 31;
    int wid = tid >> 5;
    int wm = wid & 3;
    int wn = wid >> 2;
    int r0 = blockIdx.x * 128;
    int colbase = blockIdx.y * 256;

    // ---- staging maps ----
    int arow = tid >> 2, au = tid & 3;
    int m_a = r0 + arow;
    long long ridx1 = gather ? (long long)((m_a >> 8) * NN + gather[m_a]) : m_a;
    const char* a1b0 = (const char*)(A0 + ridx1 * lda1);
    const char* a1b1 = (const char*)(A1p + ridx1 * lda1);
    const char* a2b0 = Z0 ? (const char*)(Z0 + (long long)m_a * lda2) : a1b0;
    const char* a2b1 = Z1 ? (const char*)(Z1 + (long long)m_a * lda2) : a1b1;
    unsigned aswz = ((arow >> 1) & 3) << 4;
    unsigned adst0 = (unsigned)arow * 64 + ((au * 16) ^ aswz);

    int bn = tid >> 1;
    int bu0 = (tid & 1) * 2;
    unsigned bswz = ((bn >> 1) & 3) << 4;
    long long brow = (long long)(colbase + bn) * ldw;

    const int ta3[3] = {0, 0, 1};
    const int tb3[3] = {0, 1, 0};

    // ---- mma fragment addressing ----
    int a_r = wm * 32 + (lane & 15);
    unsigned a_k0 = (unsigned)((lane >> 4) << 4);
    unsigned a_sw = ((a_r >> 1) & 3) << 4;
    int b_g = lane >> 3, b_r = lane & 7;
    int b_n0 = wn * 64 + ((b_g >> 1) << 3) + b_r;
    unsigned b_k0 = (unsigned)((b_g & 1) << 4);

    float acc[2][8][4];
#pragma unroll
    for (int mt = 0; mt < 2; mt++)
#pragma unroll
        for (int nt = 0; nt < 8; nt++)
#pragma unroll
            for (int c = 0; c < 4; c++) acc[mt][nt][c] = 0.0f;

    int nc = Ktot >> 5;

#define PS_STAGE_FN(c_) do {                                                   \
        int buf_ = (c_) & 1;                                                   \
        unsigned stg_ = sbase + buf_ * PS_STAGE;                               \
        int kc_ = (c_) << 5;                                                   \
        const char *p0_, *p1_; long long ko_;                                  \
        if (kc_ < K1) { p0_ = a1b0; p1_ = a1b1; ko_ = kc_; }                   \
        else          { p0_ = a2b0; p1_ = a2b1; ko_ = kc_ - K1; }              \
        long long ab_ = ko_ * 2 + au * 16;                                     \
        unsigned ad_ = stg_ + adst0;                                           \
        CPASYNC16(ad_, p0_ + ab_);                                             \
        CPASYNC16(ad_ + PS_AP, p1_ + ab_);                                     \
        long long bo_ = (brow + kc_) * 2;                                      \
        unsigned bd_ = stg_ + PS_BOFF + (unsigned)bn * 64;                     \
        unsigned k0_ = (unsigned)(bu0 * 16), k1_ = k0_ + 16;                   \
        CPASYNC16(bd_ + (k0_ ^ bswz), (const char*)W0 + bo_ + k0_);            \
        CPASYNC16(bd_ + (k1_ ^ bswz), (const char*)W0 + bo_ + k1_);            \
        CPASYNC16(bd_ + PS_BP + (k0_ ^ bswz), (const char*)W1 + bo_ + k0_);    \
        CPASYNC16(bd_ + PS_BP + (k1_ ^ bswz), (const char*)W1 + bo_ + k1_);    \
    } while (0)

    PS_STAGE_FN(0);
    CPCOMMIT();

    for (int c = 0; c < nc; c++) {
        if (c + 1 < nc) { PS_STAGE_FN(c + 1); CPCOMMIT(); CPWAIT1(); }
        else            { CPWAIT0(); }
        __syncthreads();

        unsigned stg = sbase + (c & 1) * PS_STAGE;
#pragma unroll
        for (int p = 0; p < 3; p++) {
            unsigned Ab = stg + ta3[p] * PS_AP;
            unsigned Bb = stg + PS_BOFF + tb3[p] * PS_BP;
#pragma unroll
            for (int ks = 0; ks < 2; ks++) {
                unsigned akb = ((unsigned)(ks << 5) + a_k0) ^ a_sw;
                unsigned a0[4], a1r[4];
                ldsm4(a0[0], a0[1], a0[2], a0[3], Ab + (unsigned)a_r * 64 + akb);
                ldsm4(a1r[0], a1r[1], a1r[2], a1r[3], Ab + (unsigned)(a_r + 16) * 64 + akb);
#pragma unroll
                for (int np = 0; np < 4; np++) {
                    int n = b_n0 + np * 16;
                    unsigned bkb = ((unsigned)(ks << 5) + b_k0) ^ (unsigned)(((n >> 1) & 3) << 4);
                    unsigned b0, b1, b2, b3;
                    ldsm4(b0, b1, b2, b3, Bb + (unsigned)n * 64 + bkb);
                    mma_f16(acc[0][2*np],   a0[0], a0[1], a0[2], a0[3], b0, b1);
                    mma_f16(acc[0][2*np+1], a0[0], a0[1], a0[2], a0[3], b2, b3);
                    mma_f16(acc[1][2*np],   a1r[0], a1r[1], a1r[2], a1r[3], b0, b1);
                    mma_f16(acc[1][2*np+1], a1r[0], a1r[1], a1r[2], a1r[3], b2, b3);
                }
            }
        }
        __syncthreads();
    }

    // ---------------- epilogue ----------------
    int qd = lane & 3;
    int rql = lane >> 2;
    float bv[16];
#pragma unroll
    for (int nt = 0; nt < 8; nt++) {
        int cg = colbase + wn * 64 + nt * 8 + 2 * qd;
        float2 t2 = *(const float2*)(bias + cg);
        bv[2*nt] = t2.x; bv[2*nt+1] = t2.y;
    }

    if (mode == 0) {
#pragma unroll
        for (int mt = 0; mt < 2; mt++)
#pragma unroll
            for (int hf = 0; hf < 2; hf++) {
                int m = r0 + wm * 32 + mt * 16 + rql + hf * 8;
#pragma unroll
                for (int nt = 0; nt < 8; nt++) {
                    int cg = colbase + wn * 64 + nt * 8 + 2 * qd;
                    float2 o;
                    o.x = acc[mt][nt][2*hf]   + bv[2*nt];
                    o.y = acc[mt][nt][2*hf+1] + bv[2*nt+1];
                    *(float2*)(C + (long long)m * ldc + cg) = o;
                }
            }
        return;
    }

    // mode 3: gelu + dot(w2) + sigmoid blend
    {
        float* red = (float*)smem;
        float wv[16];
#pragma unroll
        for (int nt = 0; nt < 8; nt++) {
            int cg = wn * 64 + nt * 8 + 2 * qd;
            float2 tw = *(const float2*)(w2 + cg);
            wv[2*nt] = tw.x; wv[2*nt+1] = tw.y;
        }
#pragma unroll
        for (int mt = 0; mt < 2; mt++)
#pragma unroll
            for (int hf = 0; hf < 2; hf++) {
                float d = 0.0f;
#pragma unroll
                for (int nt = 0; nt < 8; nt++) {
                    float f0 = gelu_f(acc[mt][nt][2*hf]   + bv[2*nt]);
                    float f1 = gelu_f(acc[mt][nt][2*hf+1] + bv[2*nt+1]);
                    d += f0 * wv[2*nt] + f1 * wv[2*nt+1];
                }
                d += __shfl_xor_sync(0xffffffffu, d, 1);
                d += __shfl_xor_sync(0xffffffffu, d, 2);
                if (qd == 0) {
                    int rl = wm * 32 + mt * 16 + rql + hf * 8;
                    red[rl * 4 + wn] = d;
                }
            }
        __syncthreads();
        if (tid < 128) {
            float d = red[tid*4] + red[tid*4+1] + red[tid*4+2] + red[tid*4+3];
            float dl = 1.0f / (1.0f + expf(-(d + b2[0])));
            int m = r0 + tid;
            float na = 0.7f * act_in[m] + 0.3f * dl;
            na = fminf(fmaxf(na, 0.0f), 1.0f);
            act_out[m] = na;
        }
    }
}

// ======================= convert-path tensor GEMM (fp32 A, fp16 3-term) =======
#define A_TERM 16384
#define B_TERM 32768
#define BB_OFF (2 * A_TERM)
#define TC_SMEM (2 * A_TERM + 2 * B_TERM)   // 98304

__global__ __launch_bounds__(512, 1)
void mma_gemm(const float* __restrict__ A1,
              const __half* __restrict__ W0, const __half* __restrict__ W1, int ldw,
              const float* __restrict__ bias,
              const float* __restrict__ rowscale,
              const float* __restrict__ lng, const float* __restrict__ lnb,
              float* __restrict__ C, int ldc,
              __half* __restrict__ n0p, __half* __restrict__ n1p,
              int Ktot, int a1_gelu, int mode) {
    extern __shared__ char smem[];
    unsigned sbase = smem_u32(smem);
    int tid = threadIdx.x;
    int lane = tid & 31;
    int wid = tid >> 5;
    int wm = wid & 3;
    int wn = wid >> 2;
    int r0 = blockIdx.x * 128;
    int colbase = blockIdx.y * 256;

    int s_arow = tid >> 2;
    int s_aq   = tid & 3;
    int m_a = r0 + s_arow;
    const float* a1p = A1 + (long long)m_a * Ktot;

    int s_bn = tid >> 1;
    int s_bh = tid & 1;
    long long bro = (long long)(colbase + s_bn) * ldw;

    const int ta3[3] = {0, 0, 1};
    const int tb3[3] = {0, 1, 0};

    int a_r = wm * 32 + (lane & 15);
    unsigned a_sw = (unsigned)((a_r & 7) << 4);
    unsigned a_kb0 = (unsigned)((lane >> 4) << 4);
    int b_g = lane >> 3, b_r = lane & 7;
    unsigned b_kb0 = (unsigned)((b_g & 1) << 4);

    float acc[2][8][4];
#pragma unroll
    for (int mt = 0; mt < 2; mt++)
#pragma unroll
        for (int nt = 0; nt < 8; nt++)
#pragma unroll
            for (int c = 0; c < 4; c++) acc[mt][nt][c] = 0.0f;

    int nchunks = Ktot >> 6;
    for (int ch = 0; ch < nchunks; ch++) {
        int kc = ch << 6;
        {
            const float* src = a1p + kc + s_aq * 16;
            float v[16];
#pragma unroll
            for (int j = 0; j < 4; j++) {
                float4 t4 = *(const float4*)(src + j * 4);
                v[j*4+0] = t4.x; v[j*4+1] = t4.y; v[j*4+2] = t4.z; v[j*4+3] = t4.w;
            }
            if (a1_gelu) {
#pragma unroll
                for (int j = 0; j < 16; j++) v[j] = gelu_f(v[j]);
            }
            unsigned u0[8], u1[8];
#pragma unroll
            for (int j = 0; j < 8; j++) {
                float x = v[2*j], y = v[2*j+1];
                __half hx0 = __float2half_rn(x);
                __half hy0 = __float2half_rn(y);
                __half hx1 = __float2half_rn(x - __half2float(hx0));
                __half hy1 = __float2half_rn(y - __half2float(hy0));
                u0[j] = ((unsigned)hbits(hy0) << 16) | hbits(hx0);
                u1[j] = ((unsigned)hbits(hy1) << 16) | hbits(hx1);
            }
            unsigned rsw = (unsigned)((s_arow & 7) << 4);
            unsigned rb = (unsigned)s_arow * 128;
#pragma unroll
            for (int j8 = 0; j8 < 4; j8++) {
                unsigned kb = (unsigned)(s_aq * 32 + j8 * 8) ^ rsw;
                *(uint2*)(smem + rb + kb) = make_uint2(u0[2*j8], u0[2*j8+1]);
                *(uint2*)(smem + A_TERM + rb + kb) = make_uint2(u1[2*j8], u1[2*j8+1]);
            }
        }
        {
            unsigned nsw = (unsigned)((s_bn & 7) << 4);
            unsigned nb = (unsigned)s_bn * 128;
            long long goff = (bro + kc) * 2;
#pragma unroll
            for (int w = 0; w < 2; w++) {
                const char* Wsrc = (const char*)((w == 0) ? W0 : W1);
#pragma unroll
                for (int i = 0; i < 4; i++) {
                    unsigned kb = (unsigned)(s_bh * 64 + i * 16);
                    CPASYNC16(sbase + BB_OFF + w * B_TERM + nb + (kb ^ nsw), Wsrc + goff + kb);
                }
            }
        }
        CPCOMMIT();
        CPWAIT0();
        __syncthreads();

#pragma unroll
        for (int p = 0; p < 3; p++) {
            unsigned Ab = sbase + ta3[p] * A_TERM;
            unsigned Bb = sbase + BB_OFF + tb3[p] * B_TERM;
#pragma unroll
            for (int ks = 0; ks < 4; ks++) {
                unsigned a0[4], a1r[4];
                unsigned akb = ((unsigned)(ks * 32) + a_kb0) ^ a_sw;
                ldsm4(a0[0], a0[1], a0[2], a0[3], Ab + (unsigned)a_r * 128 + akb);
                ldsm4(a1r[0], a1r[1], a1r[2], a1r[3], Ab + (unsigned)(a_r + 16) * 128 + akb);
#pragma unroll
                for (int np = 0; np < 4; np++) {
                    int n = wn * 64 + np * 16 + ((b_g >> 1) << 3) + b_r;
                    unsigned bkb = ((unsigned)(ks * 32) + b_kb0) ^ (unsigned)((n & 7) << 4);
                    unsigned b0, b1, b2, b3;
                    ldsm4(b0, b1, b2, b3, Bb + (unsigned)n * 128 + bkb);
                    mma_f16(acc[0][2*np],   a0[0], a0[1], a0[2], a0[3], b0, b1);
                    mma_f16(acc[0][2*np+1], a0[0], a0[1], a0[2], a0[3], b2, b3);
                    mma_f16(acc[1][2*np],   a1r[0], a1r[1], a1r[2], a1r[3], b0, b1);
                    mma_f16(acc[1][2*np+1], a1r[0], a1r[1], a1r[2], a1r[3], b2, b3);
                }
            }
        }
        __syncthreads();
    }

    int qd = lane & 3;
    int rql = lane >> 2;
    float bv[16];
#pragma unroll
    for (int nt = 0; nt < 8; nt++) {
        int cg = colbase + wn * 64 + nt * 8 + 2 * qd;
        float2 t2 = *(const float2*)(bias + cg);
        bv[2*nt] = t2.x; bv[2*nt+1] = t2.y;
    }

    if (mode == 0) {
#pragma unroll
        for (int mt = 0; mt < 2; mt++)
#pragma unroll
            for (int hf = 0; hf < 2; hf++) {
                int m = r0 + wm * 32 + mt * 16 + rql + hf * 8;
                float sc = rowscale ? rowscale[m] : 1.0f;
#pragma unroll
                for (int nt = 0; nt < 8; nt++) {
                    int cg = colbase + wn * 64 + nt * 8 + 2 * qd;
                    float2 o;
                    o.x = (acc[mt][nt][2*hf]   + bv[2*nt])   * sc;
                    o.y = (acc[mt][nt][2*hf+1] + bv[2*nt+1]) * sc;
                    *(float2*)(C + (long long)m * ldc + cg) = o;
                }
            }
        return;
    }

    // mode 2: layernorm -> fp16 plane outputs (fp32 store optional via C)
    float* red = (float*)smem;
    float* red2 = red + 512;
#pragma unroll
    for (int mt = 0; mt < 2; mt++)
#pragma unroll
        for (int hf = 0; hf < 2; hf++) {
            float s = 0.0f, sq = 0.0f;
#pragma unroll
            for (int nt = 0; nt < 8; nt++) {
                float f0 = acc[mt][nt][2*hf]   + bv[2*nt];
                float f1 = acc[mt][nt][2*hf+1] + bv[2*nt+1];
                s += f0 + f1; sq += f0 * f0 + f1 * f1;
            }
            s  += __shfl_xor_sync(0xffffffffu, s, 1);
            s  += __shfl_xor_sync(0xffffffffu, s, 2);
            sq += __shfl_xor_sync(0xffffffffu, sq, 1);
            sq += __shfl_xor_sync(0xffffffffu, sq, 2);
            if (qd == 0) {
                int rl = wm * 32 + mt * 16 + rql + hf * 8;
                red[rl * 4 + wn] = s;
                red2[rl * 4 + wn] = sq;
            }
        }
    __syncthreads();
    float* stats = red2 + 512;
    if (tid < 128) {
        float s = red[tid*4] + red[tid*4+1] + red[tid*4+2] + red[tid*4+3];
        float sq = red2[tid*4] + red2[tid*4+1] + red2[tid*4+2] + red2[tid*4+3];
        float mu = s * (1.0f / 256.0f);
        float var = sq * (1.0f / 256.0f) - mu * mu;
        stats[tid*2] = mu;
        stats[tid*2+1] = rsqrtf(var + 1e-5f);
    }
    __syncthreads();
    float gv[16], ev[16];
#pragma unroll
    for (int nt = 0; nt < 8; nt++) {
        int cg = wn * 64 + nt * 8 + 2 * qd;
        float2 tg = *(const float2*)(lng + cg);
        float2 te = *(const float2*)(lnb + cg);
        gv[2*nt] = tg.x; gv[2*nt+1] = tg.y;
        ev[2*nt] = te.x; ev[2*nt+1] = te.y;
    }
#pragma unroll
    for (int mt = 0; mt < 2; mt++)
#pragma unroll
        for (int hf = 0; hf < 2; hf++) {
            int rl = wm * 32 + mt * 16 + rql + hf * 8;
            int m = r0 + rl;
            float mu = stats[rl*2], inv = stats[rl*2+1];
#pragma unroll
            for (int nt = 0; nt < 8; nt++) {
                int cg = wn * 64 + nt * 8 + 2 * qd;
                float2 o;
                float f0 = acc[mt][nt][2*hf]   + bv[2*nt];
                float f1 = acc[mt][nt][2*hf+1] + bv[2*nt+1];
                o.x = (f0 - mu) * inv * gv[2*nt]   + ev[2*nt];
                o.y = (f1 - mu) * inv * gv[2*nt+1] + ev[2*nt+1];
                if (C) *(float2*)(C + (long long)m * ldc + cg) = o;
                {
                    long long e = (long long)m * 256 + cg;
                    __half x0 = __float2half_rn(o.x);
                    __half x1 = __float2half_rn(o.x - __half2float(x0));
                    __half y0 = __float2half_rn(o.y);
                    __half y1 = __float2half_rn(o.y - __half2float(y0));
                    *(unsigned*)(n0p + e) = ((unsigned)hbits(y0) << 16) | hbits(x0);
                    *(unsigned*)(n1p + e) = ((unsigned)hbits(y1) << 16) | hbits(x1);
                }
            }
        }
}

// ------------------------- scalar GEMM (sparse scatter-accum) --------
__global__ __launch_bounds__(TTH, 1)
void gemm2(const float* __restrict__ A1,
           const float* __restrict__ Wt, int ldw,
           float* __restrict__ C, const int* __restrict__ cgather, int ldc,
           int Ktot) {
    extern __shared__ float sm[];
    float* As = sm;
    float* Ws = sm + 2 * TBK * 132;

    int tid = threadIdx.x;
    int r0 = blockIdx.x * TBM;

    int am = tid >> 2;
    int ak = (tid & 3) << 2;
    int m_a = r0 + am;
    const float* a1row = A1 + (long long)m_a * Ktot;

    int wr = tid >> 5;
    int wc = (tid & 31) << 3;
    const float* wbase = Wt + (long long)wr * ldw + wc;

    float4 av, wv0, wv1;
#define LOAD_ST(kb) do {                                                      \
        av = *(const float4*)(a1row + (kb) + ak);                             \
        const float* wp_ = wbase + (long long)(kb) * ldw;                     \
        wv0 = *(const float4*)(wp_);                                          \
        wv1 = *(const float4*)(wp_ + 4);                                      \
    } while (0)
#define STORE_ST(buf) do {                                                    \
        float* ap_ = As + (buf) * (TBK * 132);                                \
        ap_[(ak + 0) * 132 + am] = av.x;                                      \
        ap_[(ak + 1) * 132 + am] = av.y;                                      \
        ap_[(ak + 2) * 132 + am] = av.z;                                      \
        ap_[(ak + 3) * 132 + am] = av.w;                                      \
        float* wpS_ = Ws + (buf) * (TBK * 256) + wr * 256 + wc;               \
        *(float4*)wpS_ = wv0;                                                 \
        *(float4*)(wpS_ + 4) = wv1;                                           \
    } while (0)

    int lane = tid & 31, warp = tid >> 5;
    int row0 = warp << 3, col0 = lane << 3;

    float acc[8][8];
#pragma unroll
    for (int r = 0; r < 8; r++)
#pragma unroll
        for (int c = 0; c < 8; c++) acc[r][c] = 0.0f;

    LOAD_ST(0); STORE_ST(0);
    __syncthreads();

    int S = Ktot / TBK;
    for (int s = 0; s < S; s++) {
        int cur = s & 1;
        if (s + 1 < S) LOAD_ST((s + 1) * TBK);
        const float* ab = As + cur * (TBK * 132);
        const float* wb = Ws + cur * (TBK * 256);
#pragma unroll
        for (int k = 0; k < TBK; k++) {
            float4 a0 = *(const float4*)(ab + k * 132 + row0);
            float4 a1v = *(const float4*)(ab + k * 132 + row0 + 4);
            float4 b0 = *(const float4*)(wb + k * 256 + col0);
            float4 b1 = *(const float4*)(wb + k * 256 + col0 + 4);
            float aa[8] = {a0.x, a0.y, a0.z, a0.w, a1v.x, a1v.y, a1v.z, a1v.w};
            float bvv[8] = {b0.x, b0.y, b0.z, b0.w, b1.x, b1.y, b1.z, b1.w};
#pragma unroll
            for (int r = 0; r < 8; r++)
#pragma unroll
                for (int c = 0; c < 8; c++) acc[r][c] += aa[r] * bvv[c];
        }
        if (s + 1 < S) { STORE_ST((s + 1) & 1); __syncthreads(); }
    }

#pragma unroll
    for (int r = 0; r < 8; r++) {
        int m = r0 + row0 + r;
        long long crow = (long long)((m >> 8) * NN + cgather[m]);
        float* cp = C + crow * ldc + col0;
        float4 o0 = *(float4*)cp, o1 = *(float4*)(cp + 4);
        o0.x += acc[r][0]; o0.y += acc[r][1]; o0.z += acc[r][2]; o0.w += acc[r][3];
        o1.x += acc[r][4]; o1.y += acc[r][5]; o1.z += acc[r][6]; o1.w += acc[r][7];
        *(float4*)cp = o0; *(float4*)(cp + 4) = o1;
    }
}

// ------------------------- attention -------------------------
__global__ void attn_kernel(const float* __restrict__ qkv, float* __restrict__ out) {
    extern __shared__ float sm[];
    float* Ks = sm;
    float* Vs = sm + MSGK * HD;
    int bh = blockIdx.x;
    int b = bh >> 2;
    int h = bh & 3;
    int tid = threadIdx.x;
    const float* base = qkv + (long long)b * MSGK * 768;

    for (int t = tid; t < MSGK * HD; t += 256) {
        int j = t >> 6;
        int d = t & 63;
        Ks[t] = base[j * 768 + 256 + h * 64 + d];
        Vs[t] = base[j * 768 + 512 + h * 64 + d];
    }
    __syncthreads();

    float q[HD], o[HD];
#pragma unroll
    for (int d = 0; d < HD; d++) { q[d] = base[tid * 768 + h * 64 + d] * 0.125f; o[d] = 0.0f; }

    float mval = -1e30f, l = 0.0f;
    for (int j = 0; j < MSGK; j++) {
        float s = 0.0f;
#pragma unroll
        for (int d = 0; d < HD; d++) s += q[d] * Ks[j * 64 + d];
        float nm = fmaxf(mval, s);
        float corr = expf(mval - nm);
        float p = expf(s - nm);
        l = l * corr + p;
#pragma unroll
        for (int d = 0; d < HD; d++) o[d] = o[d] * corr + p * Vs[j * 64 + d];
        mval = nm;
    }
    float inv = 1.0f / l;
    float* op = out + ((long long)(b * MSGK + tid)) * DD + h * 64;
#pragma unroll
    for (int d = 0; d < HD; d++) op[d] = o[d] * inv;
}

// ------------------------- finalize (reconstruct newhid from fp16 planes) ----
__global__ void finalize_kernel(const float* __restrict__ newact,
                                const __half* __restrict__ n0p, const __half* __restrict__ n1p,
                                const int* __restrict__ slot2, float* __restrict__ out) {
    long long total_act = (long long)BB * NN;
    float* out_act = out;
    float* out_hid = out + total_act;
    long long stride = (long long)gridDim.x * blockDim.x;
    long long t0 = (long long)blockIdx.x * blockDim.x + threadIdx.x;

    for (long long i = t0; i < total_act; i += stride)
        out_act[i] = (slot2[i] >= 0) ? newact[i] : 0.0f;

    long long totalh4 = (long long)BB * NN * DD / 4;
    float4* oh4 = reinterpret_cast<float4*>(out_hid);
    for (long long e = t0; e < totalh4; e += stride) {
        long long r = e >> 6;
        if (slot2[r] >= 0) {
            uint2 u0 = *(const uint2*)(n0p + e * 4);
            uint2 u1 = *(const uint2*)(n1p + e * 4);
            float2 a0 = __half22float2(*(const __half2*)&u0.x);
            float2 a1 = __half22float2(*(const __half2*)&u0.y);
            float2 b0 = __half22float2(*(const __half2*)&u1.x);
            float2 b1 = __half22float2(*(const __half2*)&u1.y);
            oh4[e] = make_float4(a0.x + b0.x, a0.y + b0.y, a1.x + b1.x, a1.y + b1.y);
        } else {
            oh4[e] = make_float4(0.f, 0.f, 0.f, 0.f);
        }
    }
}

// ------------------------- host launcher -------------------------
extern "C" void kernel_launch(void* const* d_in, const int* in_sizes, int n_in,
                              void* d_out, int out_size) {
    const float* act    = (const float*)d_in[0];
    const float* hidden = (const float*)d_in[1];
    const float* in_w   = (const float*)d_in[2];
    const float* in_b   = (const float*)d_in[3];
    const float* out_w  = (const float*)d_in[4];
    const float* out_b  = (const float*)d_in[5];
    const float* su_w1  = (const float*)d_in[6];
    const float* su_b1  = (const float*)d_in[7];
    const float* su_w2  = (const float*)d_in[8];
    const float* su_b2  = (const float*)d_in[9];
    const float* au_w1  = (const float*)d_in[10];
    const float* au_b1  = (const float*)d_in[11];
    const float* au_w2  = (const float*)d_in[12];
    const float* au_b2  = (const float*)d_in[13];
    const float* ln_g   = (const float*)d_in[14];
    const float* ln_b   = (const float*)d_in[15];
    const int*   kptr   = (const int*)d_in[16];

    int*   p_tidx;   cudaGetSymbolAddress((void**)&p_tidx,   g_tidx);
    float* p_tval;   cudaGetSymbolAddress((void**)&p_tval,   g_tval);
    int*   p_slot2;  cudaGetSymbolAddress((void**)&p_slot2,  g_slot2);
    float* p_qkv;    cudaGetSymbolAddress((void**)&p_qkv,    g_qkv);
    float* p_attn;   cudaGetSymbolAddress((void**)&p_attn,   g_attn);
    float* p_msg;    cudaGetSymbolAddress((void**)&p_msg,    g_msg);
    float* p_h;      cudaGetSymbolAddress((void**)&p_h,      g_h);
    float* p_newact; cudaGetSymbolAddress((void**)&p_newact, g_newact);
    float* wt_su1;   cudaGetSymbolAddress((void**)&wt_su1,   g_wt_su1);

    __half *in0,*in1, *ow0,*ow1, *s10,*s11, *s20,*s21, *a10,*a11;
    __half *h0,*h1, *n0,*n1;
    cudaGetSymbolAddress((void**)&in0, g_in0); cudaGetSymbolAddress((void**)&in1, g_in1);
    cudaGetSymbolAddress((void**)&ow0, g_ow0); cudaGetSymbolAddress((void**)&ow1, g_ow1);
    cudaGetSymbolAddress((void**)&s10, g_s10); cudaGetSymbolAddress((void**)&s11, g_s11);
    cudaGetSymbolAddress((void**)&s20, g_s20); cudaGetSymbolAddress((void**)&s21, g_s21);
    cudaGetSymbolAddress((void**)&a10, g_a10); cudaGetSymbolAddress((void**)&a11, g_a11);
    cudaGetSymbolAddress((void**)&h0, g_h0); cudaGetSymbolAddress((void**)&h1, g_h1);
    cudaGetSymbolAddress((void**)&n0, g_n0); cudaGetSymbolAddress((void**)&n1, g_n1);

    const int SMEM_GEMM2 = (2 * TBK * 132 + 2 * TBK * 256) * 4;
    const int SMEM_ATTN  = 2 * MSGK * HD * 4;

    cudaFuncSetAttribute(mma_gemm, cudaFuncAttributeMaxDynamicSharedMemorySize, TC_SMEM);
    cudaFuncSetAttribute(mma_gemm_ps, cudaFuncAttributeMaxDynamicSharedMemorySize, PS_SMEM);
    cudaFuncSetAttribute(gemm2, cudaFuncAttributeMaxDynamicSharedMemorySize, SMEM_GEMM2);
    cudaFuncSetAttribute(attn_kernel, cudaFuncAttributeMaxDynamicSharedMemorySize, SMEM_ATTN);

    // side stream + events for graph fork/join
    cudaStream_t s2;
    cudaStreamCreateWithFlags(&s2, cudaStreamNonBlocking);
    cudaEvent_t evF, evS, evJ;
    cudaEventCreateWithFlags(&evF, cudaEventDisableTiming);
    cudaEventCreateWithFlags(&evS, cudaEventDisableTiming);
    cudaEventCreateWithFlags(&evJ, cudaEventDisableTiming);

    // ---- fork: topk1 depends only on `act` (radix select; order-free compaction) ----
    cudaEventRecord(evF, 0);
    cudaStreamWaitEvent(s2, evF, 0);
    radix_topk_kernel<<<BB, 256, 0, s2>>>(act, nullptr, MSGK, p_tidx, p_tval, nullptr);

    // ---- main: weight + activation prep ----
    split_weights_kernel<<<(SZ_TOT + 255) / 256, 256>>>(
        in_w, out_w, su_w1, su_w2, au_w1,
        in0, in1, ow0, ow1, s10, s11, s20, s21, a10, a11);
    transpose_kernel<<<dim3(16, 8), dim3(32, 8)>>>(su_w1, wt_su1, 256, 512);
    split2v_kernel<<<BB * NN * DD / 2048, 256>>>(hidden, h0, h1);
    cudaEventRecord(evS, 0);

    // ---- side stream: qkv -> attn -> out-proj ----
    cudaStreamWaitEvent(s2, evS, 0);
    mma_gemm_ps<<<dim3(64, 3), 512, PS_SMEM, s2>>>(
        h0, h1, nullptr, nullptr, p_tidx,
        in0, in1, 256, in_b,
        nullptr, nullptr, nullptr, nullptr,
        p_qkv, 768, 256, 256, 256, 256, 0);
    attn_kernel<<<BB * 4, 256, SMEM_ATTN, s2>>>(p_qkv, p_attn);
    mma_gemm<<<dim3(64, 1), 512, TC_SMEM, s2>>>(
        p_attn, ow0, ow1, 256, out_b,
        p_tval, nullptr, nullptr,
        p_msg, 256, nullptr, nullptr,
        256, 0, 0);
    cudaEventRecord(evJ, s2);

    // ---- main (concurrent with side stream): su1 dense ----
    mma_gemm_ps<<<dim3(1024, 1), 512, PS_SMEM>>>(
        h0, h1, nullptr, nullptr, nullptr,
        s10, s11, 512, su_b1,
        nullptr, nullptr, nullptr, nullptr,
        p_h, 256, 256, 256, 256, 256, 0);

    // ---- join, then serial tail ----
    cudaStreamWaitEvent(0, evJ, 0);

    // su1 sparse: pre[active] += msg @ W1b^T  (scalar fp32, exact)
    gemm2<<<dim3(64, 1), TTH, SMEM_GEMM2>>>(
        p_msg, wt_su1 + 256 * 256, 256, p_h, p_tidx, 256, 256);

    // su2: newhid = LN( gelu(pre) @ W2^T + b2 ) -> fp16 planes only
    mma_gemm<<<dim3(1024, 1), 512, TC_SMEM>>>(
        p_h, s20, s21, 256, su_b2,
        nullptr, ln_g, ln_b,
        nullptr, 256, n0, n1,
        256, 1, 2);

    // au1 fused act update (3-term fp16, pipelined, A = [hidden|newhid] planes)
    mma_gemm_ps<<<dim3(1024, 1), 512, PS_SMEM>>>(
        h0, h1, n0, n1, nullptr,
        a10, a11, 512, au_b1,
        au_w2, au_b2, act, p_newact,
        nullptr, 256, 256, 256, 256, 512, 3);

    // final top-k (k from device sparsity_k) -> membership map only
    radix_topk_kernel<<<BB, 256>>>(p_newact, kptr, 0, nullptr, nullptr, p_slot2);

    // masked write [sparse_act | sparse_hidden] with fp16-plane reconstruction
    finalize_kernel<<<2048, 256>>>(p_newact, n0, n1, p_slot2, (float*)d_out);
}

// round 14
// speedup vs baseline: 9.6805x; 1.0364x over previous
#include <cuda_runtime.h>
#include <cuda_fp16.h>
#include <math.h>

#define BB 32
#define NN 4096
#define DD 256
#define MSGK 256
#define HD 64

// scalar gemm (sparse scatter-accum only)
#define TBM 128
#define TBK 16
#define TTH 512

// ------------------------- device scratch -------------------------
__device__ int   g_tidx[BB * MSGK];
__device__ float g_tval[BB * MSGK];
__device__ int   g_slot2[BB * NN];
__device__ float g_qkv[BB * MSGK * 3 * DD];
__device__ float g_attn[BB * MSGK * DD];
__device__ float g_msg[BB * MSGK * DD];
__device__ float g_h[(size_t)BB * NN * DD];
__device__ float g_newact[BB * NN];
__device__ float g_dot[2 * BB * NN];
__device__ float g_wt_su1[512 * 256];

// fp16 2-way splits of weights
__device__ __half g_in0[768*256],  g_in1[768*256];
__device__ __half g_ow0[256*256],  g_ow1[256*256];
__device__ __half g_s10[256*512],  g_s11[256*512];
__device__ __half g_s20[256*256],  g_s21[256*256];
__device__ __half g_a10[256*512],  g_a11[256*512];

// fp16 2-way splits of activations
__device__ __half g_h0[(size_t)BB*NN*DD], g_h1[(size_t)BB*NN*DD];
__device__ __half g_n0[(size_t)BB*NN*DD], g_n1[(size_t)BB*NN*DD];

__device__ __forceinline__ float gelu_f(float x) {
    return 0.5f * x * (1.0f + erff(x * 0.70710678118654752440f));
}

__device__ __forceinline__ unsigned smem_u32(const void* p) {
    unsigned a;
    asm("{ .reg .u64 t; cvta.to.shared.u64 t, %1; cvt.u32.u64 %0, t; }" : "=r"(a) : "l"(p));
    return a;
}

__device__ __forceinline__ void ldsm4(unsigned& r0, unsigned& r1, unsigned& r2, unsigned& r3,
                                      unsigned addr) {
    asm volatile("ldmatrix.sync.aligned.m8n8.x4.shared.b16 {%0,%1,%2,%3}, [%4];"
                 : "=r"(r0), "=r"(r1), "=r"(r2), "=r"(r3) : "r"(addr));
}

__device__ __forceinline__ void mma_f16(float* c, unsigned a0, unsigned a1, unsigned a2,
                                        unsigned a3, unsigned b0, unsigned b1) {
    asm volatile("mma.sync.aligned.m16n8k16.row.col.f32.f16.f16.f32 "
                 "{%0,%1,%2,%3},{%4,%5,%6,%7},{%8,%9},{%0,%1,%2,%3};"
                 : "+f"(c[0]), "+f"(c[1]), "+f"(c[2]), "+f"(c[3])
                 : "r"(a0), "r"(a1), "r"(a2), "r"(a3), "r"(b0), "r"(b1));
}

#define CPASYNC16(dst, src) \
    asm volatile("cp.async.cg.shared.global [%0], [%1], 16;" :: "r"(dst), "l"(src) : "memory")
#define CPCOMMIT() asm volatile("cp.async.commit_group;" ::: "memory")
#define CPWAIT0() asm volatile("cp.async.wait_group 0;" ::: "memory")
#define CPWAIT1() asm volatile("cp.async.wait_group 1;" ::: "memory")

__device__ __forceinline__ unsigned short hbits(__half h) {
    return *(unsigned short*)&h;
}

// ------------------------- merged weight split (fp16 2-way) -------------------
#define SZ_IN  196608
#define SZ_OW  65536
#define SZ_S1  131072
#define SZ_S2  65536
#define SZ_A1  131072
#define SZ_TOT (SZ_IN + SZ_OW + SZ_S1 + SZ_S2 + SZ_A1)   // 589824

__global__ void split_weights_kernel(
    const float* __restrict__ in_w, const float* __restrict__ out_w,
    const float* __restrict__ su_w1, const float* __restrict__ su_w2,
    const float* __restrict__ au_w1,
    __half* in0, __half* in1, __half* ow0, __half* ow1,
    __half* s10, __half* s11, __half* s20, __half* s21,
    __half* a10, __half* a11) {
    int i = blockIdx.x * 256 + threadIdx.x;
    const float* src; __half *d0, *d1; int off;
    if (i < SZ_IN)                          { src = in_w;  d0 = in0; d1 = in1; off = i; }
    else if (i < SZ_IN+SZ_OW)               { src = out_w; d0 = ow0; d1 = ow1; off = i - SZ_IN; }
    else if (i < SZ_IN+SZ_OW+SZ_S1)         { src = su_w1; d0 = s10; d1 = s11; off = i - SZ_IN - SZ_OW; }
    else if (i < SZ_IN+SZ_OW+SZ_S1+SZ_S2)   { src = su_w2; d0 = s20; d1 = s21; off = i - SZ_IN - SZ_OW - SZ_S1; }
    else if (i < SZ_TOT)                    { src = au_w1; d0 = a10; d1 = a11; off = i - SZ_IN - SZ_OW - SZ_S1 - SZ_S2; }
    else return;
    float v = src[off];
    __half a = __float2half_rn(v);
    d0[off] = a;
    d1[off] = __float2half_rn(v - __half2float(a));
}

// ------------------------- vectorized activation split (x8) -------------------
__global__ void split2v_kernel(const float* __restrict__ W, __half* o0, __half* o1) {
    long long i = ((long long)blockIdx.x * 256 + threadIdx.x) * 8;
    float4 v0 = *(const float4*)(W + i);
    float4 v1 = *(const float4*)(W + i + 4);
    float v[8] = {v0.x, v0.y, v0.z, v0.w, v1.x, v1.y, v1.z, v1.w};
    unsigned short p0[8], p1[8];
#pragma unroll
    for (int j = 0; j < 8; j++) {
        __half a = __float2half_rn(v[j]);
        p0[j] = hbits(a);
        p1[j] = hbits(__float2half_rn(v[j] - __half2float(a)));
    }
    uint4 u0 = make_uint4(((unsigned)p0[1]<<16)|p0[0], ((unsigned)p0[3]<<16)|p0[2],
                          ((unsigned)p0[5]<<16)|p0[4], ((unsigned)p0[7]<<16)|p0[6]);
    uint4 u1 = make_uint4(((unsigned)p1[1]<<16)|p1[0], ((unsigned)p1[3]<<16)|p1[2],
                          ((unsigned)p1[5]<<16)|p1[4], ((unsigned)p1[7]<<16)|p1[6]);
    *(uint4*)(o0 + i) = u0;
    *(uint4*)(o1 + i) = u1;
}

// ------------------------- weight transpose (scalar scatter gemm) ------------
__global__ void transpose_kernel(const float* __restrict__ W, float* __restrict__ Wt,
                                 int Nout, int Kd) {
    __shared__ float t[32][33];
    int k0 = blockIdx.x * 32, n0 = blockIdx.y * 32;
    int tx = threadIdx.x, ty = threadIdx.y;
#pragma unroll
    for (int i = 0; i < 32; i += 8)
        t[ty + i][tx] = W[(long long)(n0 + ty + i) * Kd + k0 + tx];
    __syncthreads();
#pragma unroll
    for (int i = 0; i < 32; i += 8)
        Wt[(long long)(k0 + ty + i) * Nout + n0 + tx] = t[tx][ty + i];
}

// ------------------------- radix-select top-k -------------------------
__global__ void radix_topk_kernel(const float* __restrict__ act,
                                  const int* __restrict__ kptr, int kconst,
                                  int* __restrict__ idx_out, float* __restrict__ val_out,
                                  int* __restrict__ slotmap) {
    __shared__ unsigned bits[NN];
    __shared__ unsigned hist[256];
    __shared__ unsigned s_sel[2];
    __shared__ int s_cnt;
    int b = blockIdx.x;
    int tid = threadIdx.x;
    int kk = kptr ? *kptr : kconst;
    if (kk > NN) kk = NN;
    if (kk < 0) kk = 0;

    const float* row = act + b * NN;
    for (int i = tid; i < NN; i += 256) bits[i] = __float_as_uint(row[i]);

    if (kk == 0) {
        if (slotmap) for (int i = tid; i < NN; i += 256) slotmap[b * NN + i] = -1;
        return;
    }
    __syncthreads();

    unsigned need = (unsigned)kk;
    unsigned prefix = 0;
    unsigned lastE = 0;
    for (int pass = 3; pass >= 0; pass--) {
        hist[tid] = 0;
        __syncthreads();
        int sh = pass * 8;
        for (int i = tid; i < NN; i += 256) {
            unsigned ub = bits[i];
            if ((pass == 3) || ((ub >> (sh + 8)) == prefix))
                atomicAdd(&hist[(ub >> sh) & 255], 1u);
        }
        __syncthreads();
        if (tid == 0) {
            unsigned cum = 0;
            int bsel = 0;
            for (int bin2 = 255; bin2 >= 0; bin2--) {
                unsigned c = hist[bin2];
                if (cum + c >= need) { bsel = bin2; break; }
                cum += c;
            }
            s_sel[0] = (unsigned)bsel;
            s_sel[1] = cum;
        }
        __syncthreads();
        lastE = hist[s_sel[0]];
        need -= s_sel[1];
        prefix = (prefix << 8) | s_sel[0];
        __syncthreads();
    }
    unsigned thr = prefix;
    bool exactAll = (lastE == need);

    if (tid == 0) s_cnt = 0;
    __syncthreads();
    for (int i = tid; i < NN; i += 256) {
        unsigned ub = bits[i];
        bool in = (ub > thr) || (exactAll && ub == thr);
        if (slotmap) slotmap[b * NN + i] = in ? 0 : -1;
        if (in && idx_out) {
            int s = atomicAdd(&s_cnt, 1);
            idx_out[b * kk + s] = i;
            val_out[b * kk + s] = row[i];
        }
    }
    if (!exactAll) {
        __syncthreads();
        if (tid == 0) {
            int take = (int)need;
            for (int i = 0; i < NN && take > 0; i++) {
                if (bits[i] == thr) {
                    if (slotmap) slotmap[b * NN + i] = 0;
                    if (idx_out) {
                        int s = s_cnt++;
                        idx_out[b * kk + s] = i;
                        val_out[b * kk + s] = row[i];
                    }
                    take--;
                }
            }
        }
    }
}

// ============ 2-CTA/SM pre-split pipelined tensor GEMM (fp16, 3-term) =========
// CTA tile 128 x 128, 256 threads, 8 warps (4m x 2n), launch_bounds(256,2).
// mode 0: bias store to C.  mode 4: bias+gelu+dot(w2) partial -> dotbuf[y][m].
#define P2_AP 8192
#define P2_BOFF 16384
#define P2_BP 8192
#define P2_STAGE 32768
#define P2_SMEM 65536

__global__ __launch_bounds__(256, 2)
void mma_gemm_ps2(const __half* __restrict__ A0, const __half* __restrict__ A1p,
                  const __half* __restrict__ Z0, const __half* __restrict__ Z1,
                  const int* __restrict__ gather,
                  const __half* __restrict__ W0, const __half* __restrict__ W1, int ldw,
                  const float* __restrict__ bias,
                  const float* __restrict__ w2, float* __restrict__ dotbuf,
                  float* __restrict__ C, int ldc,
                  int K1, int lda1, int lda2, int Ktot, int mode) {
    extern __shared__ char smem[];
    unsigned sbase = smem_u32(smem);
    int tid = threadIdx.x;
    int lane = tid & 31;
    int wid = tid >> 5;          // 0..7
    int wm = wid & 3;
    int wn = wid >> 2;           // 0..1
    int r0 = blockIdx.x * 128;
    int colbase = blockIdx.y * 128;

    // ---- staging maps (256 threads) ----
    int arow = tid >> 1, ahalf = tid & 1;      // 2 threads per A row, 32B each/plane
    int m_a = r0 + arow;
    long long ridx1 = gather ? (long long)((m_a >> 8) * NN + gather[m_a]) : m_a;
    const char* a1b0 = (const char*)(A0 + ridx1 * lda1);
    const char* a1b1 = (const char*)(A1p + ridx1 * lda1);
    const char* a2b0 = Z0 ? (const char*)(Z0 + (long long)m_a * lda2) : a1b0;
    const char* a2b1 = Z1 ? (const char*)(Z1 + (long long)m_a * lda2) : a1b1;
    unsigned aswz = ((arow >> 1) & 3) << 4;
    unsigned ad_a = (unsigned)arow * 64 + (((unsigned)(ahalf * 32)) ^ aswz);
    unsigned ad_b = (unsigned)arow * 64 + (((unsigned)(ahalf * 32 + 16)) ^ aswz);

    // B: same 2-threads-per-row map over 128 n-rows
    unsigned bswz = aswz;                       // same row index
    long long brow = (long long)(colbase + arow) * ldw;

    const int ta3[3] = {0, 0, 1};
    const int tb3[3] = {0, 1, 0};

    // ---- mma fragment addressing ----
    int a_r = wm * 32 + (lane & 15);
    unsigned a_k0 = (unsigned)((lane >> 4) << 4);
    unsigned a_sw = ((a_r >> 1) & 3) << 4;
    int b_g = lane >> 3, b_r = lane & 7;
    int b_n0 = wn * 64 + ((b_g >> 1) << 3) + b_r;
    unsigned b_k0 = (unsigned)((b_g & 1) << 4);

    float acc[2][8][4];
#pragma unroll
    for (int mt = 0; mt < 2; mt++)
#pragma unroll
        for (int nt = 0; nt < 8; nt++)
#pragma unroll
            for (int c = 0; c < 4; c++) acc[mt][nt][c] = 0.0f;

    int nc = Ktot >> 5;

#define P2_STAGE_FN(c_) do {                                                   \
        int buf_ = (c_) & 1;                                                   \
        unsigned stg_ = sbase + buf_ * P2_STAGE;                               \
        int kc_ = (c_) << 5;                                                   \
        const char *p0_, *p1_; long long ko_;                                  \
        if (kc_ < K1) { p0_ = a1b0; p1_ = a1b1; ko_ = kc_; }                   \
        else          { p0_ = a2b0; p1_ = a2b1; ko_ = kc_ - K1; }              \
        long long ab_ = ko_ * 2 + ahalf * 32;                                  \
        CPASYNC16(stg_ + ad_a, p0_ + ab_);                                     \
        CPASYNC16(stg_ + ad_b, p0_ + ab_ + 16);                                \
        CPASYNC16(stg_ + P2_AP + ad_a, p1_ + ab_);                             \
        CPASYNC16(stg_ + P2_AP + ad_b, p1_ + ab_ + 16);                        \
        long long bo_ = (brow + kc_) * 2 + ahalf * 32;                         \
        unsigned bd_ = stg_ + P2_BOFF;                                         \
        CPASYNC16(bd_ + ad_a, (const char*)W0 + bo_);                          \
        CPASYNC16(bd_ + ad_b, (const char*)W0 + bo_ + 16);                     \
        CPASYNC16(bd_ + P2_BP + ad_a, (const char*)W1 + bo_);                  \
        CPASYNC16(bd_ + P2_BP + ad_b, (const char*)W1 + bo_ + 16);             \
    } while (0)

    P2_STAGE_FN(0);
    CPCOMMIT();

    for (int c = 0; c < nc; c++) {
        if (c + 1 < nc) { P2_STAGE_FN(c + 1); CPCOMMIT(); CPWAIT1(); }
        else            { CPWAIT0(); }
        __syncthreads();

        unsigned stg = sbase + (c & 1) * P2_STAGE;
#pragma unroll
        for (int p = 0; p < 3; p++) {
            unsigned Ab = stg + ta3[p] * P2_AP;
            unsigned Bb = stg + P2_BOFF + tb3[p] * P2_BP;
#pragma unroll
            for (int ks = 0; ks < 2; ks++) {
                unsigned akb = ((unsigned)(ks << 5) + a_k0) ^ a_sw;
                unsigned a0[4], a1r[4];
                ldsm4(a0[0], a0[1], a0[2], a0[3], Ab + (unsigned)a_r * 64 + akb);
                ldsm4(a1r[0], a1r[1], a1r[2], a1r[3], Ab + (unsigned)(a_r + 16) * 64 + akb);
#pragma unroll
                for (int np = 0; np < 4; np++) {
                    int n = b_n0 + np * 16;
                    unsigned bkb = ((unsigned)(ks << 5) + b_k0) ^ (unsigned)(((n >> 1) & 3) << 4);
                    unsigned b0, b1, b2, b3;
                    ldsm4(b0, b1, b2, b3, Bb + (unsigned)n * 64 + bkb);
                    mma_f16(acc[0][2*np],   a0[0], a0[1], a0[2], a0[3], b0, b1);
                    mma_f16(acc[0][2*np+1], a0[0], a0[1], a0[2], a0[3], b2, b3);
                    mma_f16(acc[1][2*np],   a1r[0], a1r[1], a1r[2], a1r[3], b0, b1);
                    mma_f16(acc[1][2*np+1], a1r[0], a1r[1], a1r[2], a1r[3], b2, b3);
                }
            }
        }
        __syncthreads();
    }

    // ---------------- epilogue ----------------
    int qd = lane & 3;
    int rql = lane >> 2;
    float bv[16];
#pragma unroll
    for (int nt = 0; nt < 8; nt++) {
        int cg = colbase + wn * 64 + nt * 8 + 2 * qd;
        float2 t2 = *(const float2*)(bias + cg);
        bv[2*nt] = t2.x; bv[2*nt+1] = t2.y;
    }

    if (mode == 0) {
#pragma unroll
        for (int mt = 0; mt < 2; mt++)
#pragma unroll
            for (int hf = 0; hf < 2; hf++) {
                int m = r0 + wm * 32 + mt * 16 + rql + hf * 8;
#pragma unroll
                for (int nt = 0; nt < 8; nt++) {
                    int cg = colbase + wn * 64 + nt * 8 + 2 * qd;
                    float2 o;
                    o.x = acc[mt][nt][2*hf]   + bv[2*nt];
                    o.y = acc[mt][nt][2*hf+1] + bv[2*nt+1];
                    *(float2*)(C + (long long)m * ldc + cg) = o;
                }
            }
        return;
    }

    // mode 4: gelu + partial dot over local 128 cols -> dotbuf[y][m]
    {
        float* red = (float*)smem;   // 128 x 2
        float wv[16];
#pragma unroll
        for (int nt = 0; nt < 8; nt++) {
            int cg = colbase + wn * 64 + nt * 8 + 2 * qd;
            float2 tw = *(const float2*)(w2 + cg);
            wv[2*nt] = tw.x; wv[2*nt+1] = tw.y;
        }
#pragma unroll
        for (int mt = 0; mt < 2; mt++)
#pragma unroll
            for (int hf = 0; hf < 2; hf++) {
                float d = 0.0f;
#pragma unroll
                for (int nt = 0; nt < 8; nt++) {
                    float f0 = gelu_f(acc[mt][nt][2*hf]   + bv[2*nt]);
                    float f1 = gelu_f(acc[mt][nt][2*hf+1] + bv[2*nt+1]);
                    d += f0 * wv[2*nt] + f1 * wv[2*nt+1];
                }
                d += __shfl_xor_sync(0xffffffffu, d, 1);
                d += __shfl_xor_sync(0xffffffffu, d, 2);
                if (qd == 0) {
                    int rl = wm * 32 + mt * 16 + rql + hf * 8;
                    red[rl * 2 + wn] = d;
                }
            }
        __syncthreads();
        if (tid < 128)
            dotbuf[(long long)blockIdx.y * (BB * NN) + r0 + tid] = red[tid*2] + red[tid*2+1];
    }
}

// ------------------------- act update (sum partials + sigmoid blend) ---------
__global__ void act_update_kernel(const float* __restrict__ dotbuf,
                                  const float* __restrict__ b2,
                                  const float* __restrict__ act_in,
                                  float* __restrict__ act_out) {
    int i = blockIdx.x * 256 + threadIdx.x;
    float d = dotbuf[i] + dotbuf[BB * NN + i];
    float dl = 1.0f / (1.0f + expf(-(d + b2[0])));
    float na = 0.7f * act_in[i] + 0.3f * dl;
    act_out[i] = fminf(fmaxf(na, 0.0f), 1.0f);
}

// ======================= convert-path tensor GEMM (fp32 A, fp16 3-term) =======
#define A_TERM 16384
#define B_TERM 32768
#define BB_OFF (2 * A_TERM)
#define TC_SMEM (2 * A_TERM + 2 * B_TERM)   // 98304

__global__ __launch_bounds__(512, 1)
void mma_gemm(const float* __restrict__ A1,
              const __half* __restrict__ W0, const __half* __restrict__ W1, int ldw,
              const float* __restrict__ bias,
              const float* __restrict__ rowscale,
              const float* __restrict__ lng, const float* __restrict__ lnb,
              float* __restrict__ C, int ldc,
              __half* __restrict__ n0p, __half* __restrict__ n1p,
              int Ktot, int a1_gelu, int mode) {
    extern __shared__ char smem[];
    unsigned sbase = smem_u32(smem);
    int tid = threadIdx.x;
    int lane = tid & 31;
    int wid = tid >> 5;
    int wm = wid & 3;
    int wn = wid >> 2;
    int r0 = blockIdx.x * 128;
    int colbase = blockIdx.y * 256;

    int s_arow = tid >> 2;
    int s_aq   = tid & 3;
    int m_a = r0 + s_arow;
    const float* a1p = A1 + (long long)m_a * Ktot;

    int s_bn = tid >> 1;
    int s_bh = tid & 1;
    long long bro = (long long)(colbase + s_bn) * ldw;

    const int ta3[3] = {0, 0, 1};
    const int tb3[3] = {0, 1, 0};

    int a_r = wm * 32 + (lane & 15);
    unsigned a_sw = (unsigned)((a_r & 7) << 4);
    unsigned a_kb0 = (unsigned)((lane >> 4) << 4);
    int b_g = lane >> 3, b_r = lane & 7;
    unsigned b_kb0 = (unsigned)((b_g & 1) << 4);

    float acc[2][8][4];
#pragma unroll
    for (int mt = 0; mt < 2; mt++)
#pragma unroll
        for (int nt = 0; nt < 8; nt++)
#pragma unroll
            for (int c = 0; c < 4; c++) acc[mt][nt][c] = 0.0f;

    int nchunks = Ktot >> 6;
    for (int ch = 0; ch < nchunks; ch++) {
        int kc = ch << 6;
        {
            const float* src = a1p + kc + s_aq * 16;
            float v[16];
#pragma unroll
            for (int j = 0; j < 4; j++) {
                float4 t4 = *(const float4*)(src + j * 4);
                v[j*4+0] = t4.x; v[j*4+1] = t4.y; v[j*4+2] = t4.z; v[j*4+3] = t4.w;
            }
            if (a1_gelu) {
#pragma unroll
                for (int j = 0; j < 16; j++) v[j] = gelu_f(v[j]);
            }
            unsigned u0[8], u1[8];
#pragma unroll
            for (int j = 0; j < 8; j++) {
                float x = v[2*j], y = v[2*j+1];
                __half hx0 = __float2half_rn(x);
                __half hy0 = __float2half_rn(y);
                __half hx1 = __float2half_rn(x - __half2float(hx0));
                __half hy1 = __float2half_rn(y - __half2float(hy0));
                u0[j] = ((unsigned)hbits(hy0) << 16) | hbits(hx0);
                u1[j] = ((unsigned)hbits(hy1) << 16) | hbits(hx1);
            }
            unsigned rsw = (unsigned)((s_arow & 7) << 4);
            unsigned rb = (unsigned)s_arow * 128;
#pragma unroll
            for (int j8 = 0; j8 < 4; j8++) {
                unsigned kb = (unsigned)(s_aq * 32 + j8 * 8) ^ rsw;
                *(uint2*)(smem + rb + kb) = make_uint2(u0[2*j8], u0[2*j8+1]);
                *(uint2*)(smem + A_TERM + rb + kb) = make_uint2(u1[2*j8], u1[2*j8+1]);
            }
        }
        {
            unsigned nsw = (unsigned)((s_bn & 7) << 4);
            unsigned nb = (unsigned)s_bn * 128;
            long long goff = (bro + kc) * 2;
#pragma unroll
            for (int w = 0; w < 2; w++) {
                const char* Wsrc = (const char*)((w == 0) ? W0 : W1);
#pragma unroll
                for (int i = 0; i < 4; i++) {
                    unsigned kb = (unsigned)(s_bh * 64 + i * 16);
                    CPASYNC16(sbase + BB_OFF + w * B_TERM + nb + (kb ^ nsw), Wsrc + goff + kb);
                }
            }
        }
        CPCOMMIT();
        CPWAIT0();
        __syncthreads();

#pragma unroll
        for (int p = 0; p < 3; p++) {
            unsigned Ab = sbase + ta3[p] * A_TERM;
            unsigned Bb = sbase + BB_OFF + tb3[p] * B_TERM;
#pragma unroll
            for (int ks = 0; ks < 4; ks++) {
                unsigned a0[4], a1r[4];
                unsigned akb = ((unsigned)(ks * 32) + a_kb0) ^ a_sw;
                ldsm4(a0[0], a0[1], a0[2], a0[3], Ab + (unsigned)a_r * 128 + akb);
                ldsm4(a1r[0], a1r[1], a1r[2], a1r[3], Ab + (unsigned)(a_r + 16) * 128 + akb);
#pragma unroll
                for (int np = 0; np < 4; np++) {
                    int n = wn * 64 + np * 16 + ((b_g >> 1) << 3) + b_r;
                    unsigned bkb = ((unsigned)(ks * 32) + b_kb0) ^ (unsigned)((n & 7) << 4);
                    unsigned b0, b1, b2, b3;
                    ldsm4(b0, b1, b2, b3, Bb + (unsigned)n * 128 + bkb);
                    mma_f16(acc[0][2*np],   a0[0], a0[1], a0[2], a0[3], b0, b1);
                    mma_f16(acc[0][2*np+1], a0[0], a0[1], a0[2], a0[3], b2, b3);
                    mma_f16(acc[1][2*np],   a1r[0], a1r[1], a1r[2], a1r[3], b0, b1);
                    mma_f16(acc[1][2*np+1], a1r[0], a1r[1], a1r[2], a1r[3], b2, b3);
                }
            }
        }
        __syncthreads();
    }

    int qd = lane & 3;
    int rql = lane >> 2;
    float bv[16];
#pragma unroll
    for (int nt = 0; nt < 8; nt++) {
        int cg = colbase + wn * 64 + nt * 8 + 2 * qd;
        float2 t2 = *(const float2*)(bias + cg);
        bv[2*nt] = t2.x; bv[2*nt+1] = t2.y;
    }

    if (mode == 0) {
#pragma unroll
        for (int mt = 0; mt < 2; mt++)
#pragma unroll
            for (int hf = 0; hf < 2; hf++) {
                int m = r0 + wm * 32 + mt * 16 + rql + hf * 8;
                float sc = rowscale ? rowscale[m] : 1.0f;
#pragma unroll
                for (int nt = 0; nt < 8; nt++) {
                    int cg = colbase + wn * 64 + nt * 8 + 2 * qd;
                    float2 o;
                    o.x = (acc[mt][nt][2*hf]   + bv[2*nt])   * sc;
                    o.y = (acc[mt][nt][2*hf+1] + bv[2*nt+1]) * sc;
                    *(float2*)(C + (long long)m * ldc + cg) = o;
                }
            }
        return;
    }

    // mode 2: layernorm -> fp16 plane outputs
    float* red = (float*)smem;
    float* red2 = red + 512;
#pragma unroll
    for (int mt = 0; mt < 2; mt++)
#pragma unroll
        for (int hf = 0; hf < 2; hf++) {
            float s = 0.0f, sq = 0.0f;
#pragma unroll
            for (int nt = 0; nt < 8; nt++) {
                float f0 = acc[mt][nt][2*hf]   + bv[2*nt];
                float f1 = acc[mt][nt][2*hf+1] + bv[2*nt+1];
                s += f0 + f1; sq += f0 * f0 + f1 * f1;
            }
            s  += __shfl_xor_sync(0xffffffffu, s, 1);
            s  += __shfl_xor_sync(0xffffffffu, s, 2);
            sq += __shfl_xor_sync(0xffffffffu, sq, 1);
            sq += __shfl_xor_sync(0xffffffffu, sq, 2);
            if (qd == 0) {
                int rl = wm * 32 + mt * 16 + rql + hf * 8;
                red[rl * 4 + wn] = s;
                red2[rl * 4 + wn] = sq;
            }
        }
    __syncthreads();
    float* stats = red2 + 512;
    if (tid < 128) {
        float s = red[tid*4] + red[tid*4+1] + red[tid*4+2] + red[tid*4+3];
        float sq = red2[tid*4] + red2[tid*4+1] + red2[tid*4+2] + red2[tid*4+3];
        float mu = s * (1.0f / 256.0f);
        float var = sq * (1.0f / 256.0f) - mu * mu;
        stats[tid*2] = mu;
        stats[tid*2+1] = rsqrtf(var + 1e-5f);
    }
    __syncthreads();
    float gv[16], ev[16];
#pragma unroll
    for (int nt = 0; nt < 8; nt++) {
        int cg = wn * 64 + nt * 8 + 2 * qd;
        float2 tg = *(const float2*)(lng + cg);
        float2 te = *(const float2*)(lnb + cg);
        gv[2*nt] = tg.x; gv[2*nt+1] = tg.y;
        ev[2*nt] = te.x; ev[2*nt+1] = te.y;
    }
#pragma unroll
    for (int mt = 0; mt < 2; mt++)
#pragma unroll
        for (int hf = 0; hf < 2; hf++) {
            int rl = wm * 32 + mt * 16 + rql + hf * 8;
            int m = r0 + rl;
            float mu = stats[rl*2], inv = stats[rl*2+1];
#pragma unroll
            for (int nt = 0; nt < 8; nt++) {
                int cg = wn * 64 + nt * 8 + 2 * qd;
                float2 o;
                float f0 = acc[mt][nt][2*hf]   + bv[2*nt];
                float f1 = acc[mt][nt][2*hf+1] + bv[2*nt+1];
                o.x = (f0 - mu) * inv * gv[2*nt]   + ev[2*nt];
                o.y = (f1 - mu) * inv * gv[2*nt+1] + ev[2*nt+1];
                if (C) *(float2*)(C + (long long)m * ldc + cg) = o;
                {
                    long long e = (long long)m * 256 + cg;
                    __half x0 = __float2half_rn(o.x);
                    __half x1 = __float2half_rn(o.x - __half2float(x0));
                    __half y0 = __float2half_rn(o.y);
                    __half y1 = __float2half_rn(o.y - __half2float(y0));
                    *(unsigned*)(n0p + e) = ((unsigned)hbits(y0) << 16) | hbits(x0);
                    *(unsigned*)(n1p + e) = ((unsigned)hbits(y1) << 16) | hbits(x1);
                }
            }
        }
}

// ------------------------- scalar GEMM (sparse scatter-accum) --------
__global__ __launch_bounds__(TTH, 1)
void gemm2(const float* __restrict__ A1,
           const float* __restrict__ Wt, int ldw,
           float* __restrict__ C, const int* __restrict__ cgather, int ldc,
           int Ktot) {
    extern __shared__ float sm[];
    float* As = sm;
    float* Ws = sm + 2 * TBK * 132;

    int tid = threadIdx.x;
    int r0 = blockIdx.x * TBM;

    int am = tid >> 2;
    int ak = (tid & 3) << 2;
    int m_a = r0 + am;
    const float* a1row = A1 + (long long)m_a * Ktot;

    int wr = tid >> 5;
    int wc = (tid & 31) << 3;
    const float* wbase = Wt + (long long)wr * ldw + wc;

    float4 av, wv0, wv1;
#define LOAD_ST(kb) do {                                                      \
        av = *(const float4*)(a1row + (kb) + ak);                             \
        const float* wp_ = wbase + (long long)(kb) * ldw;                     \
        wv0 = *(const float4*)(wp_);                                          \
        wv1 = *(const float4*)(wp_ + 4);                                      \
    } while (0)
#define STORE_ST(buf) do {                                                    \
        float* ap_ = As + (buf) * (TBK * 132);                                \
        ap_[(ak + 0) * 132 + am] = av.x;                                      \
        ap_[(ak + 1) * 132 + am] = av.y;                                      \
        ap_[(ak + 2) * 132 + am] = av.z;                                      \
        ap_[(ak + 3) * 132 + am] = av.w;                                      \
        float* wpS_ = Ws + (buf) * (TBK * 256) + wr * 256 + wc;               \
        *(float4*)wpS_ = wv0;                                                 \
        *(float4*)(wpS_ + 4) = wv1;                                           \
    } while (0)

    int lane = tid & 31, warp = tid >> 5;
    int row0 = warp << 3, col0 = lane << 3;

    float acc[8][8];
#pragma unroll
    for (int r = 0; r < 8; r++)
#pragma unroll
        for (int c = 0; c < 8; c++) acc[r][c] = 0.0f;

    LOAD_ST(0); STORE_ST(0);
    __syncthreads();

    int S = Ktot / TBK;
    for (int s = 0; s < S; s++) {
        int cur = s & 1;
        if (s + 1 < S) LOAD_ST((s + 1) * TBK);
        const float* ab = As + cur * (TBK * 132);
        const float* wb = Ws + cur * (TBK * 256);
#pragma unroll
        for (int k = 0; k < TBK; k++) {
            float4 a0 = *(const float4*)(ab + k * 132 + row0);
            float4 a1v = *(const float4*)(ab + k * 132 + row0 + 4);
            float4 b0 = *(const float4*)(wb + k * 256 + col0);
            float4 b1 = *(const float4*)(wb + k * 256 + col0 + 4);
            float aa[8] = {a0.x, a0.y, a0.z, a0.w, a1v.x, a1v.y, a1v.z, a1v.w};
            float bvv[8] = {b0.x, b0.y, b0.z, b0.w, b1.x, b1.y, b1.z, b1.w};
#pragma unroll
            for (int r = 0; r < 8; r++)
#pragma unroll
                for (int c = 0; c < 8; c++) acc[r][c] += aa[r] * bvv[c];
        }
        if (s + 1 < S) { STORE_ST((s + 1) & 1); __syncthreads(); }
    }

#pragma unroll
    for (int r = 0; r < 8; r++) {
        int m = r0 + row0 + r;
        long long crow = (long long)((m >> 8) * NN + cgather[m]);
        float* cp = C + crow * ldc + col0;
        float4 o0 = *(float4*)cp, o1 = *(float4*)(cp + 4);
        o0.x += acc[r][0]; o0.y += acc[r][1]; o0.z += acc[r][2]; o0.w += acc[r][3];
        o1.x += acc[r][4]; o1.y += acc[r][5]; o1.z += acc[r][6]; o1.w += acc[r][7];
        *(float4*)cp = o0; *(float4*)(cp + 4) = o1;
    }
}

// ------------------------- attention -------------------------
__global__ void attn_kernel(const float* __restrict__ qkv, float* __restrict__ out) {
    extern __shared__ float sm[];
    float* Ks = sm;
    float* Vs = sm + MSGK * HD;
    int bh = blockIdx.x;
    int b = bh >> 2;
    int h = bh & 3;
    int tid = threadIdx.x;
    const float* base = qkv + (long long)b * MSGK * 768;

    for (int t = tid; t < MSGK * HD; t += 256) {
        int j = t >> 6;
        int d = t & 63;
        Ks[t] = base[j * 768 + 256 + h * 64 + d];
        Vs[t] = base[j * 768 + 512 + h * 64 + d];
    }
    __syncthreads();

    float q[HD], o[HD];
#pragma unroll
    for (int d = 0; d < HD; d++) { q[d] = base[tid * 768 + h * 64 + d] * 0.125f; o[d] = 0.0f; }

    float mval = -1e30f, l = 0.0f;
    for (int j = 0; j < MSGK; j++) {
        float s = 0.0f;
#pragma unroll
        for (int d = 0; d < HD; d++) s += q[d] * Ks[j * 64 + d];
        float nm = fmaxf(mval, s);
        float corr = expf(mval - nm);
        float p = expf(s - nm);
        l = l * corr + p;
#pragma unroll
        for (int d = 0; d < HD; d++) o[d] = o[d] * corr + p * Vs[j * 64 + d];
        mval = nm;
    }
    float inv = 1.0f / l;
    float* op = out + ((long long)(b * MSGK + tid)) * DD + h * 64;
#pragma unroll
    for (int d = 0; d < HD; d++) op[d] = o[d] * inv;
}

// ------------------------- finalize (reconstruct newhid from fp16 planes) ----
__global__ void finalize_kernel(const float* __restrict__ newact,
                                const __half* __restrict__ n0p, const __half* __restrict__ n1p,
                                const int* __restrict__ slot2, float* __restrict__ out) {
    long long total_act = (long long)BB * NN;
    float* out_act = out;
    float* out_hid = out + total_act;
    long long stride = (long long)gridDim.x * blockDim.x;
    long long t0 = (long long)blockIdx.x * blockDim.x + threadIdx.x;

    for (long long i = t0; i < total_act; i += stride)
        out_act[i] = (slot2[i] >= 0) ? newact[i] : 0.0f;

    long long totalh4 = (long long)BB * NN * DD / 4;
    float4* oh4 = reinterpret_cast<float4*>(out_hid);
    for (long long e = t0; e < totalh4; e += stride) {
        long long r = e >> 6;
        if (slot2[r] >= 0) {
            uint2 u0 = *(const uint2*)(n0p + e * 4);
            uint2 u1 = *(const uint2*)(n1p + e * 4);
            float2 a0 = __half22float2(*(const __half2*)&u0.x);
            float2 a1 = __half22float2(*(const __half2*)&u0.y);
            float2 b0 = __half22float2(*(const __half2*)&u1.x);
            float2 b1 = __half22float2(*(const __half2*)&u1.y);
            oh4[e] = make_float4(a0.x + b0.x, a0.y + b0.y, a1.x + b1.x, a1.y + b1.y);
        } else {
            oh4[e] = make_float4(0.f, 0.f, 0.f, 0.f);
        }
    }
}

// ------------------------- host launcher -------------------------
extern "C" void kernel_launch(void* const* d_in, const int* in_sizes, int n_in,
                              void* d_out, int out_size) {
    const float* act    = (const float*)d_in[0];
    const float* hidden = (const float*)d_in[1];
    const float* in_w   = (const float*)d_in[2];
    const float* in_b   = (const float*)d_in[3];
    const float* out_w  = (const float*)d_in[4];
    const float* out_b  = (const float*)d_in[5];
    const float* su_w1  = (const float*)d_in[6];
    const float* su_b1  = (const float*)d_in[7];
    const float* su_w2  = (const float*)d_in[8];
    const float* su_b2  = (const float*)d_in[9];
    const float* au_w1  = (const float*)d_in[10];
    const float* au_b1  = (const float*)d_in[11];
    const float* au_w2  = (const float*)d_in[12];
    const float* au_b2  = (const float*)d_in[13];
    const float* ln_g   = (const float*)d_in[14];
    const float* ln_b   = (const float*)d_in[15];
    const int*   kptr   = (const int*)d_in[16];

    int*   p_tidx;   cudaGetSymbolAddress((void**)&p_tidx,   g_tidx);
    float* p_tval;   cudaGetSymbolAddress((void**)&p_tval,   g_tval);
    int*   p_slot2;  cudaGetSymbolAddress((void**)&p_slot2,  g_slot2);
    float* p_qkv;    cudaGetSymbolAddress((void**)&p_qkv,    g_qkv);
    float* p_attn;   cudaGetSymbolAddress((void**)&p_attn,   g_attn);
    float* p_msg;    cudaGetSymbolAddress((void**)&p_msg,    g_msg);
    float* p_h;      cudaGetSymbolAddress((void**)&p_h,      g_h);
    float* p_newact; cudaGetSymbolAddress((void**)&p_newact, g_newact);
    float* p_dot;    cudaGetSymbolAddress((void**)&p_dot,    g_dot);
    float* wt_su1;   cudaGetSymbolAddress((void**)&wt_su1,   g_wt_su1);

    __half *in0,*in1, *ow0,*ow1, *s10,*s11, *s20,*s21, *a10,*a11;
    __half *h0,*h1, *n0,*n1;
    cudaGetSymbolAddress((void**)&in0, g_in0); cudaGetSymbolAddress((void**)&in1, g_in1);
    cudaGetSymbolAddress((void**)&ow0, g_ow0); cudaGetSymbolAddress((void**)&ow1, g_ow1);
    cudaGetSymbolAddress((void**)&s10, g_s10); cudaGetSymbolAddress((void**)&s11, g_s11);
    cudaGetSymbolAddress((void**)&s20, g_s20); cudaGetSymbolAddress((void**)&s21, g_s21);
    cudaGetSymbolAddress((void**)&a10, g_a10); cudaGetSymbolAddress((void**)&a11, g_a11);
    cudaGetSymbolAddress((void**)&h0, g_h0); cudaGetSymbolAddress((void**)&h1, g_h1);
    cudaGetSymbolAddress((void**)&n0, g_n0); cudaGetSymbolAddress((void**)&n1, g_n1);

    const int SMEM_GEMM2 = (2 * TBK * 132 + 2 * TBK * 256) * 4;
    const int SMEM_ATTN  = 2 * MSGK * HD * 4;

    cudaFuncSetAttribute(mma_gemm, cudaFuncAttributeMaxDynamicSharedMemorySize, TC_SMEM);
    cudaFuncSetAttribute(mma_gemm_ps2, cudaFuncAttributeMaxDynamicSharedMemorySize, P2_SMEM);
    cudaFuncSetAttribute(gemm2, cudaFuncAttributeMaxDynamicSharedMemorySize, SMEM_GEMM2);
    cudaFuncSetAttribute(attn_kernel, cudaFuncAttributeMaxDynamicSharedMemorySize, SMEM_ATTN);

    // side stream + events for graph fork/join
    cudaStream_t s2;
    cudaStreamCreateWithFlags(&s2, cudaStreamNonBlocking);
    cudaEvent_t evF, evS, evJ;
    cudaEventCreateWithFlags(&evF, cudaEventDisableTiming);
    cudaEventCreateWithFlags(&evS, cudaEventDisableTiming);
    cudaEventCreateWithFlags(&evJ, cudaEventDisableTiming);

    // ---- fork: topk1 depends only on `act` ----
    cudaEventRecord(evF, 0);
    cudaStreamWaitEvent(s2, evF, 0);
    radix_topk_kernel<<<BB, 256, 0, s2>>>(act, nullptr, MSGK, p_tidx, p_tval, nullptr);

    // ---- main: weight + activation prep ----
    split_weights_kernel<<<(SZ_TOT + 255) / 256, 256>>>(
        in_w, out_w, su_w1, su_w2, au_w1,
        in0, in1, ow0, ow1, s10, s11, s20, s21, a10, a11);
    transpose_kernel<<<dim3(16, 8), dim3(32, 8)>>>(su_w1, wt_su1, 256, 512);
    split2v_kernel<<<BB * NN * DD / 2048, 256>>>(hidden, h0, h1);
    cudaEventRecord(evS, 0);

    // ---- side stream: qkv -> attn -> out-proj ----
    cudaStreamWaitEvent(s2, evS, 0);
    mma_gemm_ps2<<<dim3(64, 6), 256, P2_SMEM, s2>>>(
        h0, h1, nullptr, nullptr, p_tidx,
        in0, in1, 256, in_b,
        nullptr, nullptr,
        p_qkv, 768, 256, 256, 256, 256, 0);
    attn_kernel<<<BB * 4, 256, SMEM_ATTN, s2>>>(p_qkv, p_attn);
    mma_gemm<<<dim3(64, 1), 512, TC_SMEM, s2>>>(
        p_attn, ow0, ow1, 256, out_b,
        p_tval, nullptr, nullptr,
        p_msg, 256, nullptr, nullptr,
        256, 0, 0);
    cudaEventRecord(evJ, s2);

    // ---- main (concurrent with side stream): su1 dense ----
    mma_gemm_ps2<<<dim3(1024, 2), 256, P2_SMEM>>>(
        h0, h1, nullptr, nullptr, nullptr,
        s10, s11, 512, su_b1,
        nullptr, nullptr,
        p_h, 256, 256, 256, 256, 256, 0);

    // ---- join, then serial tail ----
    cudaStreamWaitEvent(0, evJ, 0);

    // su1 sparse: pre[active] += msg @ W1b^T  (scalar fp32, exact)
    gemm2<<<dim3(64, 1), TTH, SMEM_GEMM2>>>(
        p_msg, wt_su1 + 256 * 256, 256, p_h, p_tidx, 256, 256);

    // su2: newhid = LN( gelu(pre) @ W2^T + b2 ) -> fp16 planes only
    mma_gemm<<<dim3(1024, 1), 512, TC_SMEM>>>(
        p_h, s20, s21, 256, su_b2,
        nullptr, ln_g, ln_b,
        nullptr, 256, n0, n1,
        256, 1, 2);

    // au1: partial gelu-dot per 128-col half -> g_dot[y][m]
    mma_gemm_ps2<<<dim3(1024, 2), 256, P2_SMEM>>>(
        h0, h1, n0, n1, nullptr,
        a10, a11, 512, au_b1,
        au_w2, p_dot,
        nullptr, 256, 256, 256, 256, 512, 4);

    // act update: sum partials + sigmoid + blend + clip
    act_update_kernel<<<BB * NN / 256, 256>>>(p_dot, au_b2, act, p_newact);

    // final top-k (k from device sparsity_k) -> membership map only
    radix_topk_kernel<<<BB, 256>>>(p_newact, kptr, 0, nullptr, nullptr, p_slot2);

    // masked write [sparse_act | sparse_hidden] with fp16-plane reconstruction
    finalize_kernel<<<2048, 256>>>(p_newact, n0, n1, p_slot2, (float*)d_out);
}

// round 16
// speedup vs baseline: 10.0416x; 1.0373x over previous
#include <cuda_runtime.h>
#include <cuda_fp16.h>
#include <math.h>

#define BB 32
#define NN 4096
#define DD 256
#define MSGK 256
#define HD 64

// ------------------------- device scratch -------------------------
__device__ int   g_tidx[BB * MSGK];
__device__ float g_tval[BB * MSGK];
__device__ int   g_slot2[BB * NN];
__device__ float g_qkv[BB * MSGK * 3 * DD];
__device__ float g_attn[BB * MSGK * DD];
__device__ float g_msg[BB * MSGK * DD];
__device__ float g_h[(size_t)BB * NN * DD];
__device__ float g_newact[BB * NN];
__device__ float g_dot[2 * BB * NN];

// fp16 2-way splits of weights
__device__ __half g_in0[768*256],  g_in1[768*256];
__device__ __half g_ow0[256*256],  g_ow1[256*256];
__device__ __half g_s10[256*512],  g_s11[256*512];
__device__ __half g_s20[256*256],  g_s21[256*256];
__device__ __half g_a10[256*512],  g_a11[256*512];

// fp16 2-way splits of activations / messages
__device__ __half g_h0[(size_t)BB*NN*DD], g_h1[(size_t)BB*NN*DD];
__device__ __half g_n0[(size_t)BB*NN*DD], g_n1[(size_t)BB*NN*DD];
__device__ __half g_m0[BB*MSGK*DD], g_m1[BB*MSGK*DD];

__device__ __forceinline__ float gelu_f(float x) {
    return 0.5f * x * (1.0f + erff(x * 0.70710678118654752440f));
}

__device__ __forceinline__ unsigned smem_u32(const void* p) {
    unsigned a;
    asm("{ .reg .u64 t; cvta.to.shared.u64 t, %1; cvt.u32.u64 %0, t; }" : "=r"(a) : "l"(p));
    return a;
}

__device__ __forceinline__ void ldsm4(unsigned& r0, unsigned& r1, unsigned& r2, unsigned& r3,
                                      unsigned addr) {
    asm volatile("ldmatrix.sync.aligned.m8n8.x4.shared.b16 {%0,%1,%2,%3}, [%4];"
                 : "=r"(r0), "=r"(r1), "=r"(r2), "=r"(r3) : "r"(addr));
}

__device__ __forceinline__ void mma_f16(float* c, unsigned a0, unsigned a1, unsigned a2,
                                        unsigned a3, unsigned b0, unsigned b1) {
    asm volatile("mma.sync.aligned.m16n8k16.row.col.f32.f16.f16.f32 "
                 "{%0,%1,%2,%3},{%4,%5,%6,%7},{%8,%9},{%0,%1,%2,%3};"
                 : "+f"(c[0]), "+f"(c[1]), "+f"(c[2]), "+f"(c[3])
                 : "r"(a0), "r"(a1), "r"(a2), "r"(a3), "r"(b0), "r"(b1));
}

#define CPASYNC16(dst, src) \
    asm volatile("cp.async.cg.shared.global [%0], [%1], 16;" :: "r"(dst), "l"(src) : "memory")
#define CPCOMMIT() asm volatile("cp.async.commit_group;" ::: "memory")
#define CPWAIT0() asm volatile("cp.async.wait_group 0;" ::: "memory")

__device__ __forceinline__ unsigned short hbits(__half h) {
    return *(unsigned short*)&h;
}

// ------------------------- merged weight split (fp16 2-way) -------------------
#define SZ_IN  196608
#define SZ_OW  65536
#define SZ_S1  131072
#define SZ_S2  65536
#define SZ_A1  131072
#define SZ_TOT (SZ_IN + SZ_OW + SZ_S1 + SZ_S2 + SZ_A1)

__global__ void split_weights_kernel(
    const float* __restrict__ in_w, const float* __restrict__ out_w,
    const float* __restrict__ su_w1, const float* __restrict__ su_w2,
    const float* __restrict__ au_w1,
    __half* in0, __half* in1, __half* ow0, __half* ow1,
    __half* s10, __half* s11, __half* s20, __half* s21,
    __half* a10, __half* a11) {
    int i = blockIdx.x * 256 + threadIdx.x;
    const float* src; __half *d0, *d1; int off;
    if (i < SZ_IN)                          { src = in_w;  d0 = in0; d1 = in1; off = i; }
    else if (i < SZ_IN+SZ_OW)               { src = out_w; d0 = ow0; d1 = ow1; off = i - SZ_IN; }
    else if (i < SZ_IN+SZ_OW+SZ_S1)         { src = su_w1; d0 = s10; d1 = s11; off = i - SZ_IN - SZ_OW; }
    else if (i < SZ_IN+SZ_OW+SZ_S1+SZ_S2)   { src = su_w2; d0 = s20; d1 = s21; off = i - SZ_IN - SZ_OW - SZ_S1; }
    else if (i < SZ_TOT)                    { src = au_w1; d0 = a10; d1 = a11; off = i - SZ_IN - SZ_OW - SZ_S1 - SZ_S2; }
    else return;
    float v = src[off];
    __half a = __float2half_rn(v);
    d0[off] = a;
    d1[off] = __float2half_rn(v - __half2float(a));
}

// ------------------------- vectorized activation split (x8) -------------------
__global__ void split2v_kernel(const float* __restrict__ W, __half* o0, __half* o1) {
    long long i = ((long long)blockIdx.x * 256 + threadIdx.x) * 8;
    float4 v0 = *(const float4*)(W + i);
    float4 v1 = *(const float4*)(W + i + 4);
    float v[8] = {v0.x, v0.y, v0.z, v0.w, v1.x, v1.y, v1.z, v1.w};
    unsigned short p0[8], p1[8];
#pragma unroll
    for (int j = 0; j < 8; j++) {
        __half a = __float2half_rn(v[j]);
        p0[j] = hbits(a);
        p1[j] = hbits(__float2half_rn(v[j] - __half2float(a)));
    }
    uint4 u0 = make_uint4(((unsigned)p0[1]<<16)|p0[0], ((unsigned)p0[3]<<16)|p0[2],
                          ((unsigned)p0[5]<<16)|p0[4], ((unsigned)p0[7]<<16)|p0[6]);
    uint4 u1 = make_uint4(((unsigned)p1[1]<<16)|p1[0], ((unsigned)p1[3]<<16)|p1[2],
                          ((unsigned)p1[5]<<16)|p1[4], ((unsigned)p1[7]<<16)|p1[6]);
    *(uint4*)(o0 + i) = u0;
    *(uint4*)(o1 + i) = u1;
}

// ------------------------- radix-select top-k (optionally fused act-update) ---
__global__ void radix_topk_kernel(const float* __restrict__ act,
                                  const int* __restrict__ kptr, int kconst,
                                  int* __restrict__ idx_out, float* __restrict__ val_out,
                                  int* __restrict__ slotmap,
                                  const float* __restrict__ dotbuf,
                                  const float* __restrict__ b2,
                                  float* __restrict__ act_out) {
    __shared__ unsigned bits[NN];
    __shared__ unsigned hist[256];
    __shared__ unsigned s_sel[2];
    __shared__ int s_cnt;
    int b = blockIdx.x;
    int tid = threadIdx.x;
    int kk = kptr ? *kptr : kconst;
    if (kk > NN) kk = NN;
    if (kk < 0) kk = 0;

    if (dotbuf) {
        float b2v = b2[0];
        for (int i = tid; i < NN; i += 256) {
            long long g = (long long)b * NN + i;
            float d = dotbuf[g] + dotbuf[(long long)BB * NN + g];
            float dl = 1.0f / (1.0f + expf(-(d + b2v)));
            float na = 0.7f * act[g] + 0.3f * dl;
            na = fminf(fmaxf(na, 0.0f), 1.0f);
            act_out[g] = na;
            bits[i] = __float_as_uint(na);
        }
    } else {
        const float* row = act + (long long)b * NN;
        for (int i = tid; i < NN; i += 256) bits[i] = __float_as_uint(row[i]);
    }

    if (kk == 0) {
        if (slotmap) for (int i = tid; i < NN; i += 256) slotmap[b * NN + i] = -1;
        return;
    }
    __syncthreads();

    unsigned need = (unsigned)kk;
    unsigned prefix = 0;
    unsigned lastE = 0;
    for (int pass = 3; pass >= 0; pass--) {
        hist[tid] = 0;
        __syncthreads();
        int sh = pass * 8;
        for (int i = tid; i < NN; i += 256) {
            unsigned ub = bits[i];
            if ((pass == 3) || ((ub >> (sh + 8)) == prefix))
                atomicAdd(&hist[(ub >> sh) & 255], 1u);
        }
        __syncthreads();
        if (tid == 0) {
            unsigned cum = 0;
            int bsel = 0;
            for (int bin2 = 255; bin2 >= 0; bin2--) {
                unsigned c = hist[bin2];
                if (cum + c >= need) { bsel = bin2; break; }
                cum += c;
            }
            s_sel[0] = (unsigned)bsel;
            s_sel[1] = cum;
        }
        __syncthreads();
        lastE = hist[s_sel[0]];
        need -= s_sel[1];
        prefix = (prefix << 8) | s_sel[0];
        __syncthreads();
    }
    unsigned thr = prefix;
    bool exactAll = (lastE == need);

    if (tid == 0) s_cnt = 0;
    __syncthreads();
    for (int i = tid; i < NN; i += 256) {
        unsigned ub = bits[i];
        bool in = (ub > thr) || (exactAll && ub == thr);
        if (slotmap) slotmap[b * NN + i] = in ? 0 : -1;
        if (in && idx_out) {
            int s = atomicAdd(&s_cnt, 1);
            idx_out[b * kk + s] = i;
            val_out[b * kk + s] = __uint_as_float(ub);
        }
    }
    if (!exactAll) {
        __syncthreads();
        if (tid == 0) {
            int take = (int)need;
            for (int i = 0; i < NN && take > 0; i++) {
                if (bits[i] == thr) {
                    if (slotmap) slotmap[b * NN + i] = 0;
                    if (idx_out) {
                        int s = s_cnt++;
                        idx_out[b * kk + s] = i;
                        val_out[b * kk + s] = __uint_as_float(thr);
                    }
                    take--;
                }
            }
        }
    }
}

// ============ 2-CTA/SM pre-split pipelined tensor GEMM (fp16, 3-term) =========
// CTA tile 128 x 128, 256 threads, 8 warps (4m x 2n), launch_bounds(256,2).
// mode 0: bias store. mode 4: bias+gelu+dot(w2) partial -> dotbuf[y][m].
// mode 5: scatter-accumulate into C rows via cgather (no bias).
#define P2_AP 8192
#define P2_BOFF 16384
#define P2_BP 8192
#define P2_STAGE 32768
#define P2_SMEM 65536

__global__ __launch_bounds__(256, 2)
void mma_gemm_ps2(const __half* __restrict__ A0, const __half* __restrict__ A1p,
                  const __half* __restrict__ Z0, const __half* __restrict__ Z1,
                  const int* __restrict__ gather, const int* __restrict__ cgather,
                  const __half* __restrict__ W0, const __half* __restrict__ W1, int ldw,
                  const float* __restrict__ bias,
                  const float* __restrict__ w2, float* __restrict__ dotbuf,
                  float* __restrict__ C, int ldc,
                  int K1, int lda1, int lda2, int Ktot, int mode) {
    extern __shared__ char smem[];
    unsigned sbase = smem_u32(smem);
    int tid = threadIdx.x;
    int lane = tid & 31;
    int wid = tid >> 5;
    int wm = wid & 3;
    int wn = wid >> 2;
    int r0 = blockIdx.x * 128;
    int colbase = blockIdx.y * 128;

    // ---- staging maps ----
    int arow = tid >> 1, ahalf = tid & 1;
    int m_a = r0 + arow;
    long long ridx1 = gather ? (long long)((m_a >> 8) * NN + gather[m_a]) : m_a;
    const char* a1b0 = (const char*)(A0 + ridx1 * lda1);
    const char* a1b1 = (const char*)(A1p + ridx1 * lda1);
    const char* a2b0 = Z0 ? (const char*)(Z0 + (long long)m_a * lda2) : a1b0;
    const char* a2b1 = Z1 ? (const char*)(Z1 + (long long)m_a * lda2) : a1b1;
    unsigned aswz = ((arow >> 1) & 3) << 4;
    unsigned ad_a = (unsigned)arow * 64 + (((unsigned)(ahalf * 32)) ^ aswz);
    unsigned ad_b = (unsigned)arow * 64 + (((unsigned)(ahalf * 32 + 16)) ^ aswz);

    long long brow = (long long)(colbase + arow) * ldw;

    const int ta3[3] = {0, 0, 1};
    const int tb3[3] = {0, 1, 0};

    // ---- mma fragment addressing ----
    int a_r = wm * 32 + (lane & 15);
    unsigned a_k0 = (unsigned)((lane >> 4) << 4);
    unsigned a_sw = ((a_r >> 1) & 3) << 4;
    int b_g = lane >> 3, b_r = lane & 7;
    int b_n0 = wn * 64 + ((b_g >> 1) << 3) + b_r;
    unsigned b_k0 = (unsigned)((b_g & 1) << 4);

    float acc[2][8][4];
#pragma unroll
    for (int mt = 0; mt < 2; mt++)
#pragma unroll
        for (int nt = 0; nt < 8; nt++)
#pragma unroll
            for (int c = 0; c < 4; c++) acc[mt][nt][c] = 0.0f;

    int nc = Ktot >> 5;

#define P2_STAGE_FN(c_) do {                                                   \
        int buf_ = (c_) & 1;                                                   \
        unsigned stg_ = sbase + buf_ * P2_STAGE;                               \
        int kc_ = (c_) << 5;                                                   \
        const char *p0_, *p1_; long long ko_;                                  \
        if (kc_ < K1) { p0_ = a1b0; p1_ = a1b1; ko_ = kc_; }                   \
        else          { p0_ = a2b0; p1_ = a2b1; ko_ = kc_ - K1; }              \
        long long ab_ = ko_ * 2 + ahalf * 32;                                  \
        CPASYNC16(stg_ + ad_a, p0_ + ab_);                                     \
        CPASYNC16(stg_ + ad_b, p0_ + ab_ + 16);                                \
        CPASYNC16(stg_ + P2_AP + ad_a, p1_ + ab_);                             \
        CPASYNC16(stg_ + P2_AP + ad_b, p1_ + ab_ + 16);                        \
        long long bo_ = (brow + kc_) * 2 + ahalf * 32;                         \
        unsigned bd_ = stg_ + P2_BOFF;                                         \
        CPASYNC16(bd_ + ad_a, (const char*)W0 + bo_);                          \
        CPASYNC16(bd_ + ad_b, (const char*)W0 + bo_ + 16);                     \
        CPASYNC16(bd_ + P2_BP + ad_a, (const char*)W1 + bo_);                  \
        CPASYNC16(bd_ + P2_BP + ad_b, (const char*)W1 + bo_ + 16);             \
    } while (0)

    P2_STAGE_FN(0);
    CPCOMMIT();

    // single sync per chunk: wait(all) -> sync -> prefetch next -> mma current
    for (int c = 0; c < nc; c++) {
        CPWAIT0();
        __syncthreads();
        if (c + 1 < nc) { P2_STAGE_FN(c + 1); CPCOMMIT(); }

        unsigned stg = sbase + (c & 1) * P2_STAGE;
#pragma unroll
        for (int p = 0; p < 3; p++) {
            unsigned Ab = stg + ta3[p] * P2_AP;
            unsigned Bb = stg + P2_BOFF + tb3[p] * P2_BP;
#pragma unroll
            for (int ks = 0; ks < 2; ks++) {
                unsigned akb = ((unsigned)(ks << 5) + a_k0) ^ a_sw;
                unsigned a0[4], a1r[4];
                ldsm4(a0[0], a0[1], a0[2], a0[3], Ab + (unsigned)a_r * 64 + akb);
                ldsm4(a1r[0], a1r[1], a1r[2], a1r[3], Ab + (unsigned)(a_r + 16) * 64 + akb);
#pragma unroll
                for (int np = 0; np < 4; np++) {
                    int n = b_n0 + np * 16;
                    unsigned bkb = ((unsigned)(ks << 5) + b_k0) ^ (unsigned)(((n >> 1) & 3) << 4);
                    unsigned b0, b1, b2, b3;
                    ldsm4(b0, b1, b2, b3, Bb + (unsigned)n * 64 + bkb);
                    mma_f16(acc[0][2*np],   a0[0], a0[1], a0[2], a0[3], b0, b1);
                    mma_f16(acc[0][2*np+1], a0[0], a0[1], a0[2], a0[3], b2, b3);
                    mma_f16(acc[1][2*np],   a1r[0], a1r[1], a1r[2], a1r[3], b0, b1);
                    mma_f16(acc[1][2*np+1], a1r[0], a1r[1], a1r[2], a1r[3], b2, b3);
                }
            }
        }
    }

    // ---------------- epilogue ----------------
    int qd = lane & 3;
    int rql = lane >> 2;

    if (mode == 5) {
#pragma unroll
        for (int mt = 0; mt < 2; mt++)
#pragma unroll
            for (int hf = 0; hf < 2; hf++) {
                int m = r0 + wm * 32 + mt * 16 + rql + hf * 8;
                long long crow = (long long)((m >> 8) * NN + cgather[m]);
#pragma unroll
                for (int nt = 0; nt < 8; nt++) {
                    int cg = colbase + wn * 64 + nt * 8 + 2 * qd;
                    float* cp = C + crow * ldc + cg;
                    float2 o = *(float2*)cp;
                    o.x += acc[mt][nt][2*hf];
                    o.y += acc[mt][nt][2*hf+1];
                    *(float2*)cp = o;
                }
            }
        return;
    }

    float bv[16];
#pragma unroll
    for (int nt = 0; nt < 8; nt++) {
        int cg = colbase + wn * 64 + nt * 8 + 2 * qd;
        float2 t2 = *(const float2*)(bias + cg);
        bv[2*nt] = t2.x; bv[2*nt+1] = t2.y;
    }

    if (mode == 0) {
#pragma unroll
        for (int mt = 0; mt < 2; mt++)
#pragma unroll
            for (int hf = 0; hf < 2; hf++) {
                int m = r0 + wm * 32 + mt * 16 + rql + hf * 8;
#pragma unroll
                for (int nt = 0; nt < 8; nt++) {
                    int cg = colbase + wn * 64 + nt * 8 + 2 * qd;
                    float2 o;
                    o.x = acc[mt][nt][2*hf]   + bv[2*nt];
                    o.y = acc[mt][nt][2*hf+1] + bv[2*nt+1];
                    *(float2*)(C + (long long)m * ldc + cg) = o;
                }
            }
        return;
    }

    // mode 4: gelu + partial dot over local 128 cols -> dotbuf[y][m]
    {
        __syncthreads();   // smem reuse after last mma reads
        float* red = (float*)smem;
        float wv[16];
#pragma unroll
        for (int nt = 0; nt < 8; nt++) {
            int cg = colbase + wn * 64 + nt * 8 + 2 * qd;
            float2 tw = *(const float2*)(w2 + cg);
            wv[2*nt] = tw.x; wv[2*nt+1] = tw.y;
        }
#pragma unroll
        for (int mt = 0; mt < 2; mt++)
#pragma unroll
            for (int hf = 0; hf < 2; hf++) {
                float d = 0.0f;
#pragma unroll
                for (int nt = 0; nt < 8; nt++) {
                    float f0 = gelu_f(acc[mt][nt][2*hf]   + bv[2*nt]);
                    float f1 = gelu_f(acc[mt][nt][2*hf+1] + bv[2*nt+1]);
                    d += f0 * wv[2*nt] + f1 * wv[2*nt+1];
                }
                d += __shfl_xor_sync(0xffffffffu, d, 1);
                d += __shfl_xor_sync(0xffffffffu, d, 2);
                if (qd == 0) {
                    int rl = wm * 32 + mt * 16 + rql + hf * 8;
                    red[rl * 2 + wn] = d;
                }
            }
        __syncthreads();
        if (tid < 128)
            dotbuf[(long long)blockIdx.y * (BB * NN) + r0 + tid] = red[tid*2] + red[tid*2+1];
    }
}

// ======================= convert-path tensor GEMM (fp32 A, fp16 3-term) =======
#define A_TERM 16384
#define B_TERM 32768
#define BB_OFF (2 * A_TERM)
#define TC_SMEM (2 * A_TERM + 2 * B_TERM)

__global__ __launch_bounds__(512, 1)
void mma_gemm(const float* __restrict__ A1,
              const __half* __restrict__ W0, const __half* __restrict__ W1, int ldw,
              const float* __restrict__ bias,
              const float* __restrict__ rowscale,
              const float* __restrict__ lng, const float* __restrict__ lnb,
              float* __restrict__ C, int ldc,
              __half* __restrict__ n0p, __half* __restrict__ n1p,
              int Ktot, int a1_gelu, int mode) {
    extern __shared__ char smem[];
    unsigned sbase = smem_u32(smem);
    int tid = threadIdx.x;
    int lane = tid & 31;
    int wid = tid >> 5;
    int wm = wid & 3;
    int wn = wid >> 2;
    int r0 = blockIdx.x * 128;
    int colbase = blockIdx.y * 256;

    int s_arow = tid >> 2;
    int s_aq   = tid & 3;
    int m_a = r0 + s_arow;
    const float* a1p = A1 + (long long)m_a * Ktot;

    int s_bn = tid >> 1;
    int s_bh = tid & 1;
    long long bro = (long long)(colbase + s_bn) * ldw;

    const int ta3[3] = {0, 0, 1};
    const int tb3[3] = {0, 1, 0};

    int a_r = wm * 32 + (lane & 15);
    unsigned a_sw = (unsigned)((a_r & 7) << 4);
    unsigned a_kb0 = (unsigned)((lane >> 4) << 4);
    int b_g = lane >> 3, b_r = lane & 7;
    unsigned b_kb0 = (unsigned)((b_g & 1) << 4);

    float acc[2][8][4];
#pragma unroll
    for (int mt = 0; mt < 2; mt++)
#pragma unroll
        for (int nt = 0; nt < 8; nt++)
#pragma unroll
            for (int c = 0; c < 4; c++) acc[mt][nt][c] = 0.0f;

    int nchunks = Ktot >> 6;
    for (int ch = 0; ch < nchunks; ch++) {
        int kc = ch << 6;
        {
            const float* src = a1p + kc + s_aq * 16;
            float v[16];
#pragma unroll
            for (int j = 0; j < 4; j++) {
                float4 t4 = *(const float4*)(src + j * 4);
                v[j*4+0] = t4.x; v[j*4+1] = t4.y; v[j*4+2] = t4.z; v[j*4+3] = t4.w;
            }
            if (a1_gelu) {
#pragma unroll
                for (int j = 0; j < 16; j++) v[j] = gelu_f(v[j]);
            }
            unsigned u0[8], u1[8];
#pragma unroll
            for (int j = 0; j < 8; j++) {
                float x = v[2*j], y = v[2*j+1];
                __half hx0 = __float2half_rn(x);
                __half hy0 = __float2half_rn(y);
                __half hx1 = __float2half_rn(x - __half2float(hx0));
                __half hy1 = __float2half_rn(y - __half2float(hy0));
                u0[j] = ((unsigned)hbits(hy0) << 16) | hbits(hx0);
                u1[j] = ((unsigned)hbits(hy1) << 16) | hbits(hx1);
            }
            unsigned rsw = (unsigned)((s_arow & 7) << 4);
            unsigned rb = (unsigned)s_arow * 128;
#pragma unroll
            for (int j8 = 0; j8 < 4; j8++) {
                unsigned kb = (unsigned)(s_aq * 32 + j8 * 8) ^ rsw;
                *(uint2*)(smem + rb + kb) = make_uint2(u0[2*j8], u0[2*j8+1]);
                *(uint2*)(smem + A_TERM + rb + kb) = make_uint2(u1[2*j8], u1[2*j8+1]);
            }
        }
        {
            unsigned nsw = (unsigned)((s_bn & 7) << 4);
            unsigned nb = (unsigned)s_bn * 128;
            long long goff = (bro + kc) * 2;
#pragma unroll
            for (int w = 0; w < 2; w++) {
                const char* Wsrc = (const char*)((w == 0) ? W0 : W1);
#pragma unroll
                for (int i = 0; i < 4; i++) {
                    unsigned kb = (unsigned)(s_bh * 64 + i * 16);
                    CPASYNC16(sbase + BB_OFF + w * B_TERM + nb + (kb ^ nsw), Wsrc + goff + kb);
                }
            }
        }
        CPCOMMIT();
        CPWAIT0();
        __syncthreads();

#pragma unroll
        for (int p = 0; p < 3; p++) {
            unsigned Ab = sbase + ta3[p] * A_TERM;
            unsigned Bb = sbase + BB_OFF + tb3[p] * B_TERM;
#pragma unroll
            for (int ks = 0; ks < 4; ks++) {
                unsigned a0[4], a1r[4];
                unsigned akb = ((unsigned)(ks * 32) + a_kb0) ^ a_sw;
                ldsm4(a0[0], a0[1], a0[2], a0[3], Ab + (unsigned)a_r * 128 + akb);
                ldsm4(a1r[0], a1r[1], a1r[2], a1r[3], Ab + (unsigned)(a_r + 16) * 128 + akb);
#pragma unroll
                for (int np = 0; np < 4; np++) {
                    int n = wn * 64 + np * 16 + ((b_g >> 1) << 3) + b_r;
                    unsigned bkb = ((unsigned)(ks * 32) + b_kb0) ^ (unsigned)((n & 7) << 4);
                    unsigned b0, b1, b2, b3;
                    ldsm4(b0, b1, b2, b3, Bb + (unsigned)n * 128 + bkb);
                    mma_f16(acc[0][2*np],   a0[0], a0[1], a0[2], a0[3], b0, b1);
                    mma_f16(acc[0][2*np+1], a0[0], a0[1], a0[2], a0[3], b2, b3);
                    mma_f16(acc[1][2*np],   a1r[0], a1r[1], a1r[2], a1r[3], b0, b1);
                    mma_f16(acc[1][2*np+1], a1r[0], a1r[1], a1r[2], a1r[3], b2, b3);
                }
            }
        }
        __syncthreads();
    }

    int qd = lane & 3;
    int rql = lane >> 2;
    float bv[16];
#pragma unroll
    for (int nt = 0; nt < 8; nt++) {
        int cg = colbase + wn * 64 + nt * 8 + 2 * qd;
        float2 t2 = *(const float2*)(bias + cg);
        bv[2*nt] = t2.x; bv[2*nt+1] = t2.y;
    }

    if (mode == 0) {
#pragma unroll
        for (int mt = 0; mt < 2; mt++)
#pragma unroll
            for (int hf = 0; hf < 2; hf++) {
                int m = r0 + wm * 32 + mt * 16 + rql + hf * 8;
                float sc = rowscale ? rowscale[m] : 1.0f;
#pragma unroll
                for (int nt = 0; nt < 8; nt++) {
                    int cg = colbase + wn * 64 + nt * 8 + 2 * qd;
                    float2 o;
                    o.x = (acc[mt][nt][2*hf]   + bv[2*nt])   * sc;
                    o.y = (acc[mt][nt][2*hf+1] + bv[2*nt+1]) * sc;
                    *(float2*)(C + (long long)m * ldc + cg) = o;
                    if (n0p) {
                        long long e = (long long)m * 256 + cg;
                        __half x0 = __float2half_rn(o.x);
                        __half x1 = __float2half_rn(o.x - __half2float(x0));
                        __half y0 = __float2half_rn(o.y);
                        __half y1 = __float2half_rn(o.y - __half2float(y0));
                        *(unsigned*)(n0p + e) = ((unsigned)hbits(y0) << 16) | hbits(x0);
                        *(unsigned*)(n1p + e) = ((unsigned)hbits(y1) << 16) | hbits(x1);
                    }
                }
            }
        return;
    }

    // mode 2: layernorm -> fp16 plane outputs
    float* red = (float*)smem;
    float* red2 = red + 512;
#pragma unroll
    for (int mt = 0; mt < 2; mt++)
#pragma unroll
        for (int hf = 0; hf < 2; hf++) {
            float s = 0.0f, sq = 0.0f;
#pragma unroll
            for (int nt = 0; nt < 8; nt++) {
                float f0 = acc[mt][nt][2*hf]   + bv[2*nt];
                float f1 = acc[mt][nt][2*hf+1] + bv[2*nt+1];
                s += f0 + f1; sq += f0 * f0 + f1 * f1;
            }
            s  += __shfl_xor_sync(0xffffffffu, s, 1);
            s  += __shfl_xor_sync(0xffffffffu, s, 2);
            sq += __shfl_xor_sync(0xffffffffu, sq, 1);
            sq += __shfl_xor_sync(0xffffffffu, sq, 2);
            if (qd == 0) {
                int rl = wm * 32 + mt * 16 + rql + hf * 8;
                red[rl * 4 + wn] = s;
                red2[rl * 4 + wn] = sq;
            }
        }
    __syncthreads();
    float* stats = red2 + 512;
    if (tid < 128) {
        float s = red[tid*4] + red[tid*4+1] + red[tid*4+2] + red[tid*4+3];
        float sq = red2[tid*4] + red2[tid*4+1] + red2[tid*4+2] + red2[tid*4+3];
        float mu = s * (1.0f / 256.0f);
        float var = sq * (1.0f / 256.0f) - mu * mu;
        stats[tid*2] = mu;
        stats[tid*2+1] = rsqrtf(var + 1e-5f);
    }
    __syncthreads();
    float gv[16], ev[16];
#pragma unroll
    for (int nt = 0; nt < 8; nt++) {
        int cg = wn * 64 + nt * 8 + 2 * qd;
        float2 tg = *(const float2*)(lng + cg);
        float2 te = *(const float2*)(lnb + cg);
        gv[2*nt] = tg.x; gv[2*nt+1] = tg.y;
        ev[2*nt] = te.x; ev[2*nt+1] = te.y;
    }
#pragma unroll
    for (int mt = 0; mt < 2; mt++)
#pragma unroll
        for (int hf = 0; hf < 2; hf++) {
            int rl = wm * 32 + mt * 16 + rql + hf * 8;
            int m = r0 + rl;
            float mu = stats[rl*2], inv = stats[rl*2+1];
#pragma unroll
            for (int nt = 0; nt < 8; nt++) {
                int cg = wn * 64 + nt * 8 + 2 * qd;
                float2 o;
                float f0 = acc[mt][nt][2*hf]   + bv[2*nt];
                float f1 = acc[mt][nt][2*hf+1] + bv[2*nt+1];
                o.x = (f0 - mu) * inv * gv[2*nt]   + ev[2*nt];
                o.y = (f1 - mu) * inv * gv[2*nt+1] + ev[2*nt+1];
                if (C) *(float2*)(C + (long long)m * ldc + cg) = o;
                {
                    long long e = (long long)m * 256 + cg;
                    __half x0 = __float2half_rn(o.x);
                    __half x1 = __float2half_rn(o.x - __half2float(x0));
                    __half y0 = __float2half_rn(o.y);
                    __half y1 = __float2half_rn(o.y - __half2float(y0));
                    *(unsigned*)(n0p + e) = ((unsigned)hbits(y0) << 16) | hbits(x0);
                    *(unsigned*)(n1p + e) = ((unsigned)hbits(y1) << 16) | hbits(x1);
                }
            }
        }
}

// ------------------------- attention -------------------------
__global__ void attn_kernel(const float* __restrict__ qkv, float* __restrict__ out) {
    extern __shared__ float sm[];
    float* Ks = sm;
    float* Vs = sm + MSGK * HD;
    int bh = blockIdx.x;
    int b = bh >> 2;
    int h = bh & 3;
    int tid = threadIdx.x;
    const float* base = qkv + (long long)b * MSGK * 768;

    for (int t = tid; t < MSGK * HD; t += 256) {
        int j = t >> 6;
        int d = t & 63;
        Ks[t] = base[j * 768 + 256 + h * 64 + d];
        Vs[t] = base[j * 768 + 512 + h * 64 + d];
    }
    __syncthreads();

    float q[HD], o[HD];
#pragma unroll
    for (int d = 0; d < HD; d++) { q[d] = base[tid * 768 + h * 64 + d] * 0.125f; o[d] = 0.0f; }

    float mval = -1e30f, l = 0.0f;
    for (int j = 0; j < MSGK; j++) {
        float s = 0.0f;
#pragma unroll
        for (int d = 0; d < HD; d++) s += q[d] * Ks[j * 64 + d];
        float nm = fmaxf(mval, s);
        float corr = expf(mval - nm);
        float p = expf(s - nm);
        l = l * corr + p;
#pragma unroll
        for (int d = 0; d < HD; d++) o[d] = o[d] * corr + p * Vs[j * 64 + d];
        mval = nm;
    }
    float inv = 1.0f / l;
    float* op = out + ((long long)(b * MSGK + tid)) * DD + h * 64;
#pragma unroll
    for (int d = 0; d < HD; d++) op[d] = o[d] * inv;
}

// ------------------------- finalize (reconstruct newhid from fp16 planes) ----
__global__ void finalize_kernel(const float* __restrict__ newact,
                                const __half* __restrict__ n0p, const __half* __restrict__ n1p,
                                const int* __restrict__ slot2, float* __restrict__ out) {
    long long total_act = (long long)BB * NN;
    float* out_act = out;
    float* out_hid = out + total_act;
    long long stride = (long long)gridDim.x * blockDim.x;
    long long t0 = (long long)blockIdx.x * blockDim.x + threadIdx.x;

    for (long long i = t0; i < total_act; i += stride)
        out_act[i] = (slot2[i] >= 0) ? newact[i] : 0.0f;

    long long totalh4 = (long long)BB * NN * DD / 4;
    float4* oh4 = reinterpret_cast<float4*>(out_hid);
    for (long long e = t0; e < totalh4; e += stride) {
        long long r = e >> 6;
        if (slot2[r] >= 0) {
            uint2 u0 = *(const uint2*)(n0p + e * 4);
            uint2 u1 = *(const uint2*)(n1p + e * 4);
            float2 a0 = __half22float2(*(const __half2*)&u0.x);
            float2 a1 = __half22float2(*(const __half2*)&u0.y);
            float2 b0 = __half22float2(*(const __half2*)&u1.x);
            float2 b1 = __half22float2(*(const __half2*)&u1.y);
            oh4[e] = make_float4(a0.x + b0.x, a0.y + b0.y, a1.x + b1.x, a1.y + b1.y);
        } else {
            oh4[e] = make_float4(0.f, 0.f, 0.f, 0.f);
        }
    }
}

// ------------------------- host launcher -------------------------
extern "C" void kernel_launch(void* const* d_in, const int* in_sizes, int n_in,
                              void* d_out, int out_size) {
    const float* act    = (const float*)d_in[0];
    const float* hidden = (const float*)d_in[1];
    const float* in_w   = (const float*)d_in[2];
    const float* in_b   = (const float*)d_in[3];
    const float* out_w  = (const float*)d_in[4];
    const float* out_b  = (const float*)d_in[5];
    const float* su_w1  = (const float*)d_in[6];
    const float* su_b1  = (const float*)d_in[7];
    const float* su_w2  = (const float*)d_in[8];
    const float* su_b2  = (const float*)d_in[9];
    const float* au_w1  = (const float*)d_in[10];
    const float* au_b1  = (const float*)d_in[11];
    const float* au_w2  = (const float*)d_in[12];
    const float* au_b2  = (const float*)d_in[13];
    const float* ln_g   = (const float*)d_in[14];
    const float* ln_b   = (const float*)d_in[15];
    const int*   kptr   = (const int*)d_in[16];

    int*   p_tidx;   cudaGetSymbolAddress((void**)&p_tidx,   g_tidx);
    float* p_tval;   cudaGetSymbolAddress((void**)&p_tval,   g_tval);
    int*   p_slot2;  cudaGetSymbolAddress((void**)&p_slot2,  g_slot2);
    float* p_qkv;    cudaGetSymbolAddress((void**)&p_qkv,    g_qkv);
    float* p_attn;   cudaGetSymbolAddress((void**)&p_attn,   g_attn);
    float* p_msg;    cudaGetSymbolAddress((void**)&p_msg,    g_msg);
    float* p_h;      cudaGetSymbolAddress((void**)&p_h,      g_h);
    float* p_newact; cudaGetSymbolAddress((void**)&p_newact, g_newact);
    float* p_dot;    cudaGetSymbolAddress((void**)&p_dot,    g_dot);

    __half *in0,*in1, *ow0,*ow1, *s10,*s11, *s20,*s21, *a10,*a11;
    __half *h0,*h1, *n0,*n1, *m0,*m1;
    cudaGetSymbolAddress((void**)&in0, g_in0); cudaGetSymbolAddress((void**)&in1, g_in1);
    cudaGetSymbolAddress((void**)&ow0, g_ow0); cudaGetSymbolAddress((void**)&ow1, g_ow1);
    cudaGetSymbolAddress((void**)&s10, g_s10); cudaGetSymbolAddress((void**)&s11, g_s11);
    cudaGetSymbolAddress((void**)&s20, g_s20); cudaGetSymbolAddress((void**)&s21, g_s21);
    cudaGetSymbolAddress((void**)&a10, g_a10); cudaGetSymbolAddress((void**)&a11, g_a11);
    cudaGetSymbolAddress((void**)&h0, g_h0); cudaGetSymbolAddress((void**)&h1, g_h1);
    cudaGetSymbolAddress((void**)&n0, g_n0); cudaGetSymbolAddress((void**)&n1, g_n1);
    cudaGetSymbolAddress((void**)&m0, g_m0); cudaGetSymbolAddress((void**)&m1, g_m1);

    const int SMEM_ATTN = 2 * MSGK * HD * 4;

    cudaFuncSetAttribute(mma_gemm, cudaFuncAttributeMaxDynamicSharedMemorySize, TC_SMEM);
    cudaFuncSetAttribute(mma_gemm_ps2, cudaFuncAttributeMaxDynamicSharedMemorySize, P2_SMEM);
    cudaFuncSetAttribute(attn_kernel, cudaFuncAttributeMaxDynamicSharedMemorySize, SMEM_ATTN);

    // side stream + events for graph fork/join
    cudaStream_t s2;
    cudaStreamCreateWithFlags(&s2, cudaStreamNonBlocking);
    cudaEvent_t evF, evS, evJ;
    cudaEventCreateWithFlags(&evF, cudaEventDisableTiming);
    cudaEventCreateWithFlags(&evS, cudaEventDisableTiming);
    cudaEventCreateWithFlags(&evJ, cudaEventDisableTiming);

    // ---- fork: topk1 depends only on `act` ----
    cudaEventRecord(evF, 0);
    cudaStreamWaitEvent(s2, evF, 0);
    radix_topk_kernel<<<BB, 256, 0, s2>>>(act, nullptr, MSGK, p_tidx, p_tval, nullptr,
                                          nullptr, nullptr, nullptr);

    // ---- main: weight + activation prep ----
    split_weights_kernel<<<(SZ_TOT + 255) / 256, 256>>>(
        in_w, out_w, su_w1, su_w2, au_w1,
        in0, in1, ow0, ow1, s10, s11, s20, s21, a10, a11);
    split2v_kernel<<<BB * NN * DD / 2048, 256>>>(hidden, h0, h1);
    cudaEventRecord(evS, 0);

    // ---- side stream: qkv -> attn -> out-proj (+ msg plane emission) ----
    cudaStreamWaitEvent(s2, evS, 0);
    mma_gemm_ps2<<<dim3(64, 6), 256, P2_SMEM, s2>>>(
        h0, h1, nullptr, nullptr, p_tidx, nullptr,
        in0, in1, 256, in_b,
        nullptr, nullptr,
        p_qkv, 768, 256, 256, 256, 256, 0);
    attn_kernel<<<BB * 4, 256, SMEM_ATTN, s2>>>(p_qkv, p_attn);
    mma_gemm<<<dim3(64, 1), 512, TC_SMEM, s2>>>(
        p_attn, ow0, ow1, 256, out_b,
        p_tval, nullptr, nullptr,
        p_msg, 256, m0, m1,
        256, 0, 0);
    cudaEventRecord(evJ, s2);

    // ---- main (concurrent with side stream): su1 dense ----
    mma_gemm_ps2<<<dim3(1024, 2), 256, P2_SMEM>>>(
        h0, h1, nullptr, nullptr, nullptr, nullptr,
        s10, s11, 512, su_b1,
        nullptr, nullptr,
        p_h, 256, 256, 256, 256, 256, 0);

    // ---- join, then serial tail ----
    cudaStreamWaitEvent(0, evJ, 0);

    // su1 sparse: pre[active] += msg @ W1b^T  (ps2 mode 5, scatter-accum)
    // W1b = columns [256,512) of su_w1 -> base s10 + 256 (row-major, ldw=512)
    mma_gemm_ps2<<<dim3(64, 2), 256, P2_SMEM>>>(
        m0, m1, nullptr, nullptr, nullptr, p_tidx,
        s10 + 256, s11 + 256, 512, nullptr,
        nullptr, nullptr,
        p_h, 256, 256, 256, 256, 256, 5);

    // su2: newhid = LN( gelu(pre) @ W2^T + b2 ) -> fp16 planes only
    mma_gemm<<<dim3(1024, 1), 512, TC_SMEM>>>(
        p_h, s20, s21, 256, su_b2,
        nullptr, ln_g, ln_b,
        nullptr, 256, n0, n1,
        256, 1, 2);

    // au1: partial gelu-dot per 128-col half -> g_dot[y][m]
    mma_gemm_ps2<<<dim3(1024, 2), 256, P2_SMEM>>>(
        h0, h1, n0, n1, nullptr, nullptr,
        a10, a11, 512, au_b1,
        au_w2, p_dot,
        nullptr, 256, 256, 256, 256, 512, 4);

    // final top-k fused with act update (k from device sparsity_k)
    radix_topk_kernel<<<BB, 256>>>(act, kptr, 0, nullptr, nullptr, p_slot2,
                                   p_dot, au_b2, p_newact);

    // masked write [sparse_act | sparse_hidden] with fp16-plane reconstruction
    finalize_kernel<<<2048, 256>>>(p_newact, n0, n1, p_slot2, (float*)d_out);
}